// round 1
// baseline (speedup 1.0000x reference)
#include <cuda_runtime.h>

// ---------------- problem constants ----------------
#define Bb   4
#define Tt   2048
#define Dd   512
#define Hh   8
#define Pp   16
#define DH   64
#define Cc   512
#define HF   64
#define WF   64
#define RAD  0.08f
#define BT   (Bb*Tt)        // 8192
#define HW   (HF*WF)        // 4096

// ---------------- scratch (static device globals; no allocs allowed) -------
__device__ float g_V[(size_t)Bb * HW * Dd];     // value projection, (B, HW, D)
__device__ float g_OFF[(size_t)BT * (Hh*Pp*2)]; // offsets, (BT, 256)
__device__ float g_LOG[(size_t)BT * (Hh*Pp)];   // attn logits, (BT, 128)
__device__ float g_CTX[(size_t)BT * Dd];        // gathered context, (BT, 512)

// ---------------- generic tiled fp32 GEMM: C = A*B (+bias) ----------------
// A_KMAJOR: A stored as [K][M] (k-major, e.g. fmap per batch); else [M][K].
// B is [K][N] row-major. All dims multiples of tile sizes (checked by caller).
template<bool A_KMAJOR>
__global__ __launch_bounds__(256)
void gemm64(const float* __restrict__ A, const float* __restrict__ Bm,
            const float* __restrict__ bias, float* __restrict__ C,
            int M, int N, int K,
            long long aStride, long long cStride)
{
    const int BM = 64, BN = 64, BK = 16;
    __shared__ float As[BK][BM + 1];   // +1 pad: conflict-free transposed store
    __shared__ float Bs[BK][BN];

    A += (long long)blockIdx.z * aStride;
    C += (long long)blockIdx.z * cStride;

    int tid = threadIdx.x;
    int tx = tid & 15, ty = tid >> 4;
    int m0 = blockIdx.y * BM;
    int n0 = blockIdx.x * BN;

    float acc[4][4] = {};

    for (int k0 = 0; k0 < K; k0 += BK) {
        #pragma unroll
        for (int l = 0; l < 4; l++) {
            int idx = tid + l * 256;
            if (A_KMAJOR) {
                int kk = idx >> 6, mm = idx & 63;
                As[kk][mm] = A[(long long)(k0 + kk) * M + (m0 + mm)];
            } else {
                int mm = idx >> 4, kk = idx & 15;
                As[kk][mm] = A[(long long)(m0 + mm) * K + (k0 + kk)];
            }
        }
        #pragma unroll
        for (int l = 0; l < 4; l++) {
            int idx = tid + l * 256;
            int kk = idx >> 6, nn = idx & 63;
            Bs[kk][nn] = Bm[(long long)(k0 + kk) * N + (n0 + nn)];
        }
        __syncthreads();

        #pragma unroll
        for (int kk = 0; kk < BK; kk++) {
            float a[4], bv[4];
            #pragma unroll
            for (int i = 0; i < 4; i++) a[i] = As[kk][ty * 4 + i];
            #pragma unroll
            for (int j = 0; j < 4; j++) bv[j] = Bs[kk][tx * 4 + j];
            #pragma unroll
            for (int i = 0; i < 4; i++)
                #pragma unroll
                for (int j = 0; j < 4; j++)
                    acc[i][j] += a[i] * bv[j];
        }
        __syncthreads();
    }

    #pragma unroll
    for (int i = 0; i < 4; i++) {
        int m = m0 + ty * 4 + i;
        #pragma unroll
        for (int j = 0; j < 4; j++) {
            int n = n0 + tx * 4 + j;
            float v = acc[i][j];
            if (bias) v += bias[n];
            C[(long long)m * N + n] = v;
        }
    }
}

// ---------------- softmax + bilinear gather --------------------------------
// One block per (b,t). 512 threads: thread = (head h = tid>>6, channel d = tid&63).
// V layout (B, HW, 512): a corner read by 64 lanes of one head is a single
// contiguous 256B transaction.
__global__ __launch_bounds__(512)
void sample_kernel(const float* __restrict__ V,
                   const float* __restrict__ OFF,
                   const float* __restrict__ LOG,
                   const float* __restrict__ ref,
                   float* __restrict__ CTX)
{
    int bt = blockIdx.x;
    int b  = bt >> 11;              // /T (2048)
    int tid = threadIdx.x;

    __shared__ float s_off[Hh * Pp * 2];
    __shared__ float s_logit[Hh * Pp];
    __shared__ float s_aw[Hh * Pp];
    __shared__ int   s_x0[Hh * Pp];
    __shared__ int   s_y0[Hh * Pp];
    __shared__ float s_fx[Hh * Pp];
    __shared__ float s_fy[Hh * Pp];

    if (tid < 256) s_off[tid]   = OFF[(long long)bt * 256 + tid];
    if (tid < 128) s_logit[tid] = LOG[(long long)bt * 128 + tid];
    __syncthreads();

    float rx = ref[bt * 2 + 0];
    float ry = ref[bt * 2 + 1];

    if (tid < 128) {   // per (h,p): sample coords (align_corners=True)
        float ox = s_off[tid * 2 + 0];
        float oy = s_off[tid * 2 + 1];
        float ix = (rx + RAD * ox) * (float)(WF - 1);
        float iy = (ry + RAD * oy) * (float)(HF - 1);
        float x0f = floorf(ix), y0f = floorf(iy);
        s_x0[tid] = (int)x0f;
        s_y0[tid] = (int)y0f;
        s_fx[tid] = ix - x0f;
        s_fy[tid] = iy - y0f;
    }
    __syncthreads();

    if (tid < Hh) {    // softmax over P=16 per head (trivial serial loop)
        int base = tid * Pp;
        float mx = -1e30f;
        #pragma unroll
        for (int p = 0; p < Pp; p++) mx = fmaxf(mx, s_logit[base + p]);
        float e[Pp]; float sum = 0.f;
        #pragma unroll
        for (int p = 0; p < Pp; p++) { e[p] = __expf(s_logit[base + p] - mx); sum += e[p]; }
        float inv = 1.0f / sum;
        #pragma unroll
        for (int p = 0; p < Pp; p++) s_aw[base + p] = e[p] * inv;
    }
    __syncthreads();

    int h = tid >> 6;
    int d = tid & 63;
    const float* Vb = V + (long long)b * HW * Dd + h * DH + d;

    float acc = 0.f;
    #pragma unroll
    for (int p = 0; p < Pp; p++) {
        int hp = h * Pp + p;
        int x0 = s_x0[hp], y0 = s_y0[hp];
        float fx = s_fx[hp], fy = s_fy[hp];
        float aw = s_aw[hp];
        float w00 = (1.f - fx) * (1.f - fy) * aw;
        float w10 = fx * (1.f - fy) * aw;
        float w01 = (1.f - fx) * fy * aw;
        float w11 = fx * fy * aw;
        bool vx0 = (x0 >= 0) && (x0 < WF);
        bool vx1 = (x0 + 1 >= 0) && (x0 + 1 < WF);
        bool vy0 = (y0 >= 0) && (y0 < HF);
        bool vy1 = (y0 + 1 >= 0) && (y0 + 1 < HF);
        if (vx0 && vy0) acc += w00 * Vb[(long long)(y0 * WF + x0) * Dd];
        if (vx1 && vy0) acc += w10 * Vb[(long long)(y0 * WF + x0 + 1) * Dd];
        if (vx0 && vy1) acc += w01 * Vb[(long long)((y0 + 1) * WF + x0) * Dd];
        if (vx1 && vy1) acc += w11 * Vb[(long long)((y0 + 1) * WF + x0 + 1) * Dd];
    }
    CTX[(long long)bt * Dd + h * DH + d] = acc;
}

// ---------------- launch ----------------------------------------------------
extern "C" void kernel_launch(void* const* d_in, const int* in_sizes, int n_in,
                              void* d_out, int out_size)
{
    const float* q     = (const float*)d_in[0];
    const float* fmap  = (const float*)d_in[1];
    const float* ref   = (const float*)d_in[2];
    const float* Wv    = (const float*)d_in[3];
    const float* W_off = (const float*)d_in[4];
    const float* b_off = (const float*)d_in[5];
    const float* W_w   = (const float*)d_in[6];
    const float* b_w   = (const float*)d_in[7];
    const float* W_out = (const float*)d_in[8];
    const float* b_out = (const float*)d_in[9];
    float* out = (float*)d_out;

    float *V, *OFF, *LOGp, *CTX;
    cudaGetSymbolAddress((void**)&V,    g_V);
    cudaGetSymbolAddress((void**)&OFF,  g_OFF);
    cudaGetSymbolAddress((void**)&LOGp, g_LOG);
    cudaGetSymbolAddress((void**)&CTX,  g_CTX);

    // 1) V projection: per batch, A = fmap[b] as [C][HW] (k-major), B = Wv [C][D]
    {
        dim3 grid(Dd / 64, HW / 64, Bb);
        gemm64<true><<<grid, 256>>>(fmap, Wv, nullptr, V,
                                    HW, Dd, Cc,
                                    (long long)Cc * HW, (long long)HW * Dd);
    }
    // 2) off = q @ W_off + b_off  (8192 x 256)
    {
        dim3 grid((Hh * Pp * 2) / 64, BT / 64, 1);
        gemm64<false><<<grid, 256>>>(q, W_off, b_off, OFF,
                                     BT, Hh * Pp * 2, Dd, 0, 0);
    }
    // 3) logits = q @ W_w + b_w  (8192 x 128)
    {
        dim3 grid((Hh * Pp) / 64, BT / 64, 1);
        gemm64<false><<<grid, 256>>>(q, W_w, b_w, LOGp,
                                     BT, Hh * Pp, Dd, 0, 0);
    }
    // 4) softmax + bilinear deformable gather -> CTX (8192 x 512)
    sample_kernel<<<BT, 512>>>(V, OFF, LOGp, ref, CTX);

    // 5) out = CTX @ W_out + b_out  (8192 x 512)
    {
        dim3 grid(Dd / 64, BT / 64, 1);
        gemm64<false><<<grid, 256>>>(CTX, W_out, b_out, out,
                                     BT, Dd, Dd, 0, 0);
    }
}

// round 3
// speedup vs baseline: 1.4557x; 1.4557x over previous
#include <cuda_runtime.h>

// ---------------- problem constants ----------------
#define Bb   4
#define Tt   2048
#define Dd   512
#define Hh   8
#define Pp   16
#define DH   64
#define Cc   512
#define HF   64
#define WF   64
#define RAD  0.08f
#define BT   (Bb*Tt)        // 8192
#define HW   (HF*WF)        // 4096
#define NOL  384            // 256 (offsets) + 128 (logits)

// ---------------- scratch (static device globals) --------------------------
__device__ float g_V[(size_t)Bb * HW * Dd];     // value projection, (B, HW, D)
__device__ float g_OL[(size_t)BT * NOL];        // [off(256) | logits(128)]
__device__ float g_CTX[(size_t)BT * Dd];        // gathered context
__device__ float g_Wc[(size_t)Dd * NOL];        // concat [W_off | W_w]
__device__ float g_bc[NOL];

// ---------------- packed f32x2 helpers --------------------------------------
#define FMA2(d, a, b, c) \
    asm("fma.rn.f32x2 %0, %1, %2, %3;" : "=l"(d) : "l"(a), "l"(b), "l"(c))
#define PACK2(d, lo, hi) \
    asm("mov.b64 %0, {%1, %2};" : "=l"(d) : "r"(lo), "r"(hi))
#define UNPACK2(lo, hi, in) \
    asm("mov.b64 {%0, %1}, %2;" : "=r"(lo), "=r"(hi) : "l"(in))

// ---------------- tiled fp32 GEMM with f32x2 FMAs ---------------------------
// C = A*B (+bias). A_KMAJOR: A stored [K][M]; else [M][K]. B is [K][N].
// Tile 128x128x16, 256 threads, 8x8 per thread (split 4+4 across halves).
template<bool A_KMAJOR>
__global__ __launch_bounds__(256, 2)
void gemm128(const float* __restrict__ A, const float* __restrict__ Bm,
             const float* __restrict__ bias, float* __restrict__ C,
             int M, int N, int K,
             long long aStride, long long cStride)
{
    __shared__ float As[16][132];   // pad 132: 16B-aligned rows, fewer STS conflicts
    __shared__ float Bs[16][128];

    A += (long long)blockIdx.z * aStride;
    C += (long long)blockIdx.z * cStride;

    int tid = threadIdx.x;
    int tx = tid & 15, ty = tid >> 4;
    int m0 = blockIdx.y * 128;
    int n0 = blockIdx.x * 128;

    unsigned long long acc[8][4] = {};   // (0.0,0.0) packed

    for (int k0 = 0; k0 < K; k0 += 16) {
        // ---- load A tile into As[kk][mm] ----
        if (A_KMAJOR) {
            #pragma unroll
            for (int l = 0; l < 2; l++) {
                int idx = tid + l * 256;
                int kk = idx >> 5;
                int mm = (idx & 31) * 4;
                *(float4*)&As[kk][mm] =
                    *(const float4*)&A[(long long)(k0 + kk) * M + m0 + mm];
            }
        } else {
            #pragma unroll
            for (int l = 0; l < 2; l++) {
                int idx = tid + l * 256;
                int mm = idx >> 2;
                int k4 = (idx & 3) * 4;
                float4 v = *(const float4*)&A[(long long)(m0 + mm) * K + k0 + k4];
                As[k4 + 0][mm] = v.x;
                As[k4 + 1][mm] = v.y;
                As[k4 + 2][mm] = v.z;
                As[k4 + 3][mm] = v.w;
            }
        }
        // ---- load B tile ----
        #pragma unroll
        for (int l = 0; l < 2; l++) {
            int idx = tid + l * 256;
            int kk = idx >> 5;
            int nn = (idx & 31) * 4;
            *(float4*)&Bs[kk][nn] =
                *(const float4*)&Bm[(long long)(k0 + kk) * N + n0 + nn];
        }
        __syncthreads();

        #pragma unroll
        for (int kk = 0; kk < 16; kk++) {
            // rows: ty*4..+3 and 64+ty*4..+3 ; cols: tx*4..+3 and 64+tx*4..+3
            float4 a0 = *(const float4*)&As[kk][ty * 4];
            float4 a1 = *(const float4*)&As[kk][64 + ty * 4];
            unsigned long long bp[4];
            {
                float4 b0 = *(const float4*)&Bs[kk][tx * 4];
                float4 b1 = *(const float4*)&Bs[kk][64 + tx * 4];
                PACK2(bp[0], __float_as_uint(b0.x), __float_as_uint(b0.y));
                PACK2(bp[1], __float_as_uint(b0.z), __float_as_uint(b0.w));
                PACK2(bp[2], __float_as_uint(b1.x), __float_as_uint(b1.y));
                PACK2(bp[3], __float_as_uint(b1.z), __float_as_uint(b1.w));
            }
            float av[8] = {a0.x, a0.y, a0.z, a0.w, a1.x, a1.y, a1.z, a1.w};
            #pragma unroll
            for (int i = 0; i < 8; i++) {
                unsigned int au = __float_as_uint(av[i]);
                unsigned long long a2;
                PACK2(a2, au, au);
                #pragma unroll
                for (int j = 0; j < 4; j++)
                    FMA2(acc[i][j], a2, bp[j], acc[i][j]);
            }
        }
        __syncthreads();
    }

    // ---- epilogue ----
    float4 bias0 = make_float4(0.f, 0.f, 0.f, 0.f), bias1 = bias0;
    if (bias) {
        bias0 = *(const float4*)&bias[n0 + tx * 4];
        bias1 = *(const float4*)&bias[n0 + 64 + tx * 4];
    }
    #pragma unroll
    for (int i = 0; i < 8; i++) {
        int m = m0 + ((i < 4) ? (ty * 4 + i) : (64 + ty * 4 + i - 4));
        float o[8];
        #pragma unroll
        for (int j = 0; j < 4; j++) {
            unsigned int lo, hi;
            UNPACK2(lo, hi, acc[i][j]);
            o[2 * j]     = __uint_as_float(lo);
            o[2 * j + 1] = __uint_as_float(hi);
        }
        o[0] += bias0.x; o[1] += bias0.y; o[2] += bias0.z; o[3] += bias0.w;
        o[4] += bias1.x; o[5] += bias1.y; o[6] += bias1.z; o[7] += bias1.w;
        *(float4*)&C[(long long)m * N + n0 + tx * 4]      = make_float4(o[0], o[1], o[2], o[3]);
        *(float4*)&C[(long long)m * N + n0 + 64 + tx * 4] = make_float4(o[4], o[5], o[6], o[7]);
    }
}

// ---------------- weight concat: [W_off | W_w] -> g_Wc, biases -> g_bc ------
__global__ __launch_bounds__(256)
void concat_weights(const float* __restrict__ W_off, const float* __restrict__ b_off,
                    const float* __restrict__ W_w,   const float* __restrict__ b_w,
                    float* __restrict__ Wc, float* __restrict__ bc)
{
    int i = blockIdx.x * 256 + threadIdx.x;
    if (i < Dd * NOL) {
        int k = i / NOL, n = i - k * NOL;
        Wc[i] = (n < 256) ? W_off[k * 256 + n] : W_w[k * 128 + (n - 256)];
    }
    if (i < NOL) bc[i] = (i < 256) ? b_off[i] : b_w[i - 256];
}

// ---------------- softmax + bilinear gather (v2) ----------------------------
// One block of 128 threads per (b,t). Setup: thread == (h,p); precomputes the
// 4 corner indices + (bilinear * softmax) weights into smem ONCE.
// Main: thread = (h = tid>>4, 4-channel group = tid&15); float4 gathers,
// f32x2 accumulation. A head's corner read by 16 lanes = 256B coalesced.
__global__ __launch_bounds__(128)
void sample2(const float* __restrict__ V,
             const float* __restrict__ OL,
             const float* __restrict__ ref,
             float* __restrict__ CTX)
{
    int bt = blockIdx.x;
    int b  = bt >> 11;
    int tid = threadIdx.x;

    __shared__ float s_w[Hh * Pp][4];
    __shared__ int   s_i[Hh * Pp][4];

    {   // setup: tid = hp in [0,128)
        const float* olrow = OL + (long long)bt * NOL;
        float ox = olrow[2 * tid];
        float oy = olrow[2 * tid + 1];
        float lg = olrow[256 + tid];
        float rx = ref[bt * 2 + 0];
        float ry = ref[bt * 2 + 1];

        float ix = (rx + RAD * ox) * (float)(WF - 1);
        float iy = (ry + RAD * oy) * (float)(HF - 1);
        float x0f = floorf(ix), y0f = floorf(iy);
        int x0 = (int)x0f, y0 = (int)y0f;
        float fx = ix - x0f, fy = iy - y0f;

        // softmax over P=16 within each 16-lane group
        float mx = lg;
        #pragma unroll
        for (int m = 8; m >= 1; m >>= 1)
            mx = fmaxf(mx, __shfl_xor_sync(0xffffffffu, mx, m, 16));
        float e = __expf(lg - mx);
        float s = e;
        #pragma unroll
        for (int m = 8; m >= 1; m >>= 1)
            s += __shfl_xor_sync(0xffffffffu, s, m, 16);
        float aw = e / s;

        bool vx0 = (x0 >= 0) && (x0 < WF);
        bool vx1 = (x0 + 1 >= 0) && (x0 + 1 < WF);
        bool vy0 = (y0 >= 0) && (y0 < HF);
        bool vy1 = (y0 + 1 >= 0) && (y0 + 1 < HF);
        int x0c = min(max(x0, 0), WF - 1);
        int x1c = min(max(x0 + 1, 0), WF - 1);
        int y0c = min(max(y0, 0), HF - 1);
        int y1c = min(max(y0 + 1, 0), HF - 1);

        s_w[tid][0] = (vx0 && vy0) ? (1.f - fx) * (1.f - fy) * aw : 0.f;
        s_w[tid][1] = (vx1 && vy0) ? fx * (1.f - fy) * aw : 0.f;
        s_w[tid][2] = (vx0 && vy1) ? (1.f - fx) * fy * aw : 0.f;
        s_w[tid][3] = (vx1 && vy1) ? fx * fy * aw : 0.f;
        s_i[tid][0] = y0c * WF + x0c;
        s_i[tid][1] = y0c * WF + x1c;
        s_i[tid][2] = y1c * WF + x0c;
        s_i[tid][3] = y1c * WF + x1c;
    }
    __syncthreads();

    int h  = tid >> 4;
    int c4 = tid & 15;
    const float4* Vb = (const float4*)(V + (size_t)b * HW * Dd) + (h * 16 + c4);

    unsigned long long acc0 = 0ULL, acc1 = 0ULL;
    #pragma unroll
    for (int p = 0; p < Pp; p++) {
        int hp = h * Pp + p;
        int4   ii = *(const int4*)s_i[hp];
        float4 ww = *(const float4*)s_w[hp];
        #pragma unroll
        for (int c = 0; c < 4; c++) {
            int   idx = (c == 0) ? ii.x : (c == 1) ? ii.y : (c == 2) ? ii.z : ii.w;
            float w   = (c == 0) ? ww.x : (c == 1) ? ww.y : (c == 2) ? ww.z : ww.w;
            float4 v = Vb[(long long)idx * (Dd / 4)];
            unsigned int wu = __float_as_uint(w);
            unsigned long long w2, v01, v23;
            PACK2(w2, wu, wu);
            PACK2(v01, __float_as_uint(v.x), __float_as_uint(v.y));
            PACK2(v23, __float_as_uint(v.z), __float_as_uint(v.w));
            FMA2(acc0, w2, v01, acc0);
            FMA2(acc1, w2, v23, acc1);
        }
    }

    float4 r;
    unsigned int r0, r1, r2, r3;
    UNPACK2(r0, r1, acc0);
    UNPACK2(r2, r3, acc1);
    r.x = __uint_as_float(r0);
    r.y = __uint_as_float(r1);
    r.z = __uint_as_float(r2);
    r.w = __uint_as_float(r3);
    *(float4*)&CTX[(long long)bt * Dd + h * DH + c4 * 4] = r;
}

// ---------------- launch ----------------------------------------------------
extern "C" void kernel_launch(void* const* d_in, const int* in_sizes, int n_in,
                              void* d_out, int out_size)
{
    const float* q     = (const float*)d_in[0];
    const float* fmap  = (const float*)d_in[1];
    const float* ref   = (const float*)d_in[2];
    const float* Wv    = (const float*)d_in[3];
    const float* W_off = (const float*)d_in[4];
    const float* b_off = (const float*)d_in[5];
    const float* W_w   = (const float*)d_in[6];
    const float* b_w   = (const float*)d_in[7];
    const float* W_out = (const float*)d_in[8];
    const float* b_out = (const float*)d_in[9];
    float* out = (float*)d_out;

    float *V, *OL, *CTX, *Wc, *bc;
    cudaGetSymbolAddress((void**)&V,   g_V);
    cudaGetSymbolAddress((void**)&OL,  g_OL);
    cudaGetSymbolAddress((void**)&CTX, g_CTX);
    cudaGetSymbolAddress((void**)&Wc,  g_Wc);
    cudaGetSymbolAddress((void**)&bc,  g_bc);

    // 0) concat [W_off | W_w] and biases
    concat_weights<<<(Dd * NOL + 255) / 256, 256>>>(W_off, b_off, W_w, b_w, Wc, bc);

    // 1) V projection: per batch, A = fmap[b] as [C][HW] (k-major)
    {
        dim3 grid(Dd / 128, HW / 128, Bb);
        gemm128<true><<<grid, 256>>>(fmap, Wv, nullptr, V,
                                     HW, Dd, Cc,
                                     (long long)Cc * HW, (long long)HW * Dd);
    }
    // 2) [off | logits] = q @ Wc + bc  (8192 x 384)
    {
        dim3 grid(NOL / 128, BT / 128, 1);
        gemm128<false><<<grid, 256>>>(q, Wc, bc, OL, BT, NOL, Dd, 0, 0);
    }
    // 3) softmax + bilinear deformable gather -> CTX
    sample2<<<BT, 128>>>(V, OL, ref, CTX);

    // 4) out = CTX @ W_out + b_out  (8192 x 512)
    {
        dim3 grid(Dd / 128, BT / 128, 1);
        gemm128<false><<<grid, 256>>>(CTX, W_out, b_out, out, BT, Dd, Dd, 0, 0);
    }
}

// round 5
// speedup vs baseline: 2.6284x; 1.8056x over previous
#include <cuda_runtime.h>
#include <cuda_bf16.h>
#include <cstdint>

// ---------------- problem constants ----------------
#define Bb   4
#define Tt   2048
#define Dd   512
#define Hh   8
#define Pp   16
#define DH   64
#define Cc   512
#define HF   64
#define WF   64
#define RAD  0.08f
#define BT   (Bb*Tt)        // 8192
#define HW   (HF*WF)        // 4096
#define NOL  384            // 256 (offsets) + 128 (logits)
#define KK   512            // inner dim of every GEMM
#define KST  1024           // stored K: [hi(512) | lo(512)]

// ---------------- scratch (static device globals) --------------------------
__device__ float g_V[(size_t)Bb * HW * Dd];        // value proj, (B, HW, D) fp32
__device__ float g_OL[(size_t)BT * NOL];           // [off(256) | logits(128)] fp32
__device__ float g_bc[NOL];
__device__ __align__(256) unsigned short g_Ab [(size_t)Bb * HW * KST];  // fmap^T split
__device__ __align__(256) unsigned short g_qb [(size_t)BT * KST];       // q split
__device__ __align__(256) unsigned short g_CTXb[(size_t)BT * KST];      // ctx split
__device__ __align__(256) unsigned short g_Wvb[(size_t)Dd * KST];       // Wv^T split
__device__ __align__(256) unsigned short g_Wcb[(size_t)NOL * KST];      // [W_off|W_w]^T
__device__ __align__(256) unsigned short g_Wob[(size_t)Dd * KST];       // W_out^T split

// ---------------- PTX helpers (all baseline sm_80-class; compile at compute_103)
__device__ __forceinline__ uint32_t smem_u32(const void* p) {
    uint32_t a;
    asm("{ .reg .u64 t; cvta.to.shared.u64 t, %1; cvt.u32.u64 %0, t; }"
        : "=r"(a) : "l"(p));
    return a;
}
#define SWZ(o) ((o) ^ (((o) >> 3) & 0x70))
#define CP16(dst, src) \
    asm volatile("cp.async.cg.shared.global [%0], [%1], 16;" \
                 :: "r"(dst), "l"(src))
#define CPCOMMIT() asm volatile("cp.async.commit_group;" ::: "memory")
#define CPWAIT0()  asm volatile("cp.async.wait_group 0;" ::: "memory")
#define CPWAIT1()  asm volatile("cp.async.wait_group 1;" ::: "memory")

__device__ __forceinline__ void ldmx4(uint32_t r[4], uint32_t addr) {
    asm volatile("ldmatrix.sync.aligned.m8n8.x4.shared.b16 {%0,%1,%2,%3}, [%4];"
        : "=r"(r[0]), "=r"(r[1]), "=r"(r[2]), "=r"(r[3]) : "r"(addr));
}
__device__ __forceinline__ void mma16816(float d[4], const uint32_t a[4],
                                         const uint32_t b[2]) {
    asm volatile(
        "mma.sync.aligned.m16n8k16.row.col.f32.bf16.bf16.f32 "
        "{%0,%1,%2,%3}, {%4,%5,%6,%7}, {%8,%9}, {%0,%1,%2,%3};"
        : "+f"(d[0]), "+f"(d[1]), "+f"(d[2]), "+f"(d[3])
        : "r"(a[0]), "r"(a[1]), "r"(a[2]), "r"(a[3]), "r"(b[0]), "r"(b[1]));
}

// ---------------- split helpers ---------------------------------------------
__device__ __forceinline__ void split2(float x, unsigned short& h, unsigned short& l) {
    __nv_bfloat16 hb = __float2bfloat16(x);
    __nv_bfloat16 lb = __float2bfloat16(x - __bfloat162float(hb));
    h = *reinterpret_cast<unsigned short*>(&hb);
    l = *reinterpret_cast<unsigned short*>(&lb);
}

// ---------------- transpose + split:  in[K][N] fp32 -> out[N][2K] bf16 ------
__global__ void transpose_split(const float* __restrict__ in,
                                unsigned short* __restrict__ out,
                                int K, int N, long long inBatch, long long outBatch)
{
    __shared__ float t[32][33];
    in  += (size_t)blockIdx.z * inBatch;
    out += (size_t)blockIdx.z * outBatch;
    int n0 = blockIdx.x * 32, k0 = blockIdx.y * 32;
    int tx = threadIdx.x, ty = threadIdx.y;
    #pragma unroll
    for (int i = ty; i < 32; i += 8)
        t[i][tx] = in[(size_t)(k0 + i) * N + n0 + tx];
    __syncthreads();
    #pragma unroll
    for (int i = ty; i < 32; i += 8) {
        int n = n0 + i, k = k0 + tx;
        unsigned short h, l;
        split2(t[tx][i], h, l);
        out[(size_t)n * (2 * K) + k]     = h;
        out[(size_t)n * (2 * K) + K + k] = l;
    }
}

// ---------------- row split: in[M][512] fp32 -> out[M][1024] bf16 -----------
__global__ void rows_split(const float* __restrict__ in, unsigned short* __restrict__ out)
{
    size_t i = (size_t)blockIdx.x * blockDim.x + threadIdx.x;  // over M * 128
    size_t m = i >> 7;
    int k4 = (int)(i & 127) * 4;
    float4 v = *(const float4*)(in + m * KK + k4);
    unsigned short h[4], l[4];
    split2(v.x, h[0], l[0]); split2(v.y, h[1], l[1]);
    split2(v.z, h[2], l[2]); split2(v.w, h[3], l[3]);
    uint2 hp, lp;
    hp.x = (uint32_t)h[0] | ((uint32_t)h[1] << 16);
    hp.y = (uint32_t)h[2] | ((uint32_t)h[3] << 16);
    lp.x = (uint32_t)l[0] | ((uint32_t)l[1] << 16);
    lp.y = (uint32_t)l[2] | ((uint32_t)l[3] << 16);
    *(uint2*)(out + m * KST + k4)      = hp;
    *(uint2*)(out + m * KST + KK + k4) = lp;
}

__global__ void bias_concat(const float* __restrict__ b_off, const float* __restrict__ b_w,
                            float* __restrict__ bc)
{
    int i = blockIdx.x * 256 + threadIdx.x;
    if (i < NOL) bc[i] = (i < 256) ? b_off[i] : b_w[i - 256];
}

// ---------------- mma.sync split-GEMM ---------------------------------------
// C[m][n] = sum_k A32[m][k]*B32[n][k] via 3 bf16 passes (AhBh, AhBl, AlBh).
// A,B stored [rows][KST] = [hi(512)|lo(512)] bf16.
// CTA tile 128x128, 8 warps (4x2), warp tile 32x64, K-chunks of 64 (SW128 smem),
// 2-stage cp.async pipeline, fp32 accumulators in registers.
__global__ __launch_bounds__(256, 2)
void mma_gemm(const unsigned short* __restrict__ Abf,
              const unsigned short* __restrict__ Bbf,
              const float* __restrict__ bias, float* __restrict__ C,
              int Ntot, long long aStride, long long cStride)
{
    extern __shared__ __align__(1024) unsigned char smem[];  // [2][A 16K | B 16K]
    uint32_t sb = smem_u32(smem);
    const int tid = threadIdx.x;
    const int lane = tid & 31, wid = tid >> 5;
    const int warpM = wid & 3, warpN = wid >> 2;
    Abf += (size_t)blockIdx.z * aStride;
    C   += (size_t)blockIdx.z * cStride;
    const int m0 = blockIdx.y * 128, n0 = blockIdx.x * 128;

    const unsigned short* Ag = Abf + (size_t)m0 * KST;
    const unsigned short* Bg = Bbf + (size_t)n0 * KST;

    float acc[2][8][4];
    #pragma unroll
    for (int i = 0; i < 2; i++)
        #pragma unroll
        for (int j = 0; j < 8; j++)
            #pragma unroll
            for (int r = 0; r < 4; r++) acc[i][j][r] = 0.f;

    auto load_chunk = [&](int c, int buf) {
        int p = c >> 3, cc = c & 7;
        int aoff = ((p == 2) ? KK : 0) + cc * 64;   // elements
        int boff = ((p == 1) ? KK : 0) + cc * 64;
        uint32_t d = sb + buf * 32768;
        #pragma unroll
        for (int i = 0; i < 4; i++) {
            int id  = tid + i * 256;       // 0..1023
            int row = id >> 3;
            int kc  = (id & 7) * 8;        // element offset in chunk
            uint32_t so = SWZ(row * 128 + kc * 2);
            CP16(d + so,         (const char*)(Ag + (size_t)row * KST + aoff + kc));
            CP16(d + 16384 + so, (const char*)(Bg + (size_t)row * KST + boff + kc));
        }
    };

    auto compute = [&](int buf) {
        uint32_t ab = sb + buf * 32768;
        uint32_t bb = ab + 16384;
        #pragma unroll
        for (int ks = 0; ks < 4; ks++) {
            // A fragments: lanes 0-7 rows 0-7 (k lo), 8-15 rows 8-15 (k lo),
            // 16-23 rows 0-7 (k hi), 24-31 rows 8-15 (k hi)
            uint32_t afrag[2][4];
            int arow = warpM * 32 + (lane & 15);
            int akb  = ks * 32 + ((lane >> 4) & 1) * 16;   // bytes
            #pragma unroll
            for (int i = 0; i < 2; i++)
                ldmx4(afrag[i], ab + SWZ((arow + i * 16) * 128 + akb));
            // B fragments: mats = (ntile 2jp k-lo, 2jp k-hi, 2jp+1 k-lo, 2jp+1 k-hi)
            uint32_t bfrag[8][2];
            int bkb = ks * 32 + ((lane >> 3) & 1) * 16;
            #pragma unroll
            for (int jp = 0; jp < 4; jp++) {
                int nrow = warpN * 64 + jp * 16 + ((lane >> 4) & 1) * 8 + (lane & 7);
                uint32_t r[4];
                ldmx4(r, bb + SWZ(nrow * 128 + bkb));
                bfrag[2 * jp][0]     = r[0];
                bfrag[2 * jp][1]     = r[1];
                bfrag[2 * jp + 1][0] = r[2];
                bfrag[2 * jp + 1][1] = r[3];
            }
            #pragma unroll
            for (int i = 0; i < 2; i++)
                #pragma unroll
                for (int j = 0; j < 8; j++)
                    mma16816(acc[i][j], afrag[i], bfrag[j]);
        }
    };

    const int NC = 24;   // 3 passes x 8 chunks
    load_chunk(0, 0);
    CPCOMMIT();
    for (int c = 0; c < NC; c++) {
        if (c + 1 < NC) {
            load_chunk(c + 1, (c + 1) & 1);
            CPCOMMIT();
            CPWAIT1();
        } else {
            CPWAIT0();
        }
        __syncthreads();
        compute(c & 1);
        __syncthreads();
    }

    // epilogue
    int gr = lane >> 2, tg = (lane & 3) * 2;
    #pragma unroll
    for (int i = 0; i < 2; i++) {
        int row = m0 + warpM * 32 + i * 16 + gr;
        #pragma unroll
        for (int j = 0; j < 8; j++) {
            int col = n0 + warpN * 64 + j * 8 + tg;
            float b0 = 0.f, b1 = 0.f;
            if (bias) { b0 = bias[col]; b1 = bias[col + 1]; }
            *(float2*)&C[(size_t)row * Ntot + col] =
                make_float2(acc[i][j][0] + b0, acc[i][j][1] + b1);
            *(float2*)&C[(size_t)(row + 8) * Ntot + col] =
                make_float2(acc[i][j][2] + b0, acc[i][j][3] + b1);
        }
    }
}

// ---------------- softmax + bilinear gather ---------------------------------
// Writes CTX directly as bf16 split [BT][1024] for the output GEMM.
__global__ __launch_bounds__(128)
void sample2(const float* __restrict__ V,
             const float* __restrict__ OL,
             const float* __restrict__ ref,
             unsigned short* __restrict__ CTXb)
{
    int bt = blockIdx.x;
    int b  = bt >> 11;
    int tid = threadIdx.x;

    __shared__ float s_w[Hh * Pp][4];
    __shared__ int   s_i[Hh * Pp][4];

    {
        const float* olrow = OL + (long long)bt * NOL;
        float ox = olrow[2 * tid];
        float oy = olrow[2 * tid + 1];
        float lg = olrow[256 + tid];
        float rx = ref[bt * 2 + 0];
        float ry = ref[bt * 2 + 1];

        float ix = (rx + RAD * ox) * (float)(WF - 1);
        float iy = (ry + RAD * oy) * (float)(HF - 1);
        float x0f = floorf(ix), y0f = floorf(iy);
        int x0 = (int)x0f, y0 = (int)y0f;
        float fx = ix - x0f, fy = iy - y0f;

        float mx = lg;
        #pragma unroll
        for (int m = 8; m >= 1; m >>= 1)
            mx = fmaxf(mx, __shfl_xor_sync(0xffffffffu, mx, m, 16));
        float e = __expf(lg - mx);
        float s = e;
        #pragma unroll
        for (int m = 8; m >= 1; m >>= 1)
            s += __shfl_xor_sync(0xffffffffu, s, m, 16);
        float aw = e / s;

        bool vx0 = (x0 >= 0) && (x0 < WF);
        bool vx1 = (x0 + 1 >= 0) && (x0 + 1 < WF);
        bool vy0 = (y0 >= 0) && (y0 < HF);
        bool vy1 = (y0 + 1 >= 0) && (y0 + 1 < HF);
        int x0c = min(max(x0, 0), WF - 1);
        int x1c = min(max(x0 + 1, 0), WF - 1);
        int y0c = min(max(y0, 0), HF - 1);
        int y1c = min(max(y0 + 1, 0), HF - 1);

        s_w[tid][0] = (vx0 && vy0) ? (1.f - fx) * (1.f - fy) * aw : 0.f;
        s_w[tid][1] = (vx1 && vy0) ? fx * (1.f - fy) * aw : 0.f;
        s_w[tid][2] = (vx0 && vy1) ? (1.f - fx) * fy * aw : 0.f;
        s_w[tid][3] = (vx1 && vy1) ? fx * fy * aw : 0.f;
        s_i[tid][0] = y0c * WF + x0c;
        s_i[tid][1] = y0c * WF + x1c;
        s_i[tid][2] = y1c * WF + x0c;
        s_i[tid][3] = y1c * WF + x1c;
    }
    __syncthreads();

    int h  = tid >> 4;
    int c4 = tid & 15;
    const float4* Vb = (const float4*)(V + (size_t)b * HW * Dd) + (h * 16 + c4);

    float4 acc = make_float4(0.f, 0.f, 0.f, 0.f);
    #pragma unroll
    for (int p = 0; p < Pp; p++) {
        int hp = h * Pp + p;
        int4   ii = *(const int4*)s_i[hp];
        float4 ww = *(const float4*)s_w[hp];
        #pragma unroll
        for (int c = 0; c < 4; c++) {
            int   idx = (c == 0) ? ii.x : (c == 1) ? ii.y : (c == 2) ? ii.z : ii.w;
            float w   = (c == 0) ? ww.x : (c == 1) ? ww.y : (c == 2) ? ww.z : ww.w;
            float4 v = Vb[(long long)idx * (Dd / 4)];
            acc.x += w * v.x; acc.y += w * v.y;
            acc.z += w * v.z; acc.w += w * v.w;
        }
    }

    unsigned short hh[4], ll[4];
    split2(acc.x, hh[0], ll[0]); split2(acc.y, hh[1], ll[1]);
    split2(acc.z, hh[2], ll[2]); split2(acc.w, hh[3], ll[3]);
    uint2 hp2, lp2;
    hp2.x = (uint32_t)hh[0] | ((uint32_t)hh[1] << 16);
    hp2.y = (uint32_t)hh[2] | ((uint32_t)hh[3] << 16);
    lp2.x = (uint32_t)ll[0] | ((uint32_t)ll[1] << 16);
    lp2.y = (uint32_t)ll[2] | ((uint32_t)ll[3] << 16);
    unsigned short* orow = CTXb + (size_t)bt * KST + h * DH + c4 * 4;
    *(uint2*)orow        = hp2;
    *(uint2*)(orow + KK) = lp2;
}

// ---------------- launch ----------------------------------------------------
extern "C" void kernel_launch(void* const* d_in, const int* in_sizes, int n_in,
                              void* d_out, int out_size)
{
    const float* q     = (const float*)d_in[0];
    const float* fmap  = (const float*)d_in[1];
    const float* ref   = (const float*)d_in[2];
    const float* Wv    = (const float*)d_in[3];
    const float* W_off = (const float*)d_in[4];
    const float* b_off = (const float*)d_in[5];
    const float* W_w   = (const float*)d_in[6];
    const float* b_w   = (const float*)d_in[7];
    const float* W_out = (const float*)d_in[8];
    const float* b_out = (const float*)d_in[9];
    float* out = (float*)d_out;

    float *V, *OL, *bc;
    unsigned short *Ab, *qb, *CTXb, *Wvb, *Wcb, *Wob;
    cudaGetSymbolAddress((void**)&V,    g_V);
    cudaGetSymbolAddress((void**)&OL,   g_OL);
    cudaGetSymbolAddress((void**)&bc,   g_bc);
    cudaGetSymbolAddress((void**)&Ab,   g_Ab);
    cudaGetSymbolAddress((void**)&qb,   g_qb);
    cudaGetSymbolAddress((void**)&CTXb, g_CTXb);
    cudaGetSymbolAddress((void**)&Wvb,  g_Wvb);
    cudaGetSymbolAddress((void**)&Wcb,  g_Wcb);
    cudaGetSymbolAddress((void**)&Wob,  g_Wob);

    cudaFuncSetAttribute(mma_gemm, cudaFuncAttributeMaxDynamicSharedMemorySize, 65536);

    dim3 tb(32, 8);
    // fmap [B][C][HW] -> Ab [B][HW][2C]
    transpose_split<<<dim3(HW / 32, Cc / 32, Bb), tb>>>(
        fmap, Ab, Cc, HW, (long long)Cc * HW, (long long)HW * KST);
    // weights [K][N] -> [N][2K]
    transpose_split<<<dim3(Dd / 32, Cc / 32, 1), tb>>>(Wv, Wvb, Cc, Dd, 0, 0);
    transpose_split<<<dim3(256 / 32, Dd / 32, 1), tb>>>(W_off, Wcb, Dd, 256, 0, 0);
    transpose_split<<<dim3(128 / 32, Dd / 32, 1), tb>>>(W_w, Wcb + (size_t)256 * KST, Dd, 128, 0, 0);
    transpose_split<<<dim3(Dd / 32, Dd / 32, 1), tb>>>(W_out, Wob, Dd, Dd, 0, 0);
    // q -> qb
    rows_split<<<(BT * 128) / 256, 256>>>(q, qb);
    bias_concat<<<2, 256>>>(b_off, b_w, bc);

    // 1) V = fmap^T @ Wv   (per batch, 4096 x 512)
    mma_gemm<<<dim3(Dd / 128, HW / 128, Bb), 256, 65536>>>(
        Ab, Wvb, nullptr, V, Dd, (long long)HW * KST, (long long)HW * Dd);
    // 2) OL = q @ [W_off|W_w] + bc   (8192 x 384)
    mma_gemm<<<dim3(NOL / 128, BT / 128, 1), 256, 65536>>>(
        qb, Wcb, bc, OL, NOL, 0, 0);
    // 3) softmax + bilinear gather -> CTXb (bf16 split)
    sample2<<<BT, 128>>>(V, OL, ref, CTXb);
    // 4) out = CTX @ W_out + b_out   (8192 x 512)
    mma_gemm<<<dim3(Dd / 128, BT / 128, 1), 256, 65536>>>(
        CTXb, Wob, b_out, out, Dd, 0, 0);
}

// round 6
// speedup vs baseline: 2.8006x; 1.0655x over previous
#include <cuda_runtime.h>
#include <cuda_bf16.h>
#include <cstdint>

// ---------------- problem constants ----------------
#define Bb   4
#define Tt   2048
#define Dd   512
#define Hh   8
#define Pp   16
#define DH   64
#define Cc   512
#define HF   64
#define WF   64
#define RAD  0.08f
#define BT   (Bb*Tt)        // 8192
#define HW   (HF*WF)        // 4096
#define NOL  384            // 256 (offsets) + 128 (logits)
#define KK   512            // inner dim of every GEMM
#define KST  1024           // stored K: [hi(512) | lo(512)]

// ---------------- scratch (static device globals) --------------------------
__device__ float g_V[(size_t)Bb * HW * Dd];        // value proj, (B, HW, D) fp32
__device__ float g_OL[(size_t)BT * NOL];           // [off(256) | logits(128)] fp32
__device__ float g_bc[NOL];
__device__ __align__(256) unsigned short g_Ab [(size_t)Bb * HW * KST];  // fmap^T split
__device__ __align__(256) unsigned short g_qb [(size_t)BT * KST];       // q split
__device__ __align__(256) unsigned short g_CTXb[(size_t)BT * KST];      // ctx split
__device__ __align__(256) unsigned short g_Wvb[(size_t)Dd * KST];       // Wv^T split
__device__ __align__(256) unsigned short g_Wcb[(size_t)NOL * KST];      // [W_off|W_w]^T
__device__ __align__(256) unsigned short g_Wob[(size_t)Dd * KST];       // W_out^T split

// ---------------- PTX helpers (baseline sm_80-class; compile at compute_103) -
__device__ __forceinline__ uint32_t smem_u32(const void* p) {
    uint32_t a;
    asm("{ .reg .u64 t; cvta.to.shared.u64 t, %1; cvt.u32.u64 %0, t; }"
        : "=r"(a) : "l"(p));
    return a;
}
#define SWZ(o) ((o) ^ (((o) >> 3) & 0x70))
#define CP16(dst, src) \
    asm volatile("cp.async.cg.shared.global [%0], [%1], 16;" \
                 :: "r"(dst), "l"(src))
#define CPCOMMIT() asm volatile("cp.async.commit_group;" ::: "memory")
#define CPWAIT0()  asm volatile("cp.async.wait_group 0;" ::: "memory")
#define CPWAIT1()  asm volatile("cp.async.wait_group 1;" ::: "memory")

__device__ __forceinline__ void ldmx4(uint32_t r[4], uint32_t addr) {
    asm volatile("ldmatrix.sync.aligned.m8n8.x4.shared.b16 {%0,%1,%2,%3}, [%4];"
        : "=r"(r[0]), "=r"(r[1]), "=r"(r[2]), "=r"(r[3]) : "r"(addr));
}
__device__ __forceinline__ void mma16816(float d[4], const uint32_t a[4],
                                         const uint32_t b[2]) {
    asm volatile(
        "mma.sync.aligned.m16n8k16.row.col.f32.bf16.bf16.f32 "
        "{%0,%1,%2,%3}, {%4,%5,%6,%7}, {%8,%9}, {%0,%1,%2,%3};"
        : "+f"(d[0]), "+f"(d[1]), "+f"(d[2]), "+f"(d[3])
        : "r"(a[0]), "r"(a[1]), "r"(a[2]), "r"(a[3]), "r"(b[0]), "r"(b[1]));
}

// ---------------- split helpers ---------------------------------------------
__device__ __forceinline__ void split2(float x, unsigned short& h, unsigned short& l) {
    __nv_bfloat16 hb = __float2bfloat16(x);
    __nv_bfloat16 lb = __float2bfloat16(x - __bfloat162float(hb));
    h = *reinterpret_cast<unsigned short*>(&hb);
    l = *reinterpret_cast<unsigned short*>(&lb);
}

// ---------------- fused prologue --------------------------------------------
// One launch does: fmap transpose+split, 4 weight transpose+splits, q row
// split, bias concat.  Block-range dispatch; every block has 256 threads.
//   [0,8192)        fmap [B][C][HW] -> Ab [B][HW][2C]       nx=128, ny=16, bz=4
//   [8192,8448)     Wv    [C][D]    -> Wvb [D][2C]          nx=16,  ny=16
//   [8448,8576)     W_off [D][256]  -> Wcb[0:256]           nx=8,   ny=16
//   [8576,8640)     W_w   [D][128]  -> Wcb[256:384]         nx=4,   ny=16
//   [8640,8896)     W_out [D][D]    -> Wob                  nx=16,  ny=16
//   [8896,12992)    q rows_split -> qb                      4096 blocks
//   [12992,12994)   bias concat -> bc
#define PRO_BLOCKS 12994
__global__ __launch_bounds__(256)
void prologue(const float* __restrict__ fmap, const float* __restrict__ Wv,
              const float* __restrict__ W_off, const float* __restrict__ W_w,
              const float* __restrict__ W_out, const float* __restrict__ q,
              const float* __restrict__ b_off, const float* __restrict__ b_w,
              unsigned short* __restrict__ Ab,  unsigned short* __restrict__ Wvb,
              unsigned short* __restrict__ Wcb, unsigned short* __restrict__ Wob,
              unsigned short* __restrict__ qb,  float* __restrict__ bc)
{
    __shared__ float t[32][33];
    const int bid = blockIdx.x;
    const int tid = threadIdx.x;
    const int tx = tid & 31, ty = tid >> 5;

    auto tbody = [&](const float* in, unsigned short* out, int K, int N,
                     int bx, int by) {
        int n0 = bx * 32, k0 = by * 32;
        #pragma unroll
        for (int i = ty; i < 32; i += 8)
            t[i][tx] = in[(size_t)(k0 + i) * N + n0 + tx];
        __syncthreads();
        #pragma unroll
        for (int i = ty; i < 32; i += 8) {
            int n = n0 + i, k = k0 + tx;
            unsigned short h, l;
            split2(t[tx][i], h, l);
            out[(size_t)n * (2 * K) + k]     = h;
            out[(size_t)n * (2 * K) + K + k] = l;
        }
    };

    if (bid < 8192) {
        int r = bid;
        int bx = r & 127; r >>= 7;
        int by = r & 15;  int bz = r >> 4;
        tbody(fmap + (size_t)bz * Cc * HW, Ab + (size_t)bz * HW * KST,
              Cc, HW, bx, by);
    } else if (bid < 8448) {
        int r = bid - 8192;
        tbody(Wv, Wvb, Cc, Dd, r & 15, r >> 4);
    } else if (bid < 8576) {
        int r = bid - 8448;
        tbody(W_off, Wcb, Dd, 256, r & 7, r >> 3);
    } else if (bid < 8640) {
        int r = bid - 8576;
        tbody(W_w, Wcb + (size_t)256 * KST, Dd, 128, r & 3, r >> 2);
    } else if (bid < 8896) {
        int r = bid - 8640;
        tbody(W_out, Wob, Dd, Dd, r & 15, r >> 4);
    } else if (bid < 12992) {
        size_t i = (size_t)(bid - 8896) * 256 + tid;   // over BT*128
        size_t m = i >> 7;
        int k4 = (int)(i & 127) * 4;
        float4 v = *(const float4*)(q + m * KK + k4);
        unsigned short h[4], l[4];
        split2(v.x, h[0], l[0]); split2(v.y, h[1], l[1]);
        split2(v.z, h[2], l[2]); split2(v.w, h[3], l[3]);
        uint2 hp, lp;
        hp.x = (uint32_t)h[0] | ((uint32_t)h[1] << 16);
        hp.y = (uint32_t)h[2] | ((uint32_t)h[3] << 16);
        lp.x = (uint32_t)l[0] | ((uint32_t)l[1] << 16);
        lp.y = (uint32_t)l[2] | ((uint32_t)l[3] << 16);
        *(uint2*)(qb + m * KST + k4)      = hp;
        *(uint2*)(qb + m * KST + KK + k4) = lp;
    } else {
        int i = (bid - 12992) * 256 + tid;
        if (i < NOL) bc[i] = (i < 256) ? b_off[i] : b_w[i - 256];
    }
}

// ---------------- mma.sync split-GEMM ---------------------------------------
// C[m][n] = sum_k A32[m][k]*B32[n][k] via 3 bf16 passes (AhBh, AhBl, AlBh).
// A,B stored [rows][KST] = [hi(512)|lo(512)] bf16.
// CTA tile 128xBN.  Warps: 4(M) x BN/64(N), warp tile 32x64.  K-chunks of 64
// (SW128 smem), 2-stage cp.async pipeline, fp32 accumulators in registers.
template<int BN>
__global__ __launch_bounds__(2 * BN, (BN == 128) ? 2 : 1)
void mma_gemm(const unsigned short* __restrict__ Abf,
              const unsigned short* __restrict__ Bbf,
              const float* __restrict__ bias, float* __restrict__ C,
              int Ntot, long long aStride, long long cStride)
{
    constexpr int THREADS = 2 * BN;
    constexpr int STAGE   = 16384 + BN * 128;
    constexpr int OPS     = (128 + BN) * 8 / THREADS;
    extern __shared__ __align__(1024) unsigned char smem[];
    uint32_t sb = smem_u32(smem);
    const int tid = threadIdx.x;
    const int lane = tid & 31, wid = tid >> 5;
    const int warpM = wid & 3, warpN = wid >> 2;
    Abf += (size_t)blockIdx.z * aStride;
    C   += (size_t)blockIdx.z * cStride;
    const int m0 = blockIdx.y * 128, n0 = blockIdx.x * BN;

    const unsigned short* Ag = Abf + (size_t)m0 * KST;
    const unsigned short* Bg = Bbf + (size_t)n0 * KST;

    float acc[2][8][4];
    #pragma unroll
    for (int i = 0; i < 2; i++)
        #pragma unroll
        for (int j = 0; j < 8; j++)
            #pragma unroll
            for (int r = 0; r < 4; r++) acc[i][j][r] = 0.f;

    auto load_chunk = [&](int c, int buf) {
        int p = c >> 3, cc = c & 7;
        int aoff = ((p == 2) ? KK : 0) + cc * 64;   // elements
        int boff = ((p == 1) ? KK : 0) + cc * 64;
        uint32_t d = sb + buf * STAGE;
        #pragma unroll
        for (int i = 0; i < OPS; i++) {
            int id  = tid + i * THREADS;
            int row = id >> 3;
            int kc  = (id & 7) * 8;        // element offset in chunk
            if (row < 128) {
                CP16(d + SWZ(row * 128 + kc * 2),
                     (const char*)(Ag + (size_t)row * KST + aoff + kc));
            } else {
                int br = row - 128;
                CP16(d + 16384 + SWZ(br * 128 + kc * 2),
                     (const char*)(Bg + (size_t)br * KST + boff + kc));
            }
        }
    };

    auto compute = [&](int buf) {
        uint32_t ab = sb + buf * STAGE;
        uint32_t bb = ab + 16384;
        #pragma unroll
        for (int ks = 0; ks < 4; ks++) {
            uint32_t afrag[2][4];
            int arow = warpM * 32 + (lane & 15);
            int akb  = ks * 32 + ((lane >> 4) & 1) * 16;   // bytes
            #pragma unroll
            for (int i = 0; i < 2; i++)
                ldmx4(afrag[i], ab + SWZ((arow + i * 16) * 128 + akb));
            uint32_t bfrag[8][2];
            int bkb = ks * 32 + ((lane >> 3) & 1) * 16;
            #pragma unroll
            for (int jp = 0; jp < 4; jp++) {
                int nrow = warpN * 64 + jp * 16 + ((lane >> 4) & 1) * 8 + (lane & 7);
                uint32_t r[4];
                ldmx4(r, bb + SWZ(nrow * 128 + bkb));
                bfrag[2 * jp][0]     = r[0];
                bfrag[2 * jp][1]     = r[1];
                bfrag[2 * jp + 1][0] = r[2];
                bfrag[2 * jp + 1][1] = r[3];
            }
            #pragma unroll
            for (int i = 0; i < 2; i++)
                #pragma unroll
                for (int j = 0; j < 8; j++)
                    mma16816(acc[i][j], afrag[i], bfrag[j]);
        }
    };

    const int NC = 24;   // 3 passes x 8 chunks
    load_chunk(0, 0);
    CPCOMMIT();
    for (int c = 0; c < NC; c++) {
        if (c + 1 < NC) {
            load_chunk(c + 1, (c + 1) & 1);
            CPCOMMIT();
            CPWAIT1();
        } else {
            CPWAIT0();
        }
        __syncthreads();
        compute(c & 1);
        __syncthreads();
    }

    // epilogue
    int gr = lane >> 2, tg = (lane & 3) * 2;
    #pragma unroll
    for (int i = 0; i < 2; i++) {
        int row = m0 + warpM * 32 + i * 16 + gr;
        #pragma unroll
        for (int j = 0; j < 8; j++) {
            int col = n0 + warpN * 64 + j * 8 + tg;
            float b0 = 0.f, b1 = 0.f;
            if (bias) { b0 = bias[col]; b1 = bias[col + 1]; }
            *(float2*)&C[(size_t)row * Ntot + col] =
                make_float2(acc[i][j][0] + b0, acc[i][j][1] + b1);
            *(float2*)&C[(size_t)(row + 8) * Ntot + col] =
                make_float2(acc[i][j][2] + b0, acc[i][j][3] + b1);
        }
    }
}

// ---------------- softmax + bilinear gather ---------------------------------
// Writes CTX directly as bf16 split [BT][1024] for the output GEMM.
__global__ __launch_bounds__(128)
void sample2(const float* __restrict__ V,
             const float* __restrict__ OL,
             const float* __restrict__ ref,
             unsigned short* __restrict__ CTXb)
{
    int bt = blockIdx.x;
    int b  = bt >> 11;
    int tid = threadIdx.x;

    __shared__ float s_w[Hh * Pp][4];
    __shared__ int   s_i[Hh * Pp][4];

    {
        const float* olrow = OL + (long long)bt * NOL;
        float ox = olrow[2 * tid];
        float oy = olrow[2 * tid + 1];
        float lg = olrow[256 + tid];
        float rx = ref[bt * 2 + 0];
        float ry = ref[bt * 2 + 1];

        float ix = (rx + RAD * ox) * (float)(WF - 1);
        float iy = (ry + RAD * oy) * (float)(HF - 1);
        float x0f = floorf(ix), y0f = floorf(iy);
        int x0 = (int)x0f, y0 = (int)y0f;
        float fx = ix - x0f, fy = iy - y0f;

        float mx = lg;
        #pragma unroll
        for (int m = 8; m >= 1; m >>= 1)
            mx = fmaxf(mx, __shfl_xor_sync(0xffffffffu, mx, m, 16));
        float e = __expf(lg - mx);
        float s = e;
        #pragma unroll
        for (int m = 8; m >= 1; m >>= 1)
            s += __shfl_xor_sync(0xffffffffu, s, m, 16);
        float aw = e / s;

        bool vx0 = (x0 >= 0) && (x0 < WF);
        bool vx1 = (x0 + 1 >= 0) && (x0 + 1 < WF);
        bool vy0 = (y0 >= 0) && (y0 < HF);
        bool vy1 = (y0 + 1 >= 0) && (y0 + 1 < HF);
        int x0c = min(max(x0, 0), WF - 1);
        int x1c = min(max(x0 + 1, 0), WF - 1);
        int y0c = min(max(y0, 0), HF - 1);
        int y1c = min(max(y0 + 1, 0), HF - 1);

        s_w[tid][0] = (vx0 && vy0) ? (1.f - fx) * (1.f - fy) * aw : 0.f;
        s_w[tid][1] = (vx1 && vy0) ? fx * (1.f - fy) * aw : 0.f;
        s_w[tid][2] = (vx0 && vy1) ? (1.f - fx) * fy * aw : 0.f;
        s_w[tid][3] = (vx1 && vy1) ? fx * fy * aw : 0.f;
        s_i[tid][0] = y0c * WF + x0c;
        s_i[tid][1] = y0c * WF + x1c;
        s_i[tid][2] = y1c * WF + x0c;
        s_i[tid][3] = y1c * WF + x1c;
    }
    __syncthreads();

    int h  = tid >> 4;
    int c4 = tid & 15;
    const float4* Vb = (const float4*)(V + (size_t)b * HW * Dd) + (h * 16 + c4);

    float4 acc = make_float4(0.f, 0.f, 0.f, 0.f);
    #pragma unroll
    for (int p = 0; p < Pp; p++) {
        int hp = h * Pp + p;
        int4   ii = *(const int4*)s_i[hp];
        float4 ww = *(const float4*)s_w[hp];
        #pragma unroll
        for (int c = 0; c < 4; c++) {
            int   idx = (c == 0) ? ii.x : (c == 1) ? ii.y : (c == 2) ? ii.z : ii.w;
            float w   = (c == 0) ? ww.x : (c == 1) ? ww.y : (c == 2) ? ww.z : ww.w;
            float4 v = Vb[(long long)idx * (Dd / 4)];
            acc.x += w * v.x; acc.y += w * v.y;
            acc.z += w * v.z; acc.w += w * v.w;
        }
    }

    unsigned short hh[4], ll[4];
    split2(acc.x, hh[0], ll[0]); split2(acc.y, hh[1], ll[1]);
    split2(acc.z, hh[2], ll[2]); split2(acc.w, hh[3], ll[3]);
    uint2 hp2, lp2;
    hp2.x = (uint32_t)hh[0] | ((uint32_t)hh[1] << 16);
    hp2.y = (uint32_t)hh[2] | ((uint32_t)hh[3] << 16);
    lp2.x = (uint32_t)ll[0] | ((uint32_t)ll[1] << 16);
    lp2.y = (uint32_t)ll[2] | ((uint32_t)ll[3] << 16);
    unsigned short* orow = CTXb + (size_t)bt * KST + h * DH + c4 * 4;
    *(uint2*)orow        = hp2;
    *(uint2*)(orow + KK) = lp2;
}

// ---------------- launch ----------------------------------------------------
extern "C" void kernel_launch(void* const* d_in, const int* in_sizes, int n_in,
                              void* d_out, int out_size)
{
    const float* q     = (const float*)d_in[0];
    const float* fmap  = (const float*)d_in[1];
    const float* ref   = (const float*)d_in[2];
    const float* Wv    = (const float*)d_in[3];
    const float* W_off = (const float*)d_in[4];
    const float* b_off = (const float*)d_in[5];
    const float* W_w   = (const float*)d_in[6];
    const float* b_w   = (const float*)d_in[7];
    const float* W_out = (const float*)d_in[8];
    const float* b_out = (const float*)d_in[9];
    float* out = (float*)d_out;

    float *V, *OL, *bc;
    unsigned short *Ab, *qb, *CTXb, *Wvb, *Wcb, *Wob;
    cudaGetSymbolAddress((void**)&V,    g_V);
    cudaGetSymbolAddress((void**)&OL,   g_OL);
    cudaGetSymbolAddress((void**)&bc,   g_bc);
    cudaGetSymbolAddress((void**)&Ab,   g_Ab);
    cudaGetSymbolAddress((void**)&qb,   g_qb);
    cudaGetSymbolAddress((void**)&CTXb, g_CTXb);
    cudaGetSymbolAddress((void**)&Wvb,  g_Wvb);
    cudaGetSymbolAddress((void**)&Wcb,  g_Wcb);
    cudaGetSymbolAddress((void**)&Wob,  g_Wob);

    cudaFuncSetAttribute(mma_gemm<128>, cudaFuncAttributeMaxDynamicSharedMemorySize, 65536);
    cudaFuncSetAttribute(mma_gemm<256>, cudaFuncAttributeMaxDynamicSharedMemorySize, 98304);

    // 0) fused conversions
    prologue<<<PRO_BLOCKS, 256>>>(fmap, Wv, W_off, W_w, W_out, q, b_off, b_w,
                                  Ab, Wvb, Wcb, Wob, qb, bc);

    // 1) V = fmap^T @ Wv   (per batch, 4096 x 512)
    mma_gemm<256><<<dim3(Dd / 256, HW / 128, Bb), 512, 98304>>>(
        Ab, Wvb, nullptr, V, Dd, (long long)HW * KST, (long long)HW * Dd);
    // 2) OL = q @ [W_off|W_w] + bc   (8192 x 384)
    mma_gemm<128><<<dim3(NOL / 128, BT / 128, 1), 256, 65536>>>(
        qb, Wcb, bc, OL, NOL, 0, 0);
    // 3) softmax + bilinear gather -> CTXb (bf16 split)
    sample2<<<BT, 128>>>(V, OL, ref, CTXb);
    // 4) out = CTX @ W_out + b_out   (8192 x 512)
    mma_gemm<256><<<dim3(Dd / 256, BT / 128, 1), 512, 98304>>>(
        CTXb, Wob, b_out, out, Dd, 0, 0);
}

// round 8
// speedup vs baseline: 2.8705x; 1.0250x over previous
#include <cuda_runtime.h>
#include <cuda_bf16.h>
#include <cstdint>

// ---------------- problem constants ----------------
#define Bb   4
#define Tt   2048
#define Dd   512
#define Hh   8
#define Pp   16
#define DH   64
#define Cc   512
#define HF   64
#define WF   64
#define RAD  0.08f
#define BT   (Bb*Tt)        // 8192
#define HW   (HF*WF)        // 4096
#define NOL  384            // 256 (offsets) + 128 (logits)
#define KK   512            // inner dim of every GEMM
#define KST  1024           // stored K: [hi(512) | lo(512)]

// ---------------- scratch (static device globals) --------------------------
__device__ float g_V[(size_t)Bb * HW * Dd];        // value proj, (B, HW, D) fp32
__device__ float g_OL[(size_t)BT * NOL];           // [off(256) | logits(128)] fp32
__device__ float g_bc[NOL];
__device__ __align__(256) unsigned short g_Ab [(size_t)Bb * HW * KST];  // fmap^T split
__device__ __align__(256) unsigned short g_qb [(size_t)BT * KST];       // q split
__device__ __align__(256) unsigned short g_CTXb[(size_t)BT * KST];      // ctx split
__device__ __align__(256) unsigned short g_Wvb[(size_t)Dd * KST];       // Wv^T split
__device__ __align__(256) unsigned short g_Wcb[(size_t)NOL * KST];      // [W_off|W_w]^T
__device__ __align__(256) unsigned short g_Wob[(size_t)Dd * KST];       // W_out^T split

// ---------------- PTX helpers (baseline sm_80-class; compile at compute_103) -
__device__ __forceinline__ uint32_t smem_u32(const void* p) {
    uint32_t a;
    asm("{ .reg .u64 t; cvta.to.shared.u64 t, %1; cvt.u32.u64 %0, t; }"
        : "=r"(a) : "l"(p));
    return a;
}
#define SWZ(o) ((o) ^ (((o) >> 3) & 0x70))
#define CP16(dst, src) \
    asm volatile("cp.async.cg.shared.global [%0], [%1], 16;" \
                 :: "r"(dst), "l"(src))
#define CPCOMMIT() asm volatile("cp.async.commit_group;" ::: "memory")
#define CPWAIT0()  asm volatile("cp.async.wait_group 0;" ::: "memory")
#define CPWAIT1()  asm volatile("cp.async.wait_group 1;" ::: "memory")

__device__ __forceinline__ void ldmx4(uint32_t r[4], uint32_t addr) {
    asm volatile("ldmatrix.sync.aligned.m8n8.x4.shared.b16 {%0,%1,%2,%3}, [%4];"
        : "=r"(r[0]), "=r"(r[1]), "=r"(r[2]), "=r"(r[3]) : "r"(addr));
}
__device__ __forceinline__ void mma16816(float d[4], const uint32_t a[4],
                                         const uint32_t b[2]) {
    asm volatile(
        "mma.sync.aligned.m16n8k16.row.col.f32.bf16.bf16.f32 "
        "{%0,%1,%2,%3}, {%4,%5,%6,%7}, {%8,%9}, {%0,%1,%2,%3};"
        : "+f"(d[0]), "+f"(d[1]), "+f"(d[2]), "+f"(d[3])
        : "r"(a[0]), "r"(a[1]), "r"(a[2]), "r"(a[3]), "r"(b[0]), "r"(b[1]));
}

// ---------------- split helpers ---------------------------------------------
__device__ __forceinline__ void split2(float x, unsigned short& h, unsigned short& l) {
    __nv_bfloat16 hb = __float2bfloat16(x);
    __nv_bfloat16 lb = __float2bfloat16(x - __bfloat162float(hb));
    h = *reinterpret_cast<unsigned short*>(&hb);
    l = *reinterpret_cast<unsigned short*>(&lb);
}

// ---------------- fused prologue --------------------------------------------
// One launch does: fmap transpose+split, 4 weight transpose+splits, q row
// split, bias concat.  Block-range dispatch; every block has 256 threads.
#define PRO_BLOCKS 12994
__global__ __launch_bounds__(256)
void prologue(const float* __restrict__ fmap, const float* __restrict__ Wv,
              const float* __restrict__ W_off, const float* __restrict__ W_w,
              const float* __restrict__ W_out, const float* __restrict__ q,
              const float* __restrict__ b_off, const float* __restrict__ b_w,
              unsigned short* __restrict__ Ab,  unsigned short* __restrict__ Wvb,
              unsigned short* __restrict__ Wcb, unsigned short* __restrict__ Wob,
              unsigned short* __restrict__ qb,  float* __restrict__ bc)
{
    __shared__ float t[32][33];
    const int bid = blockIdx.x;
    const int tid = threadIdx.x;
    const int tx = tid & 31, ty = tid >> 5;

    auto tbody = [&](const float* in, unsigned short* out, int K, int N,
                     int bx, int by) {
        int n0 = bx * 32, k0 = by * 32;
        #pragma unroll
        for (int i = ty; i < 32; i += 8)
            t[i][tx] = in[(size_t)(k0 + i) * N + n0 + tx];
        __syncthreads();
        #pragma unroll
        for (int i = ty; i < 32; i += 8) {
            int n = n0 + i, k = k0 + tx;
            unsigned short h, l;
            split2(t[tx][i], h, l);
            out[(size_t)n * (2 * K) + k]     = h;
            out[(size_t)n * (2 * K) + K + k] = l;
        }
    };

    if (bid < 8192) {
        int r = bid;
        int bx = r & 127; r >>= 7;
        int by = r & 15;  int bz = r >> 4;
        tbody(fmap + (size_t)bz * Cc * HW, Ab + (size_t)bz * HW * KST,
              Cc, HW, bx, by);
    } else if (bid < 8448) {
        int r = bid - 8192;
        tbody(Wv, Wvb, Cc, Dd, r & 15, r >> 4);
    } else if (bid < 8576) {
        int r = bid - 8448;
        tbody(W_off, Wcb, Dd, 256, r & 7, r >> 3);
    } else if (bid < 8640) {
        int r = bid - 8576;
        tbody(W_w, Wcb + (size_t)256 * KST, Dd, 128, r & 3, r >> 2);
    } else if (bid < 8896) {
        int r = bid - 8640;
        tbody(W_out, Wob, Dd, Dd, r & 15, r >> 4);
    } else if (bid < 12992) {
        size_t i = (size_t)(bid - 8896) * 256 + tid;   // over BT*128
        size_t m = i >> 7;
        int k4 = (int)(i & 127) * 4;
        float4 v = *(const float4*)(q + m * KK + k4);
        unsigned short h[4], l[4];
        split2(v.x, h[0], l[0]); split2(v.y, h[1], l[1]);
        split2(v.z, h[2], l[2]); split2(v.w, h[3], l[3]);
        uint2 hp, lp;
        hp.x = (uint32_t)h[0] | ((uint32_t)h[1] << 16);
        hp.y = (uint32_t)h[2] | ((uint32_t)h[3] << 16);
        lp.x = (uint32_t)l[0] | ((uint32_t)l[1] << 16);
        lp.y = (uint32_t)l[2] | ((uint32_t)l[3] << 16);
        *(uint2*)(qb + m * KST + k4)      = hp;
        *(uint2*)(qb + m * KST + KK + k4) = lp;
    } else {
        int i = (bid - 12992) * 256 + tid;
        if (i < NOL) bc[i] = (i < 256) ? b_off[i] : b_w[i - 256];
    }
}

// ---------------- mma.sync split-GEMM (3-stage pipeline) --------------------
// C[m][n] = sum_k A32[m][k]*B32[n][k] via 3 bf16 passes (AhBh, AhBl, AlBh).
// A,B stored [rows][KST] = [hi(512)|lo(512)] bf16.
// CTA tile 128x128, 8 warps (4x2), warp tile 32x64.  K-chunks of 64 (SW128
// smem), 3-stage cp.async pipeline, ONE __syncthreads per chunk,
// 2 CTAs/SM.  fp32 accumulators in registers.
#define STAGE 32768          // A 16K + B 16K per stage
#define GSMEM (3 * STAGE)    // 96 KB
__global__ __launch_bounds__(256, 2)
void mma_gemm(const unsigned short* __restrict__ Abf,
              const unsigned short* __restrict__ Bbf,
              const float* __restrict__ bias, float* __restrict__ C,
              int Ntot, long long aStride, long long cStride)
{
    extern __shared__ __align__(1024) unsigned char smem[];
    uint32_t sb = smem_u32(smem);
    const int tid = threadIdx.x;
    const int lane = tid & 31, wid = tid >> 5;
    const int warpM = wid & 3, warpN = wid >> 2;
    Abf += (size_t)blockIdx.z * aStride;
    C   += (size_t)blockIdx.z * cStride;
    const int m0 = blockIdx.y * 128, n0 = blockIdx.x * 128;

    const unsigned short* Ag = Abf + (size_t)m0 * KST;
    const unsigned short* Bg = Bbf + (size_t)n0 * KST;

    float acc[2][8][4];
    #pragma unroll
    for (int i = 0; i < 2; i++)
        #pragma unroll
        for (int j = 0; j < 8; j++)
            #pragma unroll
            for (int r = 0; r < 4; r++) acc[i][j][r] = 0.f;

    auto load_chunk = [&](int c, int buf) {
        int p = c >> 3, cc = c & 7;
        int aoff = ((p == 2) ? KK : 0) + cc * 64;   // elements
        int boff = ((p == 1) ? KK : 0) + cc * 64;
        uint32_t d = sb + buf * STAGE;
        #pragma unroll
        for (int i = 0; i < 8; i++) {
            int id  = tid + i * 256;       // 0..2047
            int row = id >> 3;
            int kc  = (id & 7) * 8;        // element offset in chunk
            if (row < 128) {
                CP16(d + SWZ(row * 128 + kc * 2),
                     (const char*)(Ag + (size_t)row * KST + aoff + kc));
            } else {
                int br = row - 128;
                CP16(d + 16384 + SWZ(br * 128 + kc * 2),
                     (const char*)(Bg + (size_t)br * KST + boff + kc));
            }
        }
    };

    auto compute = [&](int buf) {
        uint32_t ab = sb + buf * STAGE;
        uint32_t bb = ab + 16384;
        #pragma unroll
        for (int ks = 0; ks < 4; ks++) {
            uint32_t afrag[2][4];
            int arow = warpM * 32 + (lane & 15);
            int akb  = ks * 32 + ((lane >> 4) & 1) * 16;   // bytes
            #pragma unroll
            for (int i = 0; i < 2; i++)
                ldmx4(afrag[i], ab + SWZ((arow + i * 16) * 128 + akb));
            uint32_t bfrag[8][2];
            int bkb = ks * 32 + ((lane >> 3) & 1) * 16;
            #pragma unroll
            for (int jp = 0; jp < 4; jp++) {
                int nrow = warpN * 64 + jp * 16 + ((lane >> 4) & 1) * 8 + (lane & 7);
                uint32_t r[4];
                ldmx4(r, bb + SWZ(nrow * 128 + bkb));
                bfrag[2 * jp][0]     = r[0];
                bfrag[2 * jp][1]     = r[1];
                bfrag[2 * jp + 1][0] = r[2];
                bfrag[2 * jp + 1][1] = r[3];
            }
            #pragma unroll
            for (int i = 0; i < 2; i++)
                #pragma unroll
                for (int j = 0; j < 8; j++)
                    mma16816(acc[i][j], afrag[i], bfrag[j]);
        }
    };

    const int NC = 24;   // 3 passes x 8 chunks
    load_chunk(0, 0);
    CPCOMMIT();
    load_chunk(1, 1);
    CPCOMMIT();
    int buf = 0;
    #pragma unroll 1
    for (int c = 0; c < NC; c++) {
        if (c + 2 < NC) CPWAIT1(); else CPWAIT0();
        __syncthreads();
        if (c + 2 < NC) {
            int nb = buf + 2; if (nb >= 3) nb -= 3;
            load_chunk(c + 2, nb);
            CPCOMMIT();
        }
        compute(buf);
        if (++buf == 3) buf = 0;
    }

    // epilogue
    int gr = lane >> 2, tg = (lane & 3) * 2;
    #pragma unroll
    for (int i = 0; i < 2; i++) {
        int row = m0 + warpM * 32 + i * 16 + gr;
        #pragma unroll
        for (int j = 0; j < 8; j++) {
            int col = n0 + warpN * 64 + j * 8 + tg;
            float b0 = 0.f, b1 = 0.f;
            if (bias) { b0 = bias[col]; b1 = bias[col + 1]; }
            *(float2*)&C[(size_t)row * Ntot + col] =
                make_float2(acc[i][j][0] + b0, acc[i][j][1] + b1);
            *(float2*)&C[(size_t)(row + 8) * Ntot + col] =
                make_float2(acc[i][j][2] + b0, acc[i][j][3] + b1);
        }
    }
}

// ---------------- softmax + bilinear gather ---------------------------------
// Writes CTX directly as bf16 split [BT][1024] for the output GEMM.
__global__ __launch_bounds__(128)
void sample2(const float* __restrict__ V,
             const float* __restrict__ OL,
             const float* __restrict__ ref,
             unsigned short* __restrict__ CTXb)
{
    int bt = blockIdx.x;
    int b  = bt >> 11;
    int tid = threadIdx.x;

    __shared__ float s_w[Hh * Pp][4];
    __shared__ int   s_i[Hh * Pp][4];

    {
        const float* olrow = OL + (long long)bt * NOL;
        float ox = olrow[2 * tid];
        float oy = olrow[2 * tid + 1];
        float lg = olrow[256 + tid];
        float rx = ref[bt * 2 + 0];
        float ry = ref[bt * 2 + 1];

        float ix = (rx + RAD * ox) * (float)(WF - 1);
        float iy = (ry + RAD * oy) * (float)(HF - 1);
        float x0f = floorf(ix), y0f = floorf(iy);
        int x0 = (int)x0f, y0 = (int)y0f;
        float fx = ix - x0f, fy = iy - y0f;

        float mx = lg;
        #pragma unroll
        for (int m = 8; m >= 1; m >>= 1)
            mx = fmaxf(mx, __shfl_xor_sync(0xffffffffu, mx, m, 16));
        float e = __expf(lg - mx);
        float s = e;
        #pragma unroll
        for (int m = 8; m >= 1; m >>= 1)
            s += __shfl_xor_sync(0xffffffffu, s, m, 16);
        float aw = e / s;

        bool vx0 = (x0 >= 0) && (x0 < WF);
        bool vx1 = (x0 + 1 >= 0) && (x0 + 1 < WF);
        bool vy0 = (y0 >= 0) && (y0 < HF);
        bool vy1 = (y0 + 1 >= 0) && (y0 + 1 < HF);
        int x0c = min(max(x0, 0), WF - 1);
        int x1c = min(max(x0 + 1, 0), WF - 1);
        int y0c = min(max(y0, 0), HF - 1);
        int y1c = min(max(y0 + 1, 0), HF - 1);

        s_w[tid][0] = (vx0 && vy0) ? (1.f - fx) * (1.f - fy) * aw : 0.f;
        s_w[tid][1] = (vx1 && vy0) ? fx * (1.f - fy) * aw : 0.f;
        s_w[tid][2] = (vx0 && vy1) ? (1.f - fx) * fy * aw : 0.f;
        s_w[tid][3] = (vx1 && vy1) ? fx * fy * aw : 0.f;
        s_i[tid][0] = y0c * WF + x0c;
        s_i[tid][1] = y0c * WF + x1c;
        s_i[tid][2] = y1c * WF + x0c;
        s_i[tid][3] = y1c * WF + x1c;
    }
    __syncthreads();

    int h  = tid >> 4;
    int c4 = tid & 15;
    const float4* Vb = (const float4*)(V + (size_t)b * HW * Dd) + (h * 16 + c4);

    float4 acc = make_float4(0.f, 0.f, 0.f, 0.f);
    #pragma unroll
    for (int p = 0; p < Pp; p++) {
        int hp = h * Pp + p;
        int4   ii = *(const int4*)s_i[hp];
        float4 ww = *(const float4*)s_w[hp];
        #pragma unroll
        for (int c = 0; c < 4; c++) {
            int   idx = (c == 0) ? ii.x : (c == 1) ? ii.y : (c == 2) ? ii.z : ii.w;
            float w   = (c == 0) ? ww.x : (c == 1) ? ww.y : (c == 2) ? ww.z : ww.w;
            float4 v = Vb[(long long)idx * (Dd / 4)];
            acc.x += w * v.x; acc.y += w * v.y;
            acc.z += w * v.z; acc.w += w * v.w;
        }
    }

    unsigned short hh[4], ll[4];
    split2(acc.x, hh[0], ll[0]); split2(acc.y, hh[1], ll[1]);
    split2(acc.z, hh[2], ll[2]); split2(acc.w, hh[3], ll[3]);
    uint2 hp2, lp2;
    hp2.x = (uint32_t)hh[0] | ((uint32_t)hh[1] << 16);
    hp2.y = (uint32_t)hh[2] | ((uint32_t)hh[3] << 16);
    lp2.x = (uint32_t)ll[0] | ((uint32_t)ll[1] << 16);
    lp2.y = (uint32_t)ll[2] | ((uint32_t)ll[3] << 16);
    unsigned short* orow = CTXb + (size_t)bt * KST + h * DH + c4 * 4;
    *(uint2*)orow        = hp2;
    *(uint2*)(orow + KK) = lp2;
}

// ---------------- launch ----------------------------------------------------
extern "C" void kernel_launch(void* const* d_in, const int* in_sizes, int n_in,
                              void* d_out, int out_size)
{
    const float* q     = (const float*)d_in[0];
    const float* fmap  = (const float*)d_in[1];
    const float* ref   = (const float*)d_in[2];
    const float* Wv    = (const float*)d_in[3];
    const float* W_off = (const float*)d_in[4];
    const float* b_off = (const float*)d_in[5];
    const float* W_w   = (const float*)d_in[6];
    const float* b_w   = (const float*)d_in[7];
    const float* W_out = (const float*)d_in[8];
    const float* b_out = (const float*)d_in[9];
    float* out = (float*)d_out;

    float *V, *OL, *bc;
    unsigned short *Ab, *qb, *CTXb, *Wvb, *Wcb, *Wob;
    cudaGetSymbolAddress((void**)&V,    g_V);
    cudaGetSymbolAddress((void**)&OL,   g_OL);
    cudaGetSymbolAddress((void**)&bc,   g_bc);
    cudaGetSymbolAddress((void**)&Ab,   g_Ab);
    cudaGetSymbolAddress((void**)&qb,   g_qb);
    cudaGetSymbolAddress((void**)&CTXb, g_CTXb);
    cudaGetSymbolAddress((void**)&Wvb,  g_Wvb);
    cudaGetSymbolAddress((void**)&Wcb,  g_Wcb);
    cudaGetSymbolAddress((void**)&Wob,  g_Wob);

    cudaFuncSetAttribute(mma_gemm, cudaFuncAttributeMaxDynamicSharedMemorySize, GSMEM);

    // 0) fused conversions
    prologue<<<PRO_BLOCKS, 256>>>(fmap, Wv, W_off, W_w, W_out, q, b_off, b_w,
                                  Ab, Wvb, Wcb, Wob, qb, bc);

    // 1) V = fmap^T @ Wv   (per batch, 4096 x 512)
    mma_gemm<<<dim3(Dd / 128, HW / 128, Bb), 256, GSMEM>>>(
        Ab, Wvb, nullptr, V, Dd, (long long)HW * KST, (long long)HW * Dd);
    // 2) OL = q @ [W_off|W_w] + bc   (8192 x 384)
    mma_gemm<<<dim3(NOL / 128, BT / 128, 1), 256, GSMEM>>>(
        qb, Wcb, bc, OL, NOL, 0, 0);
    // 3) softmax + bilinear gather -> CTXb (bf16 split)
    sample2<<<BT, 128>>>(V, OL, ref, CTXb);
    // 4) out = CTX @ W_out + b_out   (8192 x 512)
    mma_gemm<<<dim3(Dd / 128, BT / 128, 1), 256, GSMEM>>>(
        CTXb, Wob, b_out, out, Dd, 0, 0);
}

// round 9
// speedup vs baseline: 3.2674x; 1.1383x over previous
#include <cuda_runtime.h>
#include <cuda_bf16.h>
#include <cuda_fp16.h>
#include <cstdint>

// ---------------- problem constants ----------------
#define Bb   4
#define Tt   2048
#define Dd   512
#define Hh   8
#define Pp   16
#define DH   64
#define Cc   512
#define HF   64
#define WF   64
#define RAD  0.08f
#define BT   (Bb*Tt)        // 8192
#define HW   (HF*WF)        // 4096
#define NOL  384            // 256 (offsets) + 128 (logits)
#define KK   512            // inner dim of every GEMM
#define KST  1024           // stored K for split operands: [hi(512) | lo(512)]

// ---------------- scratch (static device globals) --------------------------
__device__ float g_V[(size_t)Bb * HW * Dd];        // value proj, (B, HW, D) fp32
__device__ float g_OL[(size_t)BT * NOL];           // [off(256) | logits(128)] fp32
__device__ float g_bc[NOL];
__device__ __align__(256) unsigned short g_Ab [(size_t)Bb * HW * KST];  // fmap^T fp16 split
__device__ __align__(256) unsigned short g_qb [(size_t)BT * KST];       // q bf16 split
__device__ __align__(256) unsigned short g_CTXb[(size_t)BT * KST];      // ctx fp16 split
__device__ __align__(256) unsigned short g_Wvb[(size_t)Dd * KK];        // Wv^T fp16 single
__device__ __align__(256) unsigned short g_Wcb[(size_t)NOL * KST];      // [W_off|W_w]^T bf16 split
__device__ __align__(256) unsigned short g_Wob[(size_t)Dd * KK];        // W_out^T fp16 single

// ---------------- PTX helpers (baseline sm_80-class; compile at compute_103) -
__device__ __forceinline__ uint32_t smem_u32(const void* p) {
    uint32_t a;
    asm("{ .reg .u64 t; cvta.to.shared.u64 t, %1; cvt.u32.u64 %0, t; }"
        : "=r"(a) : "l"(p));
    return a;
}
#define SWZ(o) ((o) ^ (((o) >> 3) & 0x70))
#define CP16(dst, src) \
    asm volatile("cp.async.cg.shared.global [%0], [%1], 16;" \
                 :: "r"(dst), "l"(src))
#define CPCOMMIT() asm volatile("cp.async.commit_group;" ::: "memory")
#define CPWAIT0()  asm volatile("cp.async.wait_group 0;" ::: "memory")
#define CPWAIT1()  asm volatile("cp.async.wait_group 1;" ::: "memory")

__device__ __forceinline__ void ldmx4(uint32_t r[4], uint32_t addr) {
    asm volatile("ldmatrix.sync.aligned.m8n8.x4.shared.b16 {%0,%1,%2,%3}, [%4];"
        : "=r"(r[0]), "=r"(r[1]), "=r"(r[2]), "=r"(r[3]) : "r"(addr));
}
template<int FP16>
__device__ __forceinline__ void mma16816t(float d[4], const uint32_t a[4],
                                          const uint32_t b[2]) {
    if (FP16)
        asm volatile(
            "mma.sync.aligned.m16n8k16.row.col.f32.f16.f16.f32 "
            "{%0,%1,%2,%3}, {%4,%5,%6,%7}, {%8,%9}, {%0,%1,%2,%3};"
            : "+f"(d[0]), "+f"(d[1]), "+f"(d[2]), "+f"(d[3])
            : "r"(a[0]), "r"(a[1]), "r"(a[2]), "r"(a[3]), "r"(b[0]), "r"(b[1]));
    else
        asm volatile(
            "mma.sync.aligned.m16n8k16.row.col.f32.bf16.bf16.f32 "
            "{%0,%1,%2,%3}, {%4,%5,%6,%7}, {%8,%9}, {%0,%1,%2,%3};"
            : "+f"(d[0]), "+f"(d[1]), "+f"(d[2]), "+f"(d[3])
            : "r"(a[0]), "r"(a[1]), "r"(a[2]), "r"(a[3]), "r"(b[0]), "r"(b[1]));
}

// ---------------- split helpers ---------------------------------------------
__device__ __forceinline__ void split2(float x, unsigned short& h, unsigned short& l) {
    __nv_bfloat16 hb = __float2bfloat16(x);
    __nv_bfloat16 lb = __float2bfloat16(x - __bfloat162float(hb));
    h = *reinterpret_cast<unsigned short*>(&hb);
    l = *reinterpret_cast<unsigned short*>(&lb);
}
__device__ __forceinline__ void split2h(float x, unsigned short& h, unsigned short& l) {
    __half hb = __float2half(x);
    __half lb = __float2half(x - __half2float(hb));
    h = __half_as_ushort(hb);
    l = __half_as_ushort(lb);
}

// ---------------- fused prologue --------------------------------------------
// Block-range dispatch, 256 threads per block.
//   [0,8192)      fmap [B][C][HW] -> Ab  fp16 split [B][HW][2C]
//   [8192,8448)   Wv    [C][D]    -> Wvb fp16 single [D][C]
//   [8448,8576)   W_off [D][256]  -> Wcb bf16 split [0:256]
//   [8576,8640)   W_w   [D][128]  -> Wcb bf16 split [256:384]
//   [8640,8896)   W_out [D][D]    -> Wob fp16 single [D][D]
//   [8896,12992)  q -> qb bf16 split
//   [12992,12994) bias concat
#define PRO_BLOCKS 12994
__global__ __launch_bounds__(256)
void prologue(const float* __restrict__ fmap, const float* __restrict__ Wv,
              const float* __restrict__ W_off, const float* __restrict__ W_w,
              const float* __restrict__ W_out, const float* __restrict__ q,
              const float* __restrict__ b_off, const float* __restrict__ b_w,
              unsigned short* __restrict__ Ab,  unsigned short* __restrict__ Wvb,
              unsigned short* __restrict__ Wcb, unsigned short* __restrict__ Wob,
              unsigned short* __restrict__ qb,  float* __restrict__ bc)
{
    __shared__ float t[32][33];
    const int bid = blockIdx.x;
    const int tid = threadIdx.x;
    const int tx = tid & 31, ty = tid >> 5;

    auto tload = [&](const float* in, int N, int n0, int k0) {
        #pragma unroll
        for (int i = ty; i < 32; i += 8)
            t[i][tx] = in[(size_t)(k0 + i) * N + n0 + tx];
        __syncthreads();
    };

    if (bid < 8192) {                       // fmap -> fp16 split
        int r = bid;
        int bx = r & 127; r >>= 7;
        int by = r & 15;  int bz = r >> 4;
        const float* in = fmap + (size_t)bz * Cc * HW;
        unsigned short* out = Ab + (size_t)bz * HW * KST;
        int n0 = bx * 32, k0 = by * 32;
        tload(in, HW, n0, k0);
        #pragma unroll
        for (int i = ty; i < 32; i += 8) {
            int n = n0 + i, k = k0 + tx;
            unsigned short h, l;
            split2h(t[tx][i], h, l);
            out[(size_t)n * KST + k]      = h;
            out[(size_t)n * KST + KK + k] = l;
        }
    } else if (bid < 8448) {                // Wv -> fp16 single
        int r = bid - 8192;
        int n0 = (r & 15) * 32, k0 = (r >> 4) * 32;
        tload(Wv, Dd, n0, k0);
        #pragma unroll
        for (int i = ty; i < 32; i += 8)
            Wvb[(size_t)(n0 + i) * KK + k0 + tx] =
                __half_as_ushort(__float2half(t[tx][i]));
    } else if (bid < 8576) {                // W_off -> bf16 split
        int r = bid - 8448;
        int n0 = (r & 7) * 32, k0 = (r >> 3) * 32;
        tload(W_off, 256, n0, k0);
        #pragma unroll
        for (int i = ty; i < 32; i += 8) {
            int n = n0 + i, k = k0 + tx;
            unsigned short h, l;
            split2(t[tx][i], h, l);
            Wcb[(size_t)n * KST + k]      = h;
            Wcb[(size_t)n * KST + KK + k] = l;
        }
    } else if (bid < 8640) {                // W_w -> bf16 split
        int r = bid - 8576;
        int n0 = (r & 3) * 32, k0 = (r >> 2) * 32;
        tload(W_w, 128, n0, k0);
        unsigned short* out = Wcb + (size_t)256 * KST;
        #pragma unroll
        for (int i = ty; i < 32; i += 8) {
            int n = n0 + i, k = k0 + tx;
            unsigned short h, l;
            split2(t[tx][i], h, l);
            out[(size_t)n * KST + k]      = h;
            out[(size_t)n * KST + KK + k] = l;
        }
    } else if (bid < 8896) {                // W_out -> fp16 single
        int r = bid - 8640;
        int n0 = (r & 15) * 32, k0 = (r >> 4) * 32;
        tload(W_out, Dd, n0, k0);
        #pragma unroll
        for (int i = ty; i < 32; i += 8)
            Wob[(size_t)(n0 + i) * KK + k0 + tx] =
                __half_as_ushort(__float2half(t[tx][i]));
    } else if (bid < 12992) {               // q -> bf16 split
        size_t i = (size_t)(bid - 8896) * 256 + tid;   // over BT*128
        size_t m = i >> 7;
        int k4 = (int)(i & 127) * 4;
        float4 v = *(const float4*)(q + m * KK + k4);
        unsigned short h[4], l[4];
        split2(v.x, h[0], l[0]); split2(v.y, h[1], l[1]);
        split2(v.z, h[2], l[2]); split2(v.w, h[3], l[3]);
        uint2 hp, lp;
        hp.x = (uint32_t)h[0] | ((uint32_t)h[1] << 16);
        hp.y = (uint32_t)h[2] | ((uint32_t)h[3] << 16);
        lp.x = (uint32_t)l[0] | ((uint32_t)l[1] << 16);
        lp.y = (uint32_t)l[2] | ((uint32_t)l[3] << 16);
        *(uint2*)(qb + m * KST + k4)      = hp;
        *(uint2*)(qb + m * KST + KK + k4) = lp;
    } else {
        int i = (bid - 12992) * 256 + tid;
        if (i < NOL) bc[i] = (i < 256) ? b_off[i] : b_w[i - 256];
    }
}

// ---------------- mma.sync split-GEMM (3-stage pipeline) --------------------
// SCHEME 0: bf16 3-pass (AhBh, AhBl, AlBh); A,B stride KST.  NC=24.
// SCHEME 1: fp16 2-pass (Ah*B, Al*B); A stride KST (hi|lo), B stride KK. NC=16.
// CTA tile 128x128, 8 warps (4x2), warp tile 32x64, K-chunks of 64 (SW128),
// 3-stage cp.async pipeline, one __syncthreads per chunk, 2 CTAs/SM.
#define STAGE 32768          // A 16K + B 16K per stage
#define GSMEM (3 * STAGE)    // 96 KB
template<int SCHEME>
__global__ __launch_bounds__(256, 2)
void mma_gemm(const unsigned short* __restrict__ Abf,
              const unsigned short* __restrict__ Bbf,
              const float* __restrict__ bias, float* __restrict__ C,
              int Ntot, long long aStride, long long cStride)
{
    constexpr int NC  = SCHEME ? 16 : 24;
    constexpr int BRS = SCHEME ? KK : KST;
    extern __shared__ __align__(1024) unsigned char smem[];
    uint32_t sb = smem_u32(smem);
    const int tid = threadIdx.x;
    const int lane = tid & 31, wid = tid >> 5;
    const int warpM = wid & 3, warpN = wid >> 2;
    Abf += (size_t)blockIdx.z * aStride;
    C   += (size_t)blockIdx.z * cStride;
    const int m0 = blockIdx.y * 128, n0 = blockIdx.x * 128;

    const unsigned short* Ag = Abf + (size_t)m0 * KST;
    const unsigned short* Bg = Bbf + (size_t)n0 * BRS;

    float acc[2][8][4];
    #pragma unroll
    for (int i = 0; i < 2; i++)
        #pragma unroll
        for (int j = 0; j < 8; j++)
            #pragma unroll
            for (int r = 0; r < 4; r++) acc[i][j][r] = 0.f;

    auto load_chunk = [&](int c, int buf) {
        int p = c >> 3, cc = c & 7;
        int aoff, boff;
        if (SCHEME) { aoff = (p ? KK : 0) + cc * 64;        boff = cc * 64; }
        else        { aoff = ((p == 2) ? KK : 0) + cc * 64; boff = ((p == 1) ? KK : 0) + cc * 64; }
        uint32_t d = sb + buf * STAGE;
        #pragma unroll
        for (int i = 0; i < 8; i++) {
            int id  = tid + i * 256;       // 0..2047
            int row = id >> 3;
            int kc  = (id & 7) * 8;        // element offset in chunk
            if (row < 128) {
                CP16(d + SWZ(row * 128 + kc * 2),
                     (const char*)(Ag + (size_t)row * KST + aoff + kc));
            } else {
                int br = row - 128;
                CP16(d + 16384 + SWZ(br * 128 + kc * 2),
                     (const char*)(Bg + (size_t)br * BRS + boff + kc));
            }
        }
    };

    auto compute = [&](int buf) {
        uint32_t ab = sb + buf * STAGE;
        uint32_t bb = ab + 16384;
        #pragma unroll
        for (int ks = 0; ks < 4; ks++) {
            uint32_t afrag[2][4];
            int arow = warpM * 32 + (lane & 15);
            int akb  = ks * 32 + ((lane >> 4) & 1) * 16;   // bytes
            #pragma unroll
            for (int i = 0; i < 2; i++)
                ldmx4(afrag[i], ab + SWZ((arow + i * 16) * 128 + akb));
            uint32_t bfrag[8][2];
            int bkb = ks * 32 + ((lane >> 3) & 1) * 16;
            #pragma unroll
            for (int jp = 0; jp < 4; jp++) {
                int nrow = warpN * 64 + jp * 16 + ((lane >> 4) & 1) * 8 + (lane & 7);
                uint32_t r[4];
                ldmx4(r, bb + SWZ(nrow * 128 + bkb));
                bfrag[2 * jp][0]     = r[0];
                bfrag[2 * jp][1]     = r[1];
                bfrag[2 * jp + 1][0] = r[2];
                bfrag[2 * jp + 1][1] = r[3];
            }
            #pragma unroll
            for (int i = 0; i < 2; i++)
                #pragma unroll
                for (int j = 0; j < 8; j++)
                    mma16816t<SCHEME>(acc[i][j], afrag[i], bfrag[j]);
        }
    };

    load_chunk(0, 0);
    CPCOMMIT();
    load_chunk(1, 1);
    CPCOMMIT();
    int buf = 0;
    #pragma unroll 1
    for (int c = 0; c < NC; c++) {
        if (c + 2 < NC) CPWAIT1(); else CPWAIT0();
        __syncthreads();
        if (c + 2 < NC) {
            int nb = buf + 2; if (nb >= 3) nb -= 3;
            load_chunk(c + 2, nb);
            CPCOMMIT();
        }
        compute(buf);
        if (++buf == 3) buf = 0;
    }

    // epilogue
    int gr = lane >> 2, tg = (lane & 3) * 2;
    #pragma unroll
    for (int i = 0; i < 2; i++) {
        int row = m0 + warpM * 32 + i * 16 + gr;
        #pragma unroll
        for (int j = 0; j < 8; j++) {
            int col = n0 + warpN * 64 + j * 8 + tg;
            float b0 = 0.f, b1 = 0.f;
            if (bias) { b0 = bias[col]; b1 = bias[col + 1]; }
            *(float2*)&C[(size_t)row * Ntot + col] =
                make_float2(acc[i][j][0] + b0, acc[i][j][1] + b1);
            *(float2*)&C[(size_t)(row + 8) * Ntot + col] =
                make_float2(acc[i][j][2] + b0, acc[i][j][3] + b1);
        }
    }
}

// ---------------- softmax + bilinear gather ---------------------------------
// Writes CTX directly as fp16 split [BT][1024] for the output GEMM.
__global__ __launch_bounds__(128)
void sample2(const float* __restrict__ V,
             const float* __restrict__ OL,
             const float* __restrict__ ref,
             unsigned short* __restrict__ CTXb)
{
    int bt = blockIdx.x;
    int b  = bt >> 11;
    int tid = threadIdx.x;

    __shared__ float s_w[Hh * Pp][4];
    __shared__ int   s_i[Hh * Pp][4];

    {
        const float* olrow = OL + (long long)bt * NOL;
        float ox = olrow[2 * tid];
        float oy = olrow[2 * tid + 1];
        float lg = olrow[256 + tid];
        float rx = ref[bt * 2 + 0];
        float ry = ref[bt * 2 + 1];

        float ix = (rx + RAD * ox) * (float)(WF - 1);
        float iy = (ry + RAD * oy) * (float)(HF - 1);
        float x0f = floorf(ix), y0f = floorf(iy);
        int x0 = (int)x0f, y0 = (int)y0f;
        float fx = ix - x0f, fy = iy - y0f;

        float mx = lg;
        #pragma unroll
        for (int m = 8; m >= 1; m >>= 1)
            mx = fmaxf(mx, __shfl_xor_sync(0xffffffffu, mx, m, 16));
        float e = __expf(lg - mx);
        float s = e;
        #pragma unroll
        for (int m = 8; m >= 1; m >>= 1)
            s += __shfl_xor_sync(0xffffffffu, s, m, 16);
        float aw = e / s;

        bool vx0 = (x0 >= 0) && (x0 < WF);
        bool vx1 = (x0 + 1 >= 0) && (x0 + 1 < WF);
        bool vy0 = (y0 >= 0) && (y0 < HF);
        bool vy1 = (y0 + 1 >= 0) && (y0 + 1 < HF);
        int x0c = min(max(x0, 0), WF - 1);
        int x1c = min(max(x0 + 1, 0), WF - 1);
        int y0c = min(max(y0, 0), HF - 1);
        int y1c = min(max(y0 + 1, 0), HF - 1);

        s_w[tid][0] = (vx0 && vy0) ? (1.f - fx) * (1.f - fy) * aw : 0.f;
        s_w[tid][1] = (vx1 && vy0) ? fx * (1.f - fy) * aw : 0.f;
        s_w[tid][2] = (vx0 && vy1) ? (1.f - fx) * fy * aw : 0.f;
        s_w[tid][3] = (vx1 && vy1) ? fx * fy * aw : 0.f;
        s_i[tid][0] = y0c * WF + x0c;
        s_i[tid][1] = y0c * WF + x1c;
        s_i[tid][2] = y1c * WF + x0c;
        s_i[tid][3] = y1c * WF + x1c;
    }
    __syncthreads();

    int h  = tid >> 4;
    int c4 = tid & 15;
    const float4* Vb = (const float4*)(V + (size_t)b * HW * Dd) + (h * 16 + c4);

    float4 acc = make_float4(0.f, 0.f, 0.f, 0.f);
    #pragma unroll
    for (int p = 0; p < Pp; p++) {
        int hp = h * Pp + p;
        int4   ii = *(const int4*)s_i[hp];
        float4 ww = *(const float4*)s_w[hp];
        #pragma unroll
        for (int c = 0; c < 4; c++) {
            int   idx = (c == 0) ? ii.x : (c == 1) ? ii.y : (c == 2) ? ii.z : ii.w;
            float w   = (c == 0) ? ww.x : (c == 1) ? ww.y : (c == 2) ? ww.z : ww.w;
            float4 v = Vb[(long long)idx * (Dd / 4)];
            acc.x += w * v.x; acc.y += w * v.y;
            acc.z += w * v.z; acc.w += w * v.w;
        }
    }

    unsigned short hh[4], ll[4];
    split2h(acc.x, hh[0], ll[0]); split2h(acc.y, hh[1], ll[1]);
    split2h(acc.z, hh[2], ll[2]); split2h(acc.w, hh[3], ll[3]);
    uint2 hp2, lp2;
    hp2.x = (uint32_t)hh[0] | ((uint32_t)hh[1] << 16);
    hp2.y = (uint32_t)hh[2] | ((uint32_t)hh[3] << 16);
    lp2.x = (uint32_t)ll[0] | ((uint32_t)ll[1] << 16);
    lp2.y = (uint32_t)ll[2] | ((uint32_t)ll[3] << 16);
    unsigned short* orow = CTXb + (size_t)bt * KST + h * DH + c4 * 4;
    *(uint2*)orow        = hp2;
    *(uint2*)(orow + KK) = lp2;
}

// ---------------- launch ----------------------------------------------------
extern "C" void kernel_launch(void* const* d_in, const int* in_sizes, int n_in,
                              void* d_out, int out_size)
{
    const float* q     = (const float*)d_in[0];
    const float* fmap  = (const float*)d_in[1];
    const float* ref   = (const float*)d_in[2];
    const float* Wv    = (const float*)d_in[3];
    const float* W_off = (const float*)d_in[4];
    const float* b_off = (const float*)d_in[5];
    const float* W_w   = (const float*)d_in[6];
    const float* b_w   = (const float*)d_in[7];
    const float* W_out = (const float*)d_in[8];
    const float* b_out = (const float*)d_in[9];
    float* out = (float*)d_out;

    float *V, *OL, *bc;
    unsigned short *Ab, *qb, *CTXb, *Wvb, *Wcb, *Wob;
    cudaGetSymbolAddress((void**)&V,    g_V);
    cudaGetSymbolAddress((void**)&OL,   g_OL);
    cudaGetSymbolAddress((void**)&bc,   g_bc);
    cudaGetSymbolAddress((void**)&Ab,   g_Ab);
    cudaGetSymbolAddress((void**)&qb,   g_qb);
    cudaGetSymbolAddress((void**)&CTXb, g_CTXb);
    cudaGetSymbolAddress((void**)&Wvb,  g_Wvb);
    cudaGetSymbolAddress((void**)&Wcb,  g_Wcb);
    cudaGetSymbolAddress((void**)&Wob,  g_Wob);

    cudaFuncSetAttribute(mma_gemm<0>, cudaFuncAttributeMaxDynamicSharedMemorySize, GSMEM);
    cudaFuncSetAttribute(mma_gemm<1>, cudaFuncAttributeMaxDynamicSharedMemorySize, GSMEM);

    // 0) fused conversions
    prologue<<<PRO_BLOCKS, 256>>>(fmap, Wv, W_off, W_w, W_out, q, b_off, b_w,
                                  Ab, Wvb, Wcb, Wob, qb, bc);

    // 1) V = fmap^T @ Wv   (per batch, 4096 x 512), fp16 2-pass
    mma_gemm<1><<<dim3(Dd / 128, HW / 128, Bb), 256, GSMEM>>>(
        Ab, Wvb, nullptr, V, Dd, (long long)HW * KST, (long long)HW * Dd);
    // 2) OL = q @ [W_off|W_w] + bc   (8192 x 384), bf16 3-pass
    mma_gemm<0><<<dim3(NOL / 128, BT / 128, 1), 256, GSMEM>>>(
        qb, Wcb, bc, OL, NOL, 0, 0);
    // 3) softmax + bilinear gather -> CTXb (fp16 split)
    sample2<<<BT, 128>>>(V, OL, ref, CTXb);
    // 4) out = CTX @ W_out + b_out   (8192 x 512), fp16 2-pass
    mma_gemm<1><<<dim3(Dd / 128, BT / 128, 1), 256, GSMEM>>>(
        CTXb, Wob, b_out, out, Dd, 0, 0);
}

// round 10
// speedup vs baseline: 4.2033x; 1.2864x over previous
#include <cuda_runtime.h>
#include <cuda_bf16.h>
#include <cuda_fp16.h>
#include <cstdint>

// ---------------- problem constants ----------------
#define Bb   4
#define Tt   2048
#define Dd   512
#define Hh   8
#define Pp   16
#define DH   64
#define Cc   512
#define HF   64
#define WF   64
#define RAD  0.08f
#define BT   (Bb*Tt)        // 8192
#define HW   (HF*WF)        // 4096
#define NOL  384            // 256 (offsets) + 128 (logits)
#define KK   512            // inner dim of every GEMM
#define KST  1024           // stored K for split operands: [hi(512) | lo(512)]

// ---------------- scratch (static device globals) --------------------------
__device__ __align__(256) unsigned short g_V[(size_t)Bb * HW * Dd];  // V fp16
__device__ float g_OL[(size_t)BT * NOL];           // [off(256) | logits(128)] fp32
__device__ float g_bc[NOL];
__device__ __align__(256) unsigned short g_Ab [(size_t)Bb * HW * KK];   // fmap^T fp16 single
__device__ __align__(256) unsigned short g_qb [(size_t)BT * KST];       // q bf16 split
__device__ __align__(256) unsigned short g_CTXb[(size_t)BT * KST];      // ctx fp16 split
__device__ __align__(256) unsigned short g_Wvb[(size_t)Dd * KK];        // Wv^T fp16 single
__device__ __align__(256) unsigned short g_Wcb[(size_t)NOL * KST];      // [W_off|W_w]^T bf16 split
__device__ __align__(256) unsigned short g_Wob[(size_t)Dd * KK];        // W_out^T fp16 single

// ---------------- PTX helpers (baseline sm_80-class; compile at compute_103) -
__device__ __forceinline__ uint32_t smem_u32(const void* p) {
    uint32_t a;
    asm("{ .reg .u64 t; cvta.to.shared.u64 t, %1; cvt.u32.u64 %0, t; }"
        : "=r"(a) : "l"(p));
    return a;
}
#define SWZ(o) ((o) ^ (((o) >> 3) & 0x70))
#define CP16(dst, src) \
    asm volatile("cp.async.cg.shared.global [%0], [%1], 16;" \
                 :: "r"(dst), "l"(src))
#define CPCOMMIT() asm volatile("cp.async.commit_group;" ::: "memory")
#define CPWAIT0()  asm volatile("cp.async.wait_group 0;" ::: "memory")
#define CPWAIT1()  asm volatile("cp.async.wait_group 1;" ::: "memory")

__device__ __forceinline__ void ldmx4(uint32_t r[4], uint32_t addr) {
    asm volatile("ldmatrix.sync.aligned.m8n8.x4.shared.b16 {%0,%1,%2,%3}, [%4];"
        : "=r"(r[0]), "=r"(r[1]), "=r"(r[2]), "=r"(r[3]) : "r"(addr));
}
template<int FP16>
__device__ __forceinline__ void mma16816t(float d[4], const uint32_t a[4],
                                          const uint32_t b[2]) {
    if (FP16)
        asm volatile(
            "mma.sync.aligned.m16n8k16.row.col.f32.f16.f16.f32 "
            "{%0,%1,%2,%3}, {%4,%5,%6,%7}, {%8,%9}, {%0,%1,%2,%3};"
            : "+f"(d[0]), "+f"(d[1]), "+f"(d[2]), "+f"(d[3])
            : "r"(a[0]), "r"(a[1]), "r"(a[2]), "r"(a[3]), "r"(b[0]), "r"(b[1]));
    else
        asm volatile(
            "mma.sync.aligned.m16n8k16.row.col.f32.bf16.bf16.f32 "
            "{%0,%1,%2,%3}, {%4,%5,%6,%7}, {%8,%9}, {%0,%1,%2,%3};"
            : "+f"(d[0]), "+f"(d[1]), "+f"(d[2]), "+f"(d[3])
            : "r"(a[0]), "r"(a[1]), "r"(a[2]), "r"(a[3]), "r"(b[0]), "r"(b[1]));
}

// ---------------- split helpers ---------------------------------------------
__device__ __forceinline__ void split2(float x, unsigned short& h, unsigned short& l) {
    __nv_bfloat16 hb = __float2bfloat16(x);
    __nv_bfloat16 lb = __float2bfloat16(x - __bfloat162float(hb));
    h = *reinterpret_cast<unsigned short*>(&hb);
    l = *reinterpret_cast<unsigned short*>(&lb);
}
__device__ __forceinline__ void split2h(float x, unsigned short& h, unsigned short& l) {
    __half hb = __float2half(x);
    __half lb = __float2half(x - __half2float(hb));
    h = __half_as_ushort(hb);
    l = __half_as_ushort(lb);
}

// ---------------- fused prologue --------------------------------------------
// Block-range dispatch, 256 threads per block.
//   [0,8192)      fmap [B][C][HW] -> Ab  fp16 single [B][HW][C]
//   [8192,8448)   Wv    [C][D]    -> Wvb fp16 single [D][C]
//   [8448,8576)   W_off [D][256]  -> Wcb bf16 split [0:256]
//   [8576,8640)   W_w   [D][128]  -> Wcb bf16 split [256:384]
//   [8640,8896)   W_out [D][D]    -> Wob fp16 single [D][D]
//   [8896,12992)  q -> qb bf16 split
//   [12992,12994) bias concat
#define PRO_BLOCKS 12994
__global__ __launch_bounds__(256)
void prologue(const float* __restrict__ fmap, const float* __restrict__ Wv,
              const float* __restrict__ W_off, const float* __restrict__ W_w,
              const float* __restrict__ W_out, const float* __restrict__ q,
              const float* __restrict__ b_off, const float* __restrict__ b_w,
              unsigned short* __restrict__ Ab,  unsigned short* __restrict__ Wvb,
              unsigned short* __restrict__ Wcb, unsigned short* __restrict__ Wob,
              unsigned short* __restrict__ qb,  float* __restrict__ bc)
{
    __shared__ float t[32][33];
    const int bid = blockIdx.x;
    const int tid = threadIdx.x;
    const int tx = tid & 31, ty = tid >> 5;

    auto tload = [&](const float* in, int N, int n0, int k0) {
        #pragma unroll
        for (int i = ty; i < 32; i += 8)
            t[i][tx] = in[(size_t)(k0 + i) * N + n0 + tx];
        __syncthreads();
    };

    if (bid < 8192) {                       // fmap -> fp16 single
        int r = bid;
        int bx = r & 127; r >>= 7;
        int by = r & 15;  int bz = r >> 4;
        const float* in = fmap + (size_t)bz * Cc * HW;
        unsigned short* out = Ab + (size_t)bz * HW * KK;
        int n0 = bx * 32, k0 = by * 32;
        tload(in, HW, n0, k0);
        #pragma unroll
        for (int i = ty; i < 32; i += 8)
            out[(size_t)(n0 + i) * KK + k0 + tx] =
                __half_as_ushort(__float2half(t[tx][i]));
    } else if (bid < 8448) {                // Wv -> fp16 single
        int r = bid - 8192;
        int n0 = (r & 15) * 32, k0 = (r >> 4) * 32;
        tload(Wv, Dd, n0, k0);
        #pragma unroll
        for (int i = ty; i < 32; i += 8)
            Wvb[(size_t)(n0 + i) * KK + k0 + tx] =
                __half_as_ushort(__float2half(t[tx][i]));
    } else if (bid < 8576) {                // W_off -> bf16 split
        int r = bid - 8448;
        int n0 = (r & 7) * 32, k0 = (r >> 3) * 32;
        tload(W_off, 256, n0, k0);
        #pragma unroll
        for (int i = ty; i < 32; i += 8) {
            int n = n0 + i, k = k0 + tx;
            unsigned short h, l;
            split2(t[tx][i], h, l);
            Wcb[(size_t)n * KST + k]      = h;
            Wcb[(size_t)n * KST + KK + k] = l;
        }
    } else if (bid < 8640) {                // W_w -> bf16 split
        int r = bid - 8576;
        int n0 = (r & 3) * 32, k0 = (r >> 2) * 32;
        tload(W_w, 128, n0, k0);
        unsigned short* out = Wcb + (size_t)256 * KST;
        #pragma unroll
        for (int i = ty; i < 32; i += 8) {
            int n = n0 + i, k = k0 + tx;
            unsigned short h, l;
            split2(t[tx][i], h, l);
            out[(size_t)n * KST + k]      = h;
            out[(size_t)n * KST + KK + k] = l;
        }
    } else if (bid < 8896) {                // W_out -> fp16 single
        int r = bid - 8640;
        int n0 = (r & 15) * 32, k0 = (r >> 4) * 32;
        tload(W_out, Dd, n0, k0);
        #pragma unroll
        for (int i = ty; i < 32; i += 8)
            Wob[(size_t)(n0 + i) * KK + k0 + tx] =
                __half_as_ushort(__float2half(t[tx][i]));
    } else if (bid < 12992) {               // q -> bf16 split
        size_t i = (size_t)(bid - 8896) * 256 + tid;   // over BT*128
        size_t m = i >> 7;
        int k4 = (int)(i & 127) * 4;
        float4 v = *(const float4*)(q + m * KK + k4);
        unsigned short h[4], l[4];
        split2(v.x, h[0], l[0]); split2(v.y, h[1], l[1]);
        split2(v.z, h[2], l[2]); split2(v.w, h[3], l[3]);
        uint2 hp, lp;
        hp.x = (uint32_t)h[0] | ((uint32_t)h[1] << 16);
        hp.y = (uint32_t)h[2] | ((uint32_t)h[3] << 16);
        lp.x = (uint32_t)l[0] | ((uint32_t)l[1] << 16);
        lp.y = (uint32_t)l[2] | ((uint32_t)l[3] << 16);
        *(uint2*)(qb + m * KST + k4)      = hp;
        *(uint2*)(qb + m * KST + KK + k4) = lp;
    } else {
        int i = (bid - 12992) * 256 + tid;
        if (i < NOL) bc[i] = (i < 256) ? b_off[i] : b_w[i - 256];
    }
}

// ---------------- mma.sync GEMM (3-stage pipeline) ---------------------------
// SCHEME 0: bf16 3-pass (AhBh, AhBl, AlBh); A,B stride KST; NC=24; f32 out.
// SCHEME 1: fp16 2-pass (Ah*B, Al*B); A stride KST, B stride KK; NC=16; f32 out.
// SCHEME 2: fp16 1-pass (A*B); A,B stride KK; NC=8; f16 out.
// CTA tile 128x128, 8 warps (4x2), warp tile 32x64, K-chunks of 64 (SW128),
// 3-stage cp.async pipeline, one __syncthreads per chunk, 2 CTAs/SM.
#define STAGE 32768          // A 16K + B 16K per stage
#define GSMEM (3 * STAGE)    // 96 KB
template<int SCHEME>
__global__ __launch_bounds__(256, 2)
void mma_gemm(const unsigned short* __restrict__ Abf,
              const unsigned short* __restrict__ Bbf,
              const float* __restrict__ bias, void* __restrict__ Cv,
              int Ntot, long long aStride, long long cStride)
{
    constexpr int NC  = (SCHEME == 0) ? 24 : (SCHEME == 1) ? 16 : 8;
    constexpr int ARS = (SCHEME == 2) ? KK : KST;
    constexpr int BRS = (SCHEME == 0) ? KST : KK;
    constexpr bool F16OUT = (SCHEME == 2);
    extern __shared__ __align__(1024) unsigned char smem[];
    uint32_t sb = smem_u32(smem);
    const int tid = threadIdx.x;
    const int lane = tid & 31, wid = tid >> 5;
    const int warpM = wid & 3, warpN = wid >> 2;
    Abf += (size_t)blockIdx.z * aStride;
    const int m0 = blockIdx.y * 128, n0 = blockIdx.x * 128;

    const unsigned short* Ag = Abf + (size_t)m0 * ARS;
    const unsigned short* Bg = Bbf + (size_t)n0 * BRS;

    float acc[2][8][4];
    #pragma unroll
    for (int i = 0; i < 2; i++)
        #pragma unroll
        for (int j = 0; j < 8; j++)
            #pragma unroll
            for (int r = 0; r < 4; r++) acc[i][j][r] = 0.f;

    auto load_chunk = [&](int c, int buf) {
        int p = c >> 3, cc = c & 7;
        int aoff, boff;
        if (SCHEME == 0)      { aoff = ((p == 2) ? KK : 0) + cc * 64; boff = ((p == 1) ? KK : 0) + cc * 64; }
        else if (SCHEME == 1) { aoff = (p ? KK : 0) + cc * 64;        boff = cc * 64; }
        else                  { aoff = cc * 64;                        boff = cc * 64; }
        uint32_t d = sb + buf * STAGE;
        #pragma unroll
        for (int i = 0; i < 8; i++) {
            int id  = tid + i * 256;       // 0..2047
            int row = id >> 3;
            int kc  = (id & 7) * 8;        // element offset in chunk
            if (row < 128) {
                CP16(d + SWZ(row * 128 + kc * 2),
                     (const char*)(Ag + (size_t)row * ARS + aoff + kc));
            } else {
                int br = row - 128;
                CP16(d + 16384 + SWZ(br * 128 + kc * 2),
                     (const char*)(Bg + (size_t)br * BRS + boff + kc));
            }
        }
    };

    auto compute = [&](int buf) {
        uint32_t ab = sb + buf * STAGE;
        uint32_t bb = ab + 16384;
        #pragma unroll
        for (int ks = 0; ks < 4; ks++) {
            uint32_t afrag[2][4];
            int arow = warpM * 32 + (lane & 15);
            int akb  = ks * 32 + ((lane >> 4) & 1) * 16;   // bytes
            #pragma unroll
            for (int i = 0; i < 2; i++)
                ldmx4(afrag[i], ab + SWZ((arow + i * 16) * 128 + akb));
            uint32_t bfrag[8][2];
            int bkb = ks * 32 + ((lane >> 3) & 1) * 16;
            #pragma unroll
            for (int jp = 0; jp < 4; jp++) {
                int nrow = warpN * 64 + jp * 16 + ((lane >> 4) & 1) * 8 + (lane & 7);
                uint32_t r[4];
                ldmx4(r, bb + SWZ(nrow * 128 + bkb));
                bfrag[2 * jp][0]     = r[0];
                bfrag[2 * jp][1]     = r[1];
                bfrag[2 * jp + 1][0] = r[2];
                bfrag[2 * jp + 1][1] = r[3];
            }
            #pragma unroll
            for (int i = 0; i < 2; i++)
                #pragma unroll
                for (int j = 0; j < 8; j++)
                    mma16816t<(SCHEME >= 1)>(acc[i][j], afrag[i], bfrag[j]);
        }
    };

    load_chunk(0, 0);
    CPCOMMIT();
    load_chunk(1, 1);
    CPCOMMIT();
    int buf = 0;
    #pragma unroll 1
    for (int c = 0; c < NC; c++) {
        if (c + 2 < NC) CPWAIT1(); else CPWAIT0();
        __syncthreads();
        if (c + 2 < NC) {
            int nb = buf + 2; if (nb >= 3) nb -= 3;
            load_chunk(c + 2, nb);
            CPCOMMIT();
        }
        compute(buf);
        if (++buf == 3) buf = 0;
    }

    // epilogue
    int gr = lane >> 2, tg = (lane & 3) * 2;
    if (F16OUT) {
        __half* Ch = (__half*)Cv + (size_t)blockIdx.z * cStride;
        #pragma unroll
        for (int i = 0; i < 2; i++) {
            int row = m0 + warpM * 32 + i * 16 + gr;
            #pragma unroll
            for (int j = 0; j < 8; j++) {
                int col = n0 + warpN * 64 + j * 8 + tg;
                *(__half2*)&Ch[(size_t)row * Ntot + col] =
                    __floats2half2_rn(acc[i][j][0], acc[i][j][1]);
                *(__half2*)&Ch[(size_t)(row + 8) * Ntot + col] =
                    __floats2half2_rn(acc[i][j][2], acc[i][j][3]);
            }
        }
    } else {
        float* C = (float*)Cv + (size_t)blockIdx.z * cStride;
        #pragma unroll
        for (int i = 0; i < 2; i++) {
            int row = m0 + warpM * 32 + i * 16 + gr;
            #pragma unroll
            for (int j = 0; j < 8; j++) {
                int col = n0 + warpN * 64 + j * 8 + tg;
                float b0 = 0.f, b1 = 0.f;
                if (bias) { b0 = bias[col]; b1 = bias[col + 1]; }
                *(float2*)&C[(size_t)row * Ntot + col] =
                    make_float2(acc[i][j][0] + b0, acc[i][j][1] + b1);
                *(float2*)&C[(size_t)(row + 8) * Ntot + col] =
                    make_float2(acc[i][j][2] + b0, acc[i][j][3] + b1);
            }
        }
    }
}

// ---------------- softmax + bilinear gather ---------------------------------
// V in fp16 (halved gather traffic).  Writes CTX as fp16 split [BT][1024].
__global__ __launch_bounds__(128)
void sample2(const unsigned short* __restrict__ V,
             const float* __restrict__ OL,
             const float* __restrict__ ref,
             unsigned short* __restrict__ CTXb)
{
    int bt = blockIdx.x;
    int b  = bt >> 11;
    int tid = threadIdx.x;

    __shared__ float s_w[Hh * Pp][4];
    __shared__ int   s_i[Hh * Pp][4];

    {
        const float* olrow = OL + (long long)bt * NOL;
        float ox = olrow[2 * tid];
        float oy = olrow[2 * tid + 1];
        float lg = olrow[256 + tid];
        float rx = ref[bt * 2 + 0];
        float ry = ref[bt * 2 + 1];

        float ix = (rx + RAD * ox) * (float)(WF - 1);
        float iy = (ry + RAD * oy) * (float)(HF - 1);
        float x0f = floorf(ix), y0f = floorf(iy);
        int x0 = (int)x0f, y0 = (int)y0f;
        float fx = ix - x0f, fy = iy - y0f;

        float mx = lg;
        #pragma unroll
        for (int m = 8; m >= 1; m >>= 1)
            mx = fmaxf(mx, __shfl_xor_sync(0xffffffffu, mx, m, 16));
        float e = __expf(lg - mx);
        float s = e;
        #pragma unroll
        for (int m = 8; m >= 1; m >>= 1)
            s += __shfl_xor_sync(0xffffffffu, s, m, 16);
        float aw = e / s;

        bool vx0 = (x0 >= 0) && (x0 < WF);
        bool vx1 = (x0 + 1 >= 0) && (x0 + 1 < WF);
        bool vy0 = (y0 >= 0) && (y0 < HF);
        bool vy1 = (y0 + 1 >= 0) && (y0 + 1 < HF);
        int x0c = min(max(x0, 0), WF - 1);
        int x1c = min(max(x0 + 1, 0), WF - 1);
        int y0c = min(max(y0, 0), HF - 1);
        int y1c = min(max(y0 + 1, 0), HF - 1);

        s_w[tid][0] = (vx0 && vy0) ? (1.f - fx) * (1.f - fy) * aw : 0.f;
        s_w[tid][1] = (vx1 && vy0) ? fx * (1.f - fy) * aw : 0.f;
        s_w[tid][2] = (vx0 && vy1) ? (1.f - fx) * fy * aw : 0.f;
        s_w[tid][3] = (vx1 && vy1) ? fx * fy * aw : 0.f;
        s_i[tid][0] = y0c * WF + x0c;
        s_i[tid][1] = y0c * WF + x1c;
        s_i[tid][2] = y1c * WF + x0c;
        s_i[tid][3] = y1c * WF + x1c;
    }
    __syncthreads();

    int h  = tid >> 4;
    int c4 = tid & 15;
    const unsigned short* Vb = V + (size_t)b * HW * Dd + h * DH + c4 * 4;

    float4 acc = make_float4(0.f, 0.f, 0.f, 0.f);
    #pragma unroll
    for (int p = 0; p < Pp; p++) {
        int hp = h * Pp + p;
        int4   ii = *(const int4*)s_i[hp];
        float4 ww = *(const float4*)s_w[hp];
        #pragma unroll
        for (int c = 0; c < 4; c++) {
            int   idx = (c == 0) ? ii.x : (c == 1) ? ii.y : (c == 2) ? ii.z : ii.w;
            float w   = (c == 0) ? ww.x : (c == 1) ? ww.y : (c == 2) ? ww.z : ww.w;
            uint2 u = *(const uint2*)(Vb + (size_t)idx * Dd);
            float2 f0 = __half22float2(*reinterpret_cast<const __half2*>(&u.x));
            float2 f1 = __half22float2(*reinterpret_cast<const __half2*>(&u.y));
            acc.x += w * f0.x; acc.y += w * f0.y;
            acc.z += w * f1.x; acc.w += w * f1.y;
        }
    }

    unsigned short hh[4], ll[4];
    split2h(acc.x, hh[0], ll[0]); split2h(acc.y, hh[1], ll[1]);
    split2h(acc.z, hh[2], ll[2]); split2h(acc.w, hh[3], ll[3]);
    uint2 hp2, lp2;
    hp2.x = (uint32_t)hh[0] | ((uint32_t)hh[1] << 16);
    hp2.y = (uint32_t)hh[2] | ((uint32_t)hh[3] << 16);
    lp2.x = (uint32_t)ll[0] | ((uint32_t)ll[1] << 16);
    lp2.y = (uint32_t)ll[2] | ((uint32_t)ll[3] << 16);
    unsigned short* orow = CTXb + (size_t)bt * KST + h * DH + c4 * 4;
    *(uint2*)orow        = hp2;
    *(uint2*)(orow + KK) = lp2;
}

// ---------------- launch ----------------------------------------------------
extern "C" void kernel_launch(void* const* d_in, const int* in_sizes, int n_in,
                              void* d_out, int out_size)
{
    const float* q     = (const float*)d_in[0];
    const float* fmap  = (const float*)d_in[1];
    const float* ref   = (const float*)d_in[2];
    const float* Wv    = (const float*)d_in[3];
    const float* W_off = (const float*)d_in[4];
    const float* b_off = (const float*)d_in[5];
    const float* W_w   = (const float*)d_in[6];
    const float* b_w   = (const float*)d_in[7];
    const float* W_out = (const float*)d_in[8];
    const float* b_out = (const float*)d_in[9];
    float* out = (float*)d_out;

    float *OL, *bc;
    unsigned short *V, *Ab, *qb, *CTXb, *Wvb, *Wcb, *Wob;
    cudaGetSymbolAddress((void**)&V,    g_V);
    cudaGetSymbolAddress((void**)&OL,   g_OL);
    cudaGetSymbolAddress((void**)&bc,   g_bc);
    cudaGetSymbolAddress((void**)&Ab,   g_Ab);
    cudaGetSymbolAddress((void**)&qb,   g_qb);
    cudaGetSymbolAddress((void**)&CTXb, g_CTXb);
    cudaGetSymbolAddress((void**)&Wvb,  g_Wvb);
    cudaGetSymbolAddress((void**)&Wcb,  g_Wcb);
    cudaGetSymbolAddress((void**)&Wob,  g_Wob);

    cudaFuncSetAttribute(mma_gemm<0>, cudaFuncAttributeMaxDynamicSharedMemorySize, GSMEM);
    cudaFuncSetAttribute(mma_gemm<1>, cudaFuncAttributeMaxDynamicSharedMemorySize, GSMEM);
    cudaFuncSetAttribute(mma_gemm<2>, cudaFuncAttributeMaxDynamicSharedMemorySize, GSMEM);

    // 0) fused conversions
    prologue<<<PRO_BLOCKS, 256>>>(fmap, Wv, W_off, W_w, W_out, q, b_off, b_w,
                                  Ab, Wvb, Wcb, Wob, qb, bc);

    // 1) V = fmap^T @ Wv   (per batch, 4096 x 512), fp16 1-pass, fp16 out
    mma_gemm<2><<<dim3(Dd / 128, HW / 128, Bb), 256, GSMEM>>>(
        Ab, Wvb, nullptr, V, Dd, (long long)HW * KK, (long long)HW * Dd);
    // 2) OL = q @ [W_off|W_w] + bc   (8192 x 384), bf16 3-pass
    mma_gemm<0><<<dim3(NOL / 128, BT / 128, 1), 256, GSMEM>>>(
        qb, Wcb, bc, OL, NOL, 0, 0);
    // 3) softmax + bilinear gather (fp16 V) -> CTXb (fp16 split)
    sample2<<<BT, 128>>>(V, OL, ref, CTXb);
    // 4) out = CTX @ W_out + b_out   (8192 x 512), fp16 2-pass
    mma_gemm<1><<<dim3(Dd / 128, BT / 128, 1), 256, GSMEM>>>(
        CTXb, Wob, b_out, out, Dd, 0, 0);
}

// round 13
// speedup vs baseline: 4.6386x; 1.1036x over previous
#include <cuda_runtime.h>
#include <cuda_bf16.h>
#include <cuda_fp16.h>
#include <cstdint>

// ---------------- problem constants ----------------
#define Bb   4
#define Tt   2048
#define Dd   512
#define Hh   8
#define Pp   16
#define DH   64
#define Cc   512
#define HF   64
#define WF   64
#define RAD  0.08f
#define BT   (Bb*Tt)        // 8192
#define HW   (HF*WF)        // 4096
#define NOL  384            // 256 (offsets) + 128 (logits)
#define KK   512            // inner dim of every GEMM
#define KST  1024           // stored K for split operands: [hi(512) | lo(512)]

// ---------------- scratch (static device globals) --------------------------
__device__ __align__(256) unsigned short g_V[(size_t)Bb * HW * Dd];  // V fp16
__device__ float g_OL[(size_t)BT * NOL];           // [off(256) | logits(128)] fp32
__device__ float g_bc[NOL];
__device__ __align__(256) unsigned short g_Ab [(size_t)Bb * HW * KK];   // fmap^T fp16 single
__device__ __align__(256) unsigned short g_qb [(size_t)BT * KST];       // q bf16 split
__device__ __align__(256) unsigned short g_CTXb[(size_t)BT * KK];       // ctx fp16 single
__device__ __align__(256) unsigned short g_Wvb[(size_t)Dd * KK];        // Wv^T fp16 single
__device__ __align__(256) unsigned short g_Wcb[(size_t)NOL * KST];      // [W_off|W_w]^T bf16 split
__device__ __align__(256) unsigned short g_Wob[(size_t)Dd * KK];        // W_out^T fp16 single

// ---------------- PTX helpers (baseline sm_80-class; compile at compute_103) -
__device__ __forceinline__ uint32_t smem_u32(const void* p) {
    uint32_t a;
    asm("{ .reg .u64 t; cvta.to.shared.u64 t, %1; cvt.u32.u64 %0, t; }"
        : "=r"(a) : "l"(p));
    return a;
}
#define SWZ(o) ((o) ^ (((o) >> 3) & 0x70))
#define CP16(dst, src) \
    asm volatile("cp.async.cg.shared.global [%0], [%1], 16;" \
                 :: "r"(dst), "l"(src))
#define CPCOMMIT() asm volatile("cp.async.commit_group;" ::: "memory")
#define CPWAIT0()  asm volatile("cp.async.wait_group 0;" ::: "memory")
#define CPWAIT1()  asm volatile("cp.async.wait_group 1;" ::: "memory")

__device__ __forceinline__ void ldmx4(uint32_t r[4], uint32_t addr) {
    asm volatile("ldmatrix.sync.aligned.m8n8.x4.shared.b16 {%0,%1,%2,%3}, [%4];"
        : "=r"(r[0]), "=r"(r[1]), "=r"(r[2]), "=r"(r[3]) : "r"(addr));
}
template<int FP16>
__device__ __forceinline__ void mma16816t(float d[4], const uint32_t a[4],
                                          const uint32_t b[2]) {
    if (FP16)
        asm volatile(
            "mma.sync.aligned.m16n8k16.row.col.f32.f16.f16.f32 "
            "{%0,%1,%2,%3}, {%4,%5,%6,%7}, {%8,%9}, {%0,%1,%2,%3};"
            : "+f"(d[0]), "+f"(d[1]), "+f"(d[2]), "+f"(d[3])
            : "r"(a[0]), "r"(a[1]), "r"(a[2]), "r"(a[3]), "r"(b[0]), "r"(b[1]));
    else
        asm volatile(
            "mma.sync.aligned.m16n8k16.row.col.f32.bf16.bf16.f32 "
            "{%0,%1,%2,%3}, {%4,%5,%6,%7}, {%8,%9}, {%0,%1,%2,%3};"
            : "+f"(d[0]), "+f"(d[1]), "+f"(d[2]), "+f"(d[3])
            : "r"(a[0]), "r"(a[1]), "r"(a[2]), "r"(a[3]), "r"(b[0]), "r"(b[1]));
}

// ---------------- split helpers ---------------------------------------------
__device__ __forceinline__ void split2(float x, unsigned short& h, unsigned short& l) {
    __nv_bfloat16 hb = __float2bfloat16(x);
    __nv_bfloat16 lb = __float2bfloat16(x - __bfloat162float(hb));
    h = *reinterpret_cast<unsigned short*>(&hb);
    l = *reinterpret_cast<unsigned short*>(&lb);
}

// ---------------- fused prologue --------------------------------------------
// Block-range dispatch, 256 threads per block.
//   [0,8192)      fmap [B][C][HW] -> Ab  fp16 single [B][HW][C]
//   [8192,8448)   Wv    [C][D]    -> Wvb fp16 single [D][C]
//   [8448,8576)   W_off [D][256]  -> Wcb bf16 split [0:256]
//   [8576,8640)   W_w   [D][128]  -> Wcb bf16 split [256:384]
//   [8640,8896)   W_out [D][D]    -> Wob fp16 single [D][D]
//   [8896,12992)  q -> qb bf16 split
//   [12992,12994) bias concat
#define PRO_BLOCKS 12994
__global__ __launch_bounds__(256)
void prologue(const float* __restrict__ fmap, const float* __restrict__ Wv,
              const float* __restrict__ W_off, const float* __restrict__ W_w,
              const float* __restrict__ W_out, const float* __restrict__ q,
              const float* __restrict__ b_off, const float* __restrict__ b_w,
              unsigned short* __restrict__ Ab,  unsigned short* __restrict__ Wvb,
              unsigned short* __restrict__ Wcb, unsigned short* __restrict__ Wob,
              unsigned short* __restrict__ qb,  float* __restrict__ bc)
{
    __shared__ float t[32][33];
    const int bid = blockIdx.x;
    const int tid = threadIdx.x;
    const int tx = tid & 31, ty = tid >> 5;

    auto tload = [&](const float* in, int N, int n0, int k0) {
        #pragma unroll
        for (int i = ty; i < 32; i += 8)
            t[i][tx] = in[(size_t)(k0 + i) * N + n0 + tx];
        __syncthreads();
    };

    if (bid < 8192) {                       // fmap -> fp16 single
        int r = bid;
        int bx = r & 127; r >>= 7;
        int by = r & 15;  int bz = r >> 4;
        const float* in = fmap + (size_t)bz * Cc * HW;
        unsigned short* out = Ab + (size_t)bz * HW * KK;
        int n0 = bx * 32, k0 = by * 32;
        tload(in, HW, n0, k0);
        #pragma unroll
        for (int i = ty; i < 32; i += 8)
            out[(size_t)(n0 + i) * KK + k0 + tx] =
                __half_as_ushort(__float2half(t[tx][i]));
    } else if (bid < 8448) {                // Wv -> fp16 single
        int r = bid - 8192;
        int n0 = (r & 15) * 32, k0 = (r >> 4) * 32;
        tload(Wv, Dd, n0, k0);
        #pragma unroll
        for (int i = ty; i < 32; i += 8)
            Wvb[(size_t)(n0 + i) * KK + k0 + tx] =
                __half_as_ushort(__float2half(t[tx][i]));
    } else if (bid < 8576) {                // W_off -> bf16 split
        int r = bid - 8448;
        int n0 = (r & 7) * 32, k0 = (r >> 3) * 32;
        tload(W_off, 256, n0, k0);
        #pragma unroll
        for (int i = ty; i < 32; i += 8) {
            int n = n0 + i, k = k0 + tx;
            unsigned short h, l;
            split2(t[tx][i], h, l);
            Wcb[(size_t)n * KST + k]      = h;
            Wcb[(size_t)n * KST + KK + k] = l;
        }
    } else if (bid < 8640) {                // W_w -> bf16 split
        int r = bid - 8576;
        int n0 = (r & 3) * 32, k0 = (r >> 2) * 32;
        tload(W_w, 128, n0, k0);
        unsigned short* out = Wcb + (size_t)256 * KST;
        #pragma unroll
        for (int i = ty; i < 32; i += 8) {
            int n = n0 + i, k = k0 + tx;
            unsigned short h, l;
            split2(t[tx][i], h, l);
            out[(size_t)n * KST + k]      = h;
            out[(size_t)n * KST + KK + k] = l;
        }
    } else if (bid < 8896) {                // W_out -> fp16 single
        int r = bid - 8640;
        int n0 = (r & 15) * 32, k0 = (r >> 4) * 32;
        tload(W_out, Dd, n0, k0);
        #pragma unroll
        for (int i = ty; i < 32; i += 8)
            Wob[(size_t)(n0 + i) * KK + k0 + tx] =
                __half_as_ushort(__float2half(t[tx][i]));
    } else if (bid < 12992) {               // q -> bf16 split
        size_t i = (size_t)(bid - 8896) * 256 + tid;   // over BT*128
        size_t m = i >> 7;
        int k4 = (int)(i & 127) * 4;
        float4 v = *(const float4*)(q + m * KK + k4);
        unsigned short h[4], l[4];
        split2(v.x, h[0], l[0]); split2(v.y, h[1], l[1]);
        split2(v.z, h[2], l[2]); split2(v.w, h[3], l[3]);
        uint2 hp, lp;
        hp.x = (uint32_t)h[0] | ((uint32_t)h[1] << 16);
        hp.y = (uint32_t)h[2] | ((uint32_t)h[3] << 16);
        lp.x = (uint32_t)l[0] | ((uint32_t)l[1] << 16);
        lp.y = (uint32_t)l[2] | ((uint32_t)l[3] << 16);
        *(uint2*)(qb + m * KST + k4)      = hp;
        *(uint2*)(qb + m * KST + KK + k4) = lp;
    } else {
        int i = (bid - 12992) * 256 + tid;
        if (i < NOL) bc[i] = (i < 256) ? b_off[i] : b_w[i - 256];
    }
}

// ---------------- mma.sync GEMM (3-stage pipeline) ---------------------------
// SCHEME 0: bf16 3-pass (AhBh, AhBl, AlBh); A,B stride KST; NC=24; f32 out.
// SCHEME 1: fp16 2-pass (Ah*B, Al*B); A stride KST, B stride KK; NC=16; f32 out.
// SCHEME 2: fp16 1-pass; A,B stride KK; NC=8; f16 out (no bias).
// SCHEME 3: fp16 1-pass; A,B stride KK; NC=8; f32 out (+bias).
// CTA tile 128x128, 8 warps (4x2), warp tile 32x64, K-chunks of 64 (SW128),
// 3-stage cp.async pipeline, one __syncthreads per chunk, 2 CTAs/SM.
#define STAGE 32768          // A 16K + B 16K per stage
#define GSMEM (3 * STAGE)    // 96 KB
template<int SCHEME>
__global__ __launch_bounds__(256, 2)
void mma_gemm(const unsigned short* __restrict__ Abf,
              const unsigned short* __restrict__ Bbf,
              const float* __restrict__ bias, void* __restrict__ Cv,
              int Ntot, long long aStride, long long cStride)
{
    constexpr int NC  = (SCHEME == 0) ? 24 : (SCHEME == 1) ? 16 : 8;
    constexpr int ARS = (SCHEME >= 2) ? KK : KST;
    constexpr int BRS = (SCHEME == 0) ? KST : KK;
    constexpr bool F16OUT = (SCHEME == 2);
    extern __shared__ __align__(1024) unsigned char smem[];
    uint32_t sb = smem_u32(smem);
    const int tid = threadIdx.x;
    const int lane = tid & 31, wid = tid >> 5;
    const int warpM = wid & 3, warpN = wid >> 2;
    Abf += (size_t)blockIdx.z * aStride;
    const int m0 = blockIdx.y * 128, n0 = blockIdx.x * 128;

    const unsigned short* Ag = Abf + (size_t)m0 * ARS;
    const unsigned short* Bg = Bbf + (size_t)n0 * BRS;

    float acc[2][8][4];
    #pragma unroll
    for (int i = 0; i < 2; i++)
        #pragma unroll
        for (int j = 0; j < 8; j++)
            #pragma unroll
            for (int r = 0; r < 4; r++) acc[i][j][r] = 0.f;

    auto load_chunk = [&](int c, int buf) {
        int p = c >> 3, cc = c & 7;
        int aoff, boff;
        if (SCHEME == 0)      { aoff = ((p == 2) ? KK : 0) + cc * 64; boff = ((p == 1) ? KK : 0) + cc * 64; }
        else if (SCHEME == 1) { aoff = (p ? KK : 0) + cc * 64;        boff = cc * 64; }
        else                  { aoff = cc * 64;                        boff = cc * 64; }
        uint32_t d = sb + buf * STAGE;
        #pragma unroll
        for (int i = 0; i < 8; i++) {
            int id  = tid + i * 256;       // 0..2047
            int row = id >> 3;
            int kc  = (id & 7) * 8;        // element offset in chunk
            if (row < 128) {
                CP16(d + SWZ(row * 128 + kc * 2),
                     (const char*)(Ag + (size_t)row * ARS + aoff + kc));
            } else {
                int br = row - 128;
                CP16(d + 16384 + SWZ(br * 128 + kc * 2),
                     (const char*)(Bg + (size_t)br * BRS + boff + kc));
            }
        }
    };

    auto compute = [&](int buf) {
        uint32_t ab = sb + buf * STAGE;
        uint32_t bb = ab + 16384;
        #pragma unroll
        for (int ks = 0; ks < 4; ks++) {
            uint32_t afrag[2][4];
            int arow = warpM * 32 + (lane & 15);
            int akb  = ks * 32 + ((lane >> 4) & 1) * 16;   // bytes
            #pragma unroll
            for (int i = 0; i < 2; i++)
                ldmx4(afrag[i], ab + SWZ((arow + i * 16) * 128 + akb));
            uint32_t bfrag[8][2];
            int bkb = ks * 32 + ((lane >> 3) & 1) * 16;
            #pragma unroll
            for (int jp = 0; jp < 4; jp++) {
                int nrow = warpN * 64 + jp * 16 + ((lane >> 4) & 1) * 8 + (lane & 7);
                uint32_t r[4];
                ldmx4(r, bb + SWZ(nrow * 128 + bkb));
                bfrag[2 * jp][0]     = r[0];
                bfrag[2 * jp][1]     = r[1];
                bfrag[2 * jp + 1][0] = r[2];
                bfrag[2 * jp + 1][1] = r[3];
            }
            #pragma unroll
            for (int i = 0; i < 2; i++)
                #pragma unroll
                for (int j = 0; j < 8; j++)
                    mma16816t<(SCHEME >= 1)>(acc[i][j], afrag[i], bfrag[j]);
        }
    };

    load_chunk(0, 0);
    CPCOMMIT();
    load_chunk(1, 1);
    CPCOMMIT();
    int buf = 0;
    #pragma unroll 1
    for (int c = 0; c < NC; c++) {
        if (c + 2 < NC) CPWAIT1(); else CPWAIT0();
        __syncthreads();
        if (c + 2 < NC) {
            int nb = buf + 2; if (nb >= 3) nb -= 3;
            load_chunk(c + 2, nb);
            CPCOMMIT();
        }
        compute(buf);
        if (++buf == 3) buf = 0;
    }

    // epilogue
    int gr = lane >> 2, tg = (lane & 3) * 2;
    if (F16OUT) {
        __half* Ch = (__half*)Cv + (size_t)blockIdx.z * cStride;
        #pragma unroll
        for (int i = 0; i < 2; i++) {
            int row = m0 + warpM * 32 + i * 16 + gr;
            #pragma unroll
            for (int j = 0; j < 8; j++) {
                int col = n0 + warpN * 64 + j * 8 + tg;
                *(__half2*)&Ch[(size_t)row * Ntot + col] =
                    __floats2half2_rn(acc[i][j][0], acc[i][j][1]);
                *(__half2*)&Ch[(size_t)(row + 8) * Ntot + col] =
                    __floats2half2_rn(acc[i][j][2], acc[i][j][3]);
            }
        }
    } else {
        float* C = (float*)Cv + (size_t)blockIdx.z * cStride;
        #pragma unroll
        for (int i = 0; i < 2; i++) {
            int row = m0 + warpM * 32 + i * 16 + gr;
            #pragma unroll
            for (int j = 0; j < 8; j++) {
                int col = n0 + warpN * 64 + j * 8 + tg;
                float b0 = 0.f, b1 = 0.f;
                if (bias) { b0 = bias[col]; b1 = bias[col + 1]; }
                *(float2*)&C[(size_t)row * Ntot + col] =
                    make_float2(acc[i][j][0] + b0, acc[i][j][1] + b1);
                *(float2*)&C[(size_t)(row + 8) * Ntot + col] =
                    make_float2(acc[i][j][2] + b0, acc[i][j][3] + b1);
            }
        }
    }
}

// ---------------- softmax + bilinear gather ---------------------------------
// 64 threads per token; thread = (head h = tid>>3, 8-channel group tid&7).
// Gathers are uint4 (LDG.128); ctx written as SINGLE fp16 [BT][512].
__global__ __launch_bounds__(64)
void sample2(const unsigned short* __restrict__ V,
             const float* __restrict__ OL,
             const float* __restrict__ ref,
             unsigned short* __restrict__ CTXb)
{
    int bt = blockIdx.x;
    int b  = bt >> 11;
    int tid = threadIdx.x;

    __shared__ float s_w[Hh * Pp][4];
    __shared__ int   s_i[Hh * Pp][4];

    const float* olrow = OL + (long long)bt * NOL;
    float rx = ref[bt * 2 + 0];
    float ry = ref[bt * 2 + 1];

    #pragma unroll
    for (int rep = 0; rep < 2; rep++) {
        int hp = tid + rep * 64;
        float ox = olrow[2 * hp];
        float oy = olrow[2 * hp + 1];
        float lg = olrow[256 + hp];

        float ix = (rx + RAD * ox) * (float)(WF - 1);
        float iy = (ry + RAD * oy) * (float)(HF - 1);
        float x0f = floorf(ix), y0f = floorf(iy);
        int x0 = (int)x0f, y0 = (int)y0f;
        float fx = ix - x0f, fy = iy - y0f;

        // softmax over P=16 within each 16-lane group (hp groups == lane groups)
        float mx = lg;
        #pragma unroll
        for (int m = 8; m >= 1; m >>= 1)
            mx = fmaxf(mx, __shfl_xor_sync(0xffffffffu, mx, m, 16));
        float e = __expf(lg - mx);
        float s = e;
        #pragma unroll
        for (int m = 8; m >= 1; m >>= 1)
            s += __shfl_xor_sync(0xffffffffu, s, m, 16);
        float aw = e / s;

        bool vx0 = (x0 >= 0) && (x0 < WF);
        bool vx1 = (x0 + 1 >= 0) && (x0 + 1 < WF);
        bool vy0 = (y0 >= 0) && (y0 < HF);
        bool vy1 = (y0 + 1 >= 0) && (y0 + 1 < HF);
        int x0c = min(max(x0, 0), WF - 1);
        int x1c = min(max(x0 + 1, 0), WF - 1);
        int y0c = min(max(y0, 0), HF - 1);
        int y1c = min(max(y0 + 1, 0), HF - 1);

        s_w[hp][0] = (vx0 && vy0) ? (1.f - fx) * (1.f - fy) * aw : 0.f;
        s_w[hp][1] = (vx1 && vy0) ? fx * (1.f - fy) * aw : 0.f;
        s_w[hp][2] = (vx0 && vy1) ? (1.f - fx) * fy * aw : 0.f;
        s_w[hp][3] = (vx1 && vy1) ? fx * fy * aw : 0.f;
        s_i[hp][0] = y0c * WF + x0c;
        s_i[hp][1] = y0c * WF + x1c;
        s_i[hp][2] = y1c * WF + x0c;
        s_i[hp][3] = y1c * WF + x1c;
    }
    __syncthreads();

    int h  = tid >> 3;
    int l8 = tid & 7;
    const unsigned short* Vb = V + (size_t)b * HW * Dd + h * DH + l8 * 8;

    float acc[8];
    #pragma unroll
    for (int j = 0; j < 8; j++) acc[j] = 0.f;

    #pragma unroll
    for (int p = 0; p < Pp; p++) {
        int hp = h * Pp + p;
        int4   ii = *(const int4*)s_i[hp];
        float4 ww = *(const float4*)s_w[hp];
        #pragma unroll
        for (int c = 0; c < 4; c++) {
            int   idx = (c == 0) ? ii.x : (c == 1) ? ii.y : (c == 2) ? ii.z : ii.w;
            float w   = (c == 0) ? ww.x : (c == 1) ? ww.y : (c == 2) ? ww.z : ww.w;
            uint4 u = *(const uint4*)(Vb + (size_t)idx * Dd);
            float2 f0 = __half22float2(*reinterpret_cast<const __half2*>(&u.x));
            float2 f1 = __half22float2(*reinterpret_cast<const __half2*>(&u.y));
            float2 f2 = __half22float2(*reinterpret_cast<const __half2*>(&u.z));
            float2 f3 = __half22float2(*reinterpret_cast<const __half2*>(&u.w));
            acc[0] += w * f0.x; acc[1] += w * f0.y;
            acc[2] += w * f1.x; acc[3] += w * f1.y;
            acc[4] += w * f2.x; acc[5] += w * f2.y;
            acc[6] += w * f3.x; acc[7] += w * f3.y;
        }
    }

    uint4 o;
    __half2 h01 = __floats2half2_rn(acc[0], acc[1]);
    __half2 h23 = __floats2half2_rn(acc[2], acc[3]);
    __half2 h45 = __floats2half2_rn(acc[4], acc[5]);
    __half2 h67 = __floats2half2_rn(acc[6], acc[7]);
    o.x = *reinterpret_cast<uint32_t*>(&h01);
    o.y = *reinterpret_cast<uint32_t*>(&h23);
    o.z = *reinterpret_cast<uint32_t*>(&h45);
    o.w = *reinterpret_cast<uint32_t*>(&h67);
    *(uint4*)(CTXb + (size_t)bt * KK + h * DH + l8 * 8) = o;
}

// ---------------- launch ----------------------------------------------------
extern "C" void kernel_launch(void* const* d_in, const int* in_sizes, int n_in,
                              void* d_out, int out_size)
{
    const float* q     = (const float*)d_in[0];
    const float* fmap  = (const float*)d_in[1];
    const float* ref   = (const float*)d_in[2];
    const float* Wv    = (const float*)d_in[3];
    const float* W_off = (const float*)d_in[4];
    const float* b_off = (const float*)d_in[5];
    const float* W_w   = (const float*)d_in[6];
    const float* b_w   = (const float*)d_in[7];
    const float* W_out = (const float*)d_in[8];
    const float* b_out = (const float*)d_in[9];
    float* out = (float*)d_out;

    float *OL, *bc;
    unsigned short *V, *Ab, *qb, *CTXb, *Wvb, *Wcb, *Wob;
    cudaGetSymbolAddress((void**)&V,    g_V);
    cudaGetSymbolAddress((void**)&OL,   g_OL);
    cudaGetSymbolAddress((void**)&bc,   g_bc);
    cudaGetSymbolAddress((void**)&Ab,   g_Ab);
    cudaGetSymbolAddress((void**)&qb,   g_qb);
    cudaGetSymbolAddress((void**)&CTXb, g_CTXb);
    cudaGetSymbolAddress((void**)&Wvb,  g_Wvb);
    cudaGetSymbolAddress((void**)&Wcb,  g_Wcb);
    cudaGetSymbolAddress((void**)&Wob,  g_Wob);

    cudaFuncSetAttribute(mma_gemm<0>, cudaFuncAttributeMaxDynamicSharedMemorySize, GSMEM);
    cudaFuncSetAttribute(mma_gemm<2>, cudaFuncAttributeMaxDynamicSharedMemorySize, GSMEM);
    cudaFuncSetAttribute(mma_gemm<3>, cudaFuncAttributeMaxDynamicSharedMemorySize, GSMEM);

    // 0) fused conversions
    prologue<<<PRO_BLOCKS, 256>>>(fmap, Wv, W_off, W_w, W_out, q, b_off, b_w,
                                  Ab, Wvb, Wcb, Wob, qb, bc);

    // 1) V = fmap^T @ Wv   (per batch, 4096 x 512), fp16 1-pass, fp16 out
    mma_gemm<2><<<dim3(Dd / 128, HW / 128, Bb), 256, GSMEM>>>(
        Ab, Wvb, nullptr, V, Dd, (long long)HW * KK, (long long)HW * Dd);
    // 2) OL = q @ [W_off|W_w] + bc   (8192 x 384), bf16 3-pass
    mma_gemm<0><<<dim3(NOL / 128, BT / 128, 1), 256, GSMEM>>>(
        qb, Wcb, bc, OL, NOL, 0, 0);
    // 3) softmax + bilinear gather (fp16 V) -> CTXb (fp16 single)
    sample2<<<BT, 64>>>(V, OL, ref, CTXb);
    // 4) out = CTX @ W_out + b_out   (8192 x 512), fp16 1-pass, f32 out
    mma_gemm<3><<<dim3(Dd / 128, BT / 128, 1), 256, GSMEM>>>(
        CTXb, Wob, b_out, out, Dd, 0, 0);
}

// round 15
// speedup vs baseline: 4.7726x; 1.0289x over previous
#include <cuda_runtime.h>
#include <cuda_bf16.h>
#include <cuda_fp16.h>
#include <cstdint>

// ---------------- problem constants ----------------
#define Bb   4
#define Tt   2048
#define Dd   512
#define Hh   8
#define Pp   16
#define DH   64
#define Cc   512
#define HF   64
#define WF   64
#define RAD  0.08f
#define BT   (Bb*Tt)        // 8192
#define HW   (HF*WF)        // 4096
#define NOL  384            // 256 (offsets) + 128 (logits)
#define KK   512            // inner dim of every GEMM
#define KST  1024           // stored K for split operands: [hi(512) | lo(512)]

// ---------------- scratch (static device globals) --------------------------
__device__ __align__(256) unsigned short g_V[(size_t)Bb * HW * Dd];  // V fp16
__device__ float g_OL[(size_t)BT * NOL];           // [off(256) | logits(128)] fp32
__device__ float g_bc[NOL];
__device__ __align__(256) unsigned short g_Ab [(size_t)Bb * HW * KK];   // fmap^T fp16 single
__device__ __align__(256) unsigned short g_qb [(size_t)BT * KST];       // q bf16 split
__device__ __align__(256) unsigned short g_qh [(size_t)BT * KK];        // q fp16 single
__device__ __align__(256) unsigned short g_CTXb[(size_t)BT * KK];       // ctx fp16 single
__device__ __align__(256) unsigned short g_Wvb[(size_t)Dd * KK];        // Wv^T fp16 single
__device__ __align__(256) unsigned short g_Wcb[(size_t)256 * KST];      // W_off^T bf16 split
__device__ __align__(256) unsigned short g_Wwh[(size_t)128 * KK];       // W_w^T fp16 single
__device__ __align__(256) unsigned short g_Wob[(size_t)Dd * KK];        // W_out^T fp16 single

// ---------------- PTX helpers (baseline sm_80-class; compile at compute_103) -
__device__ __forceinline__ uint32_t smem_u32(const void* p) {
    uint32_t a;
    asm("{ .reg .u64 t; cvta.to.shared.u64 t, %1; cvt.u32.u64 %0, t; }"
        : "=r"(a) : "l"(p));
    return a;
}
#define SWZ(o) ((o) ^ (((o) >> 3) & 0x70))
#define CP16(dst, src) \
    asm volatile("cp.async.cg.shared.global [%0], [%1], 16;" \
                 :: "r"(dst), "l"(src))
#define CPCOMMIT() asm volatile("cp.async.commit_group;" ::: "memory")
#define CPWAIT0()  asm volatile("cp.async.wait_group 0;" ::: "memory")
#define CPWAIT1()  asm volatile("cp.async.wait_group 1;" ::: "memory")

// packed f32x2 helpers (bit-identical fp32 pairs)
#define FMA2(d, a, b, c) \
    asm("fma.rn.f32x2 %0, %1, %2, %3;" : "=l"(d) : "l"(a), "l"(b), "l"(c))
#define PACK2(d, lo, hi) \
    asm("mov.b64 %0, {%1, %2};" : "=l"(d) : "r"(lo), "r"(hi))
#define UNPACK2(lo, hi, in) \
    asm("mov.b64 {%0, %1}, %2;" : "=r"(lo), "=r"(hi) : "l"(in))

__device__ __forceinline__ void ldmx4(uint32_t r[4], uint32_t addr) {
    asm volatile("ldmatrix.sync.aligned.m8n8.x4.shared.b16 {%0,%1,%2,%3}, [%4];"
        : "=r"(r[0]), "=r"(r[1]), "=r"(r[2]), "=r"(r[3]) : "r"(addr));
}
template<int FP16>
__device__ __forceinline__ void mma16816t(float d[4], const uint32_t a[4],
                                          const uint32_t b[2]) {
    if (FP16)
        asm volatile(
            "mma.sync.aligned.m16n8k16.row.col.f32.f16.f16.f32 "
            "{%0,%1,%2,%3}, {%4,%5,%6,%7}, {%8,%9}, {%0,%1,%2,%3};"
            : "+f"(d[0]), "+f"(d[1]), "+f"(d[2]), "+f"(d[3])
            : "r"(a[0]), "r"(a[1]), "r"(a[2]), "r"(a[3]), "r"(b[0]), "r"(b[1]));
    else
        asm volatile(
            "mma.sync.aligned.m16n8k16.row.col.f32.bf16.bf16.f32 "
            "{%0,%1,%2,%3}, {%4,%5,%6,%7}, {%8,%9}, {%0,%1,%2,%3};"
            : "+f"(d[0]), "+f"(d[1]), "+f"(d[2]), "+f"(d[3])
            : "r"(a[0]), "r"(a[1]), "r"(a[2]), "r"(a[3]), "r"(b[0]), "r"(b[1]));
}

// ---------------- split helpers ---------------------------------------------
__device__ __forceinline__ void split2(float x, unsigned short& h, unsigned short& l) {
    __nv_bfloat16 hb = __float2bfloat16(x);
    __nv_bfloat16 lb = __float2bfloat16(x - __bfloat162float(hb));
    h = *reinterpret_cast<unsigned short*>(&hb);
    l = *reinterpret_cast<unsigned short*>(&lb);
}

// ---------------- fused prologue --------------------------------------------
// Block-range dispatch, 256 threads per block.
//   [0,8192)      fmap [B][C][HW] -> Ab  fp16 single [B][HW][C]
//   [8192,8448)   Wv    [C][D]    -> Wvb fp16 single [D][C]
//   [8448,8576)   W_off [D][256]  -> Wcb bf16 split
//   [8576,8640)   W_w   [D][128]  -> Wwh fp16 single [128][D]
//   [8640,8896)   W_out [D][D]    -> Wob fp16 single [D][D]
//   [8896,12992)  q -> qb bf16 split + qh fp16 single
//   [12992,12994) bias concat
#define PRO_BLOCKS 12994
__global__ __launch_bounds__(256)
void prologue(const float* __restrict__ fmap, const float* __restrict__ Wv,
              const float* __restrict__ W_off, const float* __restrict__ W_w,
              const float* __restrict__ W_out, const float* __restrict__ q,
              const float* __restrict__ b_off, const float* __restrict__ b_w,
              unsigned short* __restrict__ Ab,  unsigned short* __restrict__ Wvb,
              unsigned short* __restrict__ Wcb, unsigned short* __restrict__ Wwh,
              unsigned short* __restrict__ Wob, unsigned short* __restrict__ qb,
              unsigned short* __restrict__ qh,  float* __restrict__ bc)
{
    __shared__ float t[32][33];
    const int bid = blockIdx.x;
    const int tid = threadIdx.x;
    const int tx = tid & 31, ty = tid >> 5;

    auto tload = [&](const float* in, int N, int n0, int k0) {
        #pragma unroll
        for (int i = ty; i < 32; i += 8)
            t[i][tx] = in[(size_t)(k0 + i) * N + n0 + tx];
        __syncthreads();
    };

    if (bid < 8192) {                       // fmap -> fp16 single
        int r = bid;
        int bx = r & 127; r >>= 7;
        int by = r & 15;  int bz = r >> 4;
        const float* in = fmap + (size_t)bz * Cc * HW;
        unsigned short* out = Ab + (size_t)bz * HW * KK;
        int n0 = bx * 32, k0 = by * 32;
        tload(in, HW, n0, k0);
        #pragma unroll
        for (int i = ty; i < 32; i += 8)
            out[(size_t)(n0 + i) * KK + k0 + tx] =
                __half_as_ushort(__float2half(t[tx][i]));
    } else if (bid < 8448) {                // Wv -> fp16 single
        int r = bid - 8192;
        int n0 = (r & 15) * 32, k0 = (r >> 4) * 32;
        tload(Wv, Dd, n0, k0);
        #pragma unroll
        for (int i = ty; i < 32; i += 8)
            Wvb[(size_t)(n0 + i) * KK + k0 + tx] =
                __half_as_ushort(__float2half(t[tx][i]));
    } else if (bid < 8576) {                // W_off -> bf16 split
        int r = bid - 8448;
        int n0 = (r & 7) * 32, k0 = (r >> 3) * 32;
        tload(W_off, 256, n0, k0);
        #pragma unroll
        for (int i = ty; i < 32; i += 8) {
            int n = n0 + i, k = k0 + tx;
            unsigned short h, l;
            split2(t[tx][i], h, l);
            Wcb[(size_t)n * KST + k]      = h;
            Wcb[(size_t)n * KST + KK + k] = l;
        }
    } else if (bid < 8640) {                // W_w -> fp16 single
        int r = bid - 8576;
        int n0 = (r & 3) * 32, k0 = (r >> 2) * 32;
        tload(W_w, 128, n0, k0);
        #pragma unroll
        for (int i = ty; i < 32; i += 8)
            Wwh[(size_t)(n0 + i) * KK + k0 + tx] =
                __half_as_ushort(__float2half(t[tx][i]));
    } else if (bid < 8896) {                // W_out -> fp16 single
        int r = bid - 8640;
        int n0 = (r & 15) * 32, k0 = (r >> 4) * 32;
        tload(W_out, Dd, n0, k0);
        #pragma unroll
        for (int i = ty; i < 32; i += 8)
            Wob[(size_t)(n0 + i) * KK + k0 + tx] =
                __half_as_ushort(__float2half(t[tx][i]));
    } else if (bid < 12992) {               // q -> bf16 split + fp16 single
        size_t i = (size_t)(bid - 8896) * 256 + tid;   // over BT*128
        size_t m = i >> 7;
        int k4 = (int)(i & 127) * 4;
        float4 v = *(const float4*)(q + m * KK + k4);
        unsigned short h[4], l[4];
        split2(v.x, h[0], l[0]); split2(v.y, h[1], l[1]);
        split2(v.z, h[2], l[2]); split2(v.w, h[3], l[3]);
        uint2 hp, lp;
        hp.x = (uint32_t)h[0] | ((uint32_t)h[1] << 16);
        hp.y = (uint32_t)h[2] | ((uint32_t)h[3] << 16);
        lp.x = (uint32_t)l[0] | ((uint32_t)l[1] << 16);
        lp.y = (uint32_t)l[2] | ((uint32_t)l[3] << 16);
        *(uint2*)(qb + m * KST + k4)      = hp;
        *(uint2*)(qb + m * KST + KK + k4) = lp;
        __half2 q01 = __floats2half2_rn(v.x, v.y);
        __half2 q23 = __floats2half2_rn(v.z, v.w);
        uint2 qp;
        qp.x = *reinterpret_cast<uint32_t*>(&q01);
        qp.y = *reinterpret_cast<uint32_t*>(&q23);
        *(uint2*)(qh + m * KK + k4) = qp;
    } else {
        int i = (bid - 12992) * 256 + tid;
        if (i < NOL) bc[i] = (i < 256) ? b_off[i] : b_w[i - 256];
    }
}

// ---------------- mma.sync GEMM (3-stage pipeline) ---------------------------
// SCHEME 0: bf16 3-pass (AhBh, AhBl, AlBh); A,B stride KST; NC=24; f32 out.
// SCHEME 2: fp16 1-pass; A,B stride KK; NC=8; f16 out (no bias).
// SCHEME 3: fp16 1-pass; A,B stride KK; NC=8; f32 out (+bias).
// CTA tile 128x128, 8 warps (4x2), warp tile 32x64, K-chunks of 64 (SW128),
// 3-stage cp.async pipeline, one __syncthreads per chunk, 2 CTAs/SM.
#define STAGE 32768          // A 16K + B 16K per stage
#define GSMEM (3 * STAGE)    // 96 KB
template<int SCHEME>
__global__ __launch_bounds__(256, 2)
void mma_gemm(const unsigned short* __restrict__ Abf,
              const unsigned short* __restrict__ Bbf,
              const float* __restrict__ bias, void* __restrict__ Cv,
              int Ntot, long long aStride, long long cStride)
{
    constexpr int NC  = (SCHEME == 0) ? 24 : 8;
    constexpr int ARS = (SCHEME >= 2) ? KK : KST;
    constexpr int BRS = (SCHEME == 0) ? KST : KK;
    constexpr bool F16OUT = (SCHEME == 2);
    extern __shared__ __align__(1024) unsigned char smem[];
    uint32_t sb = smem_u32(smem);
    const int tid = threadIdx.x;
    const int lane = tid & 31, wid = tid >> 5;
    const int warpM = wid & 3, warpN = wid >> 2;
    Abf += (size_t)blockIdx.z * aStride;
    const int m0 = blockIdx.y * 128, n0 = blockIdx.x * 128;

    const unsigned short* Ag = Abf + (size_t)m0 * ARS;
    const unsigned short* Bg = Bbf + (size_t)n0 * BRS;

    float acc[2][8][4];
    #pragma unroll
    for (int i = 0; i < 2; i++)
        #pragma unroll
        for (int j = 0; j < 8; j++)
            #pragma unroll
            for (int r = 0; r < 4; r++) acc[i][j][r] = 0.f;

    auto load_chunk = [&](int c, int buf) {
        int p = c >> 3, cc = c & 7;
        int aoff, boff;
        if (SCHEME == 0) { aoff = ((p == 2) ? KK : 0) + cc * 64; boff = ((p == 1) ? KK : 0) + cc * 64; }
        else             { aoff = cc * 64;                        boff = cc * 64; }
        uint32_t d = sb + buf * STAGE;
        #pragma unroll
        for (int i = 0; i < 8; i++) {
            int id  = tid + i * 256;       // 0..2047
            int row = id >> 3;
            int kc  = (id & 7) * 8;        // element offset in chunk
            if (row < 128) {
                CP16(d + SWZ(row * 128 + kc * 2),
                     (const char*)(Ag + (size_t)row * ARS + aoff + kc));
            } else {
                int br = row - 128;
                CP16(d + 16384 + SWZ(br * 128 + kc * 2),
                     (const char*)(Bg + (size_t)br * BRS + boff + kc));
            }
        }
    };

    auto compute = [&](int buf) {
        uint32_t ab = sb + buf * STAGE;
        uint32_t bb = ab + 16384;
        #pragma unroll
        for (int ks = 0; ks < 4; ks++) {
            uint32_t afrag[2][4];
            int arow = warpM * 32 + (lane & 15);
            int akb  = ks * 32 + ((lane >> 4) & 1) * 16;   // bytes
            #pragma unroll
            for (int i = 0; i < 2; i++)
                ldmx4(afrag[i], ab + SWZ((arow + i * 16) * 128 + akb));
            uint32_t bfrag[8][2];
            int bkb = ks * 32 + ((lane >> 3) & 1) * 16;
            #pragma unroll
            for (int jp = 0; jp < 4; jp++) {
                int nrow = warpN * 64 + jp * 16 + ((lane >> 4) & 1) * 8 + (lane & 7);
                uint32_t r[4];
                ldmx4(r, bb + SWZ(nrow * 128 + bkb));
                bfrag[2 * jp][0]     = r[0];
                bfrag[2 * jp][1]     = r[1];
                bfrag[2 * jp + 1][0] = r[2];
                bfrag[2 * jp + 1][1] = r[3];
            }
            #pragma unroll
            for (int i = 0; i < 2; i++)
                #pragma unroll
                for (int j = 0; j < 8; j++)
                    mma16816t<(SCHEME >= 2)>(acc[i][j], afrag[i], bfrag[j]);
        }
    };

    load_chunk(0, 0);
    CPCOMMIT();
    load_chunk(1, 1);
    CPCOMMIT();
    int buf = 0;
    #pragma unroll 1
    for (int c = 0; c < NC; c++) {
        if (c + 2 < NC) CPWAIT1(); else CPWAIT0();
        __syncthreads();
        if (c + 2 < NC) {
            int nb = buf + 2; if (nb >= 3) nb -= 3;
            load_chunk(c + 2, nb);
            CPCOMMIT();
        }
        compute(buf);
        if (++buf == 3) buf = 0;
    }

    // epilogue
    int gr = lane >> 2, tg = (lane & 3) * 2;
    if (F16OUT) {
        __half* Ch = (__half*)Cv + (size_t)blockIdx.z * cStride;
        #pragma unroll
        for (int i = 0; i < 2; i++) {
            int row = m0 + warpM * 32 + i * 16 + gr;
            #pragma unroll
            for (int j = 0; j < 8; j++) {
                int col = n0 + warpN * 64 + j * 8 + tg;
                *(__half2*)&Ch[(size_t)row * Ntot + col] =
                    __floats2half2_rn(acc[i][j][0], acc[i][j][1]);
                *(__half2*)&Ch[(size_t)(row + 8) * Ntot + col] =
                    __floats2half2_rn(acc[i][j][2], acc[i][j][3]);
            }
        }
    } else {
        float* C = (float*)Cv + (size_t)blockIdx.z * cStride;
        #pragma unroll
        for (int i = 0; i < 2; i++) {
            int row = m0 + warpM * 32 + i * 16 + gr;
            #pragma unroll
            for (int j = 0; j < 8; j++) {
                int col = n0 + warpN * 64 + j * 8 + tg;
                float b0 = 0.f, b1 = 0.f;
                if (bias) { b0 = bias[col]; b1 = bias[col + 1]; }
                *(float2*)&C[(size_t)row * Ntot + col] =
                    make_float2(acc[i][j][0] + b0, acc[i][j][1] + b1);
                *(float2*)&C[(size_t)(row + 8) * Ntot + col] =
                    make_float2(acc[i][j][2] + b0, acc[i][j][3] + b1);
            }
        }
    }
}

// ---------------- softmax + bilinear gather ---------------------------------
// 64 threads per token; thread = (head h = tid>>3, 8-channel group tid&8).
// uint4 (LDG.128) gathers; packed f32x2 accumulation; ctx fp16 [BT][512].
__global__ __launch_bounds__(64)
void sample2(const unsigned short* __restrict__ V,
             const float* __restrict__ OL,
             const float* __restrict__ ref,
             unsigned short* __restrict__ CTXb)
{
    int bt = blockIdx.x;
    int b  = bt >> 11;
    int tid = threadIdx.x;

    __shared__ float s_w[Hh * Pp][4];
    __shared__ int   s_i[Hh * Pp][4];

    const float* olrow = OL + (long long)bt * NOL;
    float rx = ref[bt * 2 + 0];
    float ry = ref[bt * 2 + 1];

    #pragma unroll
    for (int rep = 0; rep < 2; rep++) {
        int hp = tid + rep * 64;
        float ox = olrow[2 * hp];
        float oy = olrow[2 * hp + 1];
        float lg = olrow[256 + hp];

        float ix = (rx + RAD * ox) * (float)(WF - 1);
        float iy = (ry + RAD * oy) * (float)(HF - 1);
        float x0f = floorf(ix), y0f = floorf(iy);
        int x0 = (int)x0f, y0 = (int)y0f;
        float fx = ix - x0f, fy = iy - y0f;

        // softmax over P=16 within each 16-lane group (hp groups == lane groups)
        float mx = lg;
        #pragma unroll
        for (int m = 8; m >= 1; m >>= 1)
            mx = fmaxf(mx, __shfl_xor_sync(0xffffffffu, mx, m, 16));
        float e = __expf(lg - mx);
        float s = e;
        #pragma unroll
        for (int m = 8; m >= 1; m >>= 1)
            s += __shfl_xor_sync(0xffffffffu, s, m, 16);
        float aw = e / s;

        bool vx0 = (x0 >= 0) && (x0 < WF);
        bool vx1 = (x0 + 1 >= 0) && (x0 + 1 < WF);
        bool vy0 = (y0 >= 0) && (y0 < HF);
        bool vy1 = (y0 + 1 >= 0) && (y0 + 1 < HF);
        int x0c = min(max(x0, 0), WF - 1);
        int x1c = min(max(x0 + 1, 0), WF - 1);
        int y0c = min(max(y0, 0), HF - 1);
        int y1c = min(max(y0 + 1, 0), HF - 1);

        s_w[hp][0] = (vx0 && vy0) ? (1.f - fx) * (1.f - fy) * aw : 0.f;
        s_w[hp][1] = (vx1 && vy0) ? fx * (1.f - fy) * aw : 0.f;
        s_w[hp][2] = (vx0 && vy1) ? (1.f - fx) * fy * aw : 0.f;
        s_w[hp][3] = (vx1 && vy1) ? fx * fy * aw : 0.f;
        s_i[hp][0] = y0c * WF + x0c;
        s_i[hp][1] = y0c * WF + x1c;
        s_i[hp][2] = y1c * WF + x0c;
        s_i[hp][3] = y1c * WF + x1c;
    }
    __syncthreads();

    int h  = tid >> 3;
    int l8 = tid & 7;
    const unsigned short* Vb = V + (size_t)b * HW * Dd + h * DH + l8 * 8;

    unsigned long long pacc[4] = {0ULL, 0ULL, 0ULL, 0ULL};

    #pragma unroll
    for (int p = 0; p < Pp; p++) {
        int hp = h * Pp + p;
        int4   ii = *(const int4*)s_i[hp];
        float4 ww = *(const float4*)s_w[hp];
        #pragma unroll
        for (int c = 0; c < 4; c++) {
            int   idx = (c == 0) ? ii.x : (c == 1) ? ii.y : (c == 2) ? ii.z : ii.w;
            float w   = (c == 0) ? ww.x : (c == 1) ? ww.y : (c == 2) ? ww.z : ww.w;
            uint4 u = *(const uint4*)(Vb + (size_t)idx * Dd);
            float2 f0 = __half22float2(*reinterpret_cast<const __half2*>(&u.x));
            float2 f1 = __half22float2(*reinterpret_cast<const __half2*>(&u.y));
            float2 f2 = __half22float2(*reinterpret_cast<const __half2*>(&u.z));
            float2 f3 = __half22float2(*reinterpret_cast<const __half2*>(&u.w));
            unsigned int wu = __float_as_uint(w);
            unsigned long long w2, v0, v1, v2, v3;
            PACK2(w2, wu, wu);
            PACK2(v0, __float_as_uint(f0.x), __float_as_uint(f0.y));
            PACK2(v1, __float_as_uint(f1.x), __float_as_uint(f1.y));
            PACK2(v2, __float_as_uint(f2.x), __float_as_uint(f2.y));
            PACK2(v3, __float_as_uint(f3.x), __float_as_uint(f3.y));
            FMA2(pacc[0], w2, v0, pacc[0]);
            FMA2(pacc[1], w2, v1, pacc[1]);
            FMA2(pacc[2], w2, v2, pacc[2]);
            FMA2(pacc[3], w2, v3, pacc[3]);
        }
    }

    uint4 o;
    #pragma unroll
    for (int j = 0; j < 4; j++) {
        unsigned int lo, hi;
        UNPACK2(lo, hi, pacc[j]);
        __half2 hh = __floats2half2_rn(__uint_as_float(lo), __uint_as_float(hi));
        ((uint32_t*)&o)[j] = *reinterpret_cast<uint32_t*>(&hh);
    }
    *(uint4*)(CTXb + (size_t)bt * KK + h * DH + l8 * 8) = o;
}

// ---------------- launch ----------------------------------------------------
extern "C" void kernel_launch(void* const* d_in, const int* in_sizes, int n_in,
                              void* d_out, int out_size)
{
    const float* q     = (const float*)d_in[0];
    const float* fmap  = (const float*)d_in[1];
    const float* ref   = (const float*)d_in[2];
    const float* Wv    = (const float*)d_in[3];
    const float* W_off = (const float*)d_in[4];
    const float* b_off = (const float*)d_in[5];
    const float* W_w   = (const float*)d_in[6];
    const float* b_w   = (const float*)d_in[7];
    const float* W_out = (const float*)d_in[8];
    const float* b_out = (const float*)d_in[9];
    float* out = (float*)d_out;

    float *OL, *bc;
    unsigned short *V, *Ab, *qb, *qh, *CTXb, *Wvb, *Wcb, *Wwh, *Wob;
    cudaGetSymbolAddress((void**)&V,    g_V);
    cudaGetSymbolAddress((void**)&OL,   g_OL);
    cudaGetSymbolAddress((void**)&bc,   g_bc);
    cudaGetSymbolAddress((void**)&Ab,   g_Ab);
    cudaGetSymbolAddress((void**)&qb,   g_qb);
    cudaGetSymbolAddress((void**)&qh,   g_qh);
    cudaGetSymbolAddress((void**)&CTXb, g_CTXb);
    cudaGetSymbolAddress((void**)&Wvb,  g_Wvb);
    cudaGetSymbolAddress((void**)&Wcb,  g_Wcb);
    cudaGetSymbolAddress((void**)&Wwh,  g_Wwh);
    cudaGetSymbolAddress((void**)&Wob,  g_Wob);

    cudaFuncSetAttribute(mma_gemm<0>, cudaFuncAttributeMaxDynamicSharedMemorySize, GSMEM);
    cudaFuncSetAttribute(mma_gemm<2>, cudaFuncAttributeMaxDynamicSharedMemorySize, GSMEM);
    cudaFuncSetAttribute(mma_gemm<3>, cudaFuncAttributeMaxDynamicSharedMemorySize, GSMEM);

    // 0) fused conversions
    prologue<<<PRO_BLOCKS, 256>>>(fmap, Wv, W_off, W_w, W_out, q, b_off, b_w,
                                  Ab, Wvb, Wcb, Wwh, Wob, qb, qh, bc);

    // 1) V = fmap^T @ Wv   (per batch, 4096 x 512), fp16 1-pass, fp16 out
    mma_gemm<2><<<dim3(Dd / 128, HW / 128, Bb), 256, GSMEM>>>(
        Ab, Wvb, nullptr, V, Dd, (long long)HW * KK, (long long)HW * Dd);
    // 2a) offsets = q @ W_off + b_off  (8192 x 256), bf16 3-pass -> OL[:, 0:256]
    mma_gemm<0><<<dim3(2, BT / 128, 1), 256, GSMEM>>>(
        qb, Wcb, bc, OL, NOL, 0, 0);
    // 2b) logits = q @ W_w + b_w  (8192 x 128), fp16 1-pass -> OL[:, 256:384]
    mma_gemm<3><<<dim3(1, BT / 128, 1), 256, GSMEM>>>(
        qh, Wwh, bc + 256, OL + 256, NOL, 0, 0);
    // 3) softmax + bilinear gather (fp16 V) -> CTXb (fp16 single)
    sample2<<<BT, 64>>>(V, OL, ref, CTXb);
    // 4) out = CTX @ W_out + b_out   (8192 x 512), fp16 1-pass, f32 out
    mma_gemm<3><<<dim3(Dd / 128, BT / 128, 1), 256, GSMEM>>>(
        CTXb, Wob, b_out, out, Dd, 0, 0);
}

// round 16
// speedup vs baseline: 5.2858x; 1.1075x over previous
#include <cuda_runtime.h>
#include <cuda_bf16.h>
#include <cuda_fp16.h>
#include <cstdint>

// ---------------- problem constants ----------------
#define Bb   4
#define Tt   2048
#define Dd   512
#define Hh   8
#define Pp   16
#define DH   64
#define Cc   512
#define HF   64
#define WF   64
#define RAD  0.08f
#define BT   (Bb*Tt)        // 8192
#define HW   (HF*WF)        // 4096
#define NOL  384            // 256 (offsets) + 128 (logits)
#define KK   512            // inner dim of every GEMM
#define KST  1024           // stored K for split operands: [hi(512) | lo(512)]

// ---------------- scratch (static device globals) --------------------------
__device__ __align__(256) unsigned short g_V[(size_t)Bb * HW * Dd];  // V fp16
__device__ float g_OL[(size_t)BT * NOL];           // [off(256) | logits(128)] fp32
__device__ float g_bc[NOL];
__device__ __align__(256) unsigned short g_Ab [(size_t)Bb * HW * KK];   // fmap^T fp16 single
__device__ __align__(256) unsigned short g_qb [(size_t)BT * KST];       // q bf16 split
__device__ __align__(256) unsigned short g_qh [(size_t)BT * KK];        // q fp16 single
__device__ __align__(256) unsigned short g_CTXb[(size_t)BT * KK];       // ctx fp16 single
__device__ __align__(256) unsigned short g_Wvb[(size_t)Dd * KK];        // Wv^T fp16 single
__device__ __align__(256) unsigned short g_Wcb[(size_t)256 * KST];      // W_off^T bf16 split
__device__ __align__(256) unsigned short g_Wwh[(size_t)128 * KK];       // W_w^T fp16 single
__device__ __align__(256) unsigned short g_Wob[(size_t)Dd * KK];        // W_out^T fp16 single

// ---------------- PTX helpers (baseline sm_80-class; compile at compute_103) -
__device__ __forceinline__ uint32_t smem_u32(const void* p) {
    uint32_t a;
    asm("{ .reg .u64 t; cvta.to.shared.u64 t, %1; cvt.u32.u64 %0, t; }"
        : "=r"(a) : "l"(p));
    return a;
}
#define SWZ(o) ((o) ^ (((o) >> 3) & 0x70))
#define CP16(dst, src) \
    asm volatile("cp.async.cg.shared.global [%0], [%1], 16;" \
                 :: "r"(dst), "l"(src))
#define CPCOMMIT() asm volatile("cp.async.commit_group;" ::: "memory")
#define CPWAIT0()  asm volatile("cp.async.wait_group 0;" ::: "memory")
#define CPWAIT1()  asm volatile("cp.async.wait_group 1;" ::: "memory")

// packed f32x2 helpers (bit-identical fp32 pairs)
#define FMA2(d, a, b, c) \
    asm("fma.rn.f32x2 %0, %1, %2, %3;" : "=l"(d) : "l"(a), "l"(b), "l"(c))
#define PACK2(d, lo, hi) \
    asm("mov.b64 %0, {%1, %2};" : "=l"(d) : "r"(lo), "r"(hi))
#define UNPACK2(lo, hi, in) \
    asm("mov.b64 {%0, %1}, %2;" : "=r"(lo), "=r"(hi) : "l"(in))

__device__ __forceinline__ void ldmx4(uint32_t r[4], uint32_t addr) {
    asm volatile("ldmatrix.sync.aligned.m8n8.x4.shared.b16 {%0,%1,%2,%3}, [%4];"
        : "=r"(r[0]), "=r"(r[1]), "=r"(r[2]), "=r"(r[3]) : "r"(addr));
}
template<int FP16>
__device__ __forceinline__ void mma16816t(float d[4], const uint32_t a[4],
                                          const uint32_t b[2]) {
    if (FP16)
        asm volatile(
            "mma.sync.aligned.m16n8k16.row.col.f32.f16.f16.f32 "
            "{%0,%1,%2,%3}, {%4,%5,%6,%7}, {%8,%9}, {%0,%1,%2,%3};"
            : "+f"(d[0]), "+f"(d[1]), "+f"(d[2]), "+f"(d[3])
            : "r"(a[0]), "r"(a[1]), "r"(a[2]), "r"(a[3]), "r"(b[0]), "r"(b[1]));
    else
        asm volatile(
            "mma.sync.aligned.m16n8k16.row.col.f32.bf16.bf16.f32 "
            "{%0,%1,%2,%3}, {%4,%5,%6,%7}, {%8,%9}, {%0,%1,%2,%3};"
            : "+f"(d[0]), "+f"(d[1]), "+f"(d[2]), "+f"(d[3])
            : "r"(a[0]), "r"(a[1]), "r"(a[2]), "r"(a[3]), "r"(b[0]), "r"(b[1]));
}

// ---------------- split helpers ---------------------------------------------
__device__ __forceinline__ void split2(float x, unsigned short& h, unsigned short& l) {
    __nv_bfloat16 hb = __float2bfloat16(x);
    __nv_bfloat16 lb = __float2bfloat16(x - __bfloat162float(hb));
    h = *reinterpret_cast<unsigned short*>(&hb);
    l = *reinterpret_cast<unsigned short*>(&lb);
}

// ---------------- fused prologue --------------------------------------------
#define PRO_BLOCKS 12994
__global__ __launch_bounds__(256)
void prologue(const float* __restrict__ fmap, const float* __restrict__ Wv,
              const float* __restrict__ W_off, const float* __restrict__ W_w,
              const float* __restrict__ W_out, const float* __restrict__ q,
              const float* __restrict__ b_off, const float* __restrict__ b_w,
              unsigned short* __restrict__ Ab,  unsigned short* __restrict__ Wvb,
              unsigned short* __restrict__ Wcb, unsigned short* __restrict__ Wwh,
              unsigned short* __restrict__ Wob, unsigned short* __restrict__ qb,
              unsigned short* __restrict__ qh,  float* __restrict__ bc)
{
    __shared__ float t[32][33];
    const int bid = blockIdx.x;
    const int tid = threadIdx.x;
    const int tx = tid & 31, ty = tid >> 5;

    auto tload = [&](const float* in, int N, int n0, int k0) {
        #pragma unroll
        for (int i = ty; i < 32; i += 8)
            t[i][tx] = in[(size_t)(k0 + i) * N + n0 + tx];
        __syncthreads();
    };

    if (bid < 8192) {                       // fmap -> fp16 single
        int r = bid;
        int bx = r & 127; r >>= 7;
        int by = r & 15;  int bz = r >> 4;
        const float* in = fmap + (size_t)bz * Cc * HW;
        unsigned short* out = Ab + (size_t)bz * HW * KK;
        int n0 = bx * 32, k0 = by * 32;
        tload(in, HW, n0, k0);
        #pragma unroll
        for (int i = ty; i < 32; i += 8)
            out[(size_t)(n0 + i) * KK + k0 + tx] =
                __half_as_ushort(__float2half(t[tx][i]));
    } else if (bid < 8448) {                // Wv -> fp16 single
        int r = bid - 8192;
        int n0 = (r & 15) * 32, k0 = (r >> 4) * 32;
        tload(Wv, Dd, n0, k0);
        #pragma unroll
        for (int i = ty; i < 32; i += 8)
            Wvb[(size_t)(n0 + i) * KK + k0 + tx] =
                __half_as_ushort(__float2half(t[tx][i]));
    } else if (bid < 8576) {                // W_off -> bf16 split
        int r = bid - 8448;
        int n0 = (r & 7) * 32, k0 = (r >> 3) * 32;
        tload(W_off, 256, n0, k0);
        #pragma unroll
        for (int i = ty; i < 32; i += 8) {
            int n = n0 + i, k = k0 + tx;
            unsigned short h, l;
            split2(t[tx][i], h, l);
            Wcb[(size_t)n * KST + k]      = h;
            Wcb[(size_t)n * KST + KK + k] = l;
        }
    } else if (bid < 8640) {                // W_w -> fp16 single
        int r = bid - 8576;
        int n0 = (r & 3) * 32, k0 = (r >> 2) * 32;
        tload(W_w, 128, n0, k0);
        #pragma unroll
        for (int i = ty; i < 32; i += 8)
            Wwh[(size_t)(n0 + i) * KK + k0 + tx] =
                __half_as_ushort(__float2half(t[tx][i]));
    } else if (bid < 8896) {                // W_out -> fp16 single
        int r = bid - 8640;
        int n0 = (r & 15) * 32, k0 = (r >> 4) * 32;
        tload(W_out, Dd, n0, k0);
        #pragma unroll
        for (int i = ty; i < 32; i += 8)
            Wob[(size_t)(n0 + i) * KK + k0 + tx] =
                __half_as_ushort(__float2half(t[tx][i]));
    } else if (bid < 12992) {               // q -> bf16 split + fp16 single
        size_t i = (size_t)(bid - 8896) * 256 + tid;   // over BT*128
        size_t m = i >> 7;
        int k4 = (int)(i & 127) * 4;
        float4 v = *(const float4*)(q + m * KK + k4);
        unsigned short h[4], l[4];
        split2(v.x, h[0], l[0]); split2(v.y, h[1], l[1]);
        split2(v.z, h[2], l[2]); split2(v.w, h[3], l[3]);
        uint2 hp, lp;
        hp.x = (uint32_t)h[0] | ((uint32_t)h[1] << 16);
        hp.y = (uint32_t)h[2] | ((uint32_t)h[3] << 16);
        lp.x = (uint32_t)l[0] | ((uint32_t)l[1] << 16);
        lp.y = (uint32_t)l[2] | ((uint32_t)l[3] << 16);
        *(uint2*)(qb + m * KST + k4)      = hp;
        *(uint2*)(qb + m * KST + KK + k4) = lp;
        __half2 q01 = __floats2half2_rn(v.x, v.y);
        __half2 q23 = __floats2half2_rn(v.z, v.w);
        uint2 qp;
        qp.x = *reinterpret_cast<uint32_t*>(&q01);
        qp.y = *reinterpret_cast<uint32_t*>(&q23);
        *(uint2*)(qh + m * KK + k4) = qp;
    } else {
        int i = (bid - 12992) * 256 + tid;
        if (i < NOL) bc[i] = (i < 256) ? b_off[i] : b_w[i - 256];
    }
}

// ---------------- GEMM body (device function, 3-stage pipeline) --------------
// SCHEME 0: bf16 3-pass (AhBh, AhBl, AlBh); A,B stride KST; NC=24; f32 out.
// SCHEME 2: fp16 1-pass; A,B stride KK; NC=8; f16 out (no bias).
// SCHEME 3: fp16 1-pass; A,B stride KK; NC=8; f32 out (+bias).
// CTA tile 128x128, 8 warps (4x2), warp tile 32x64, K-chunks of 64 (SW128),
// one __syncthreads per chunk.
#define STAGE 32768          // A 16K + B 16K per stage
#define GSMEM (3 * STAGE)    // 96 KB
template<int SCHEME>
__device__ __forceinline__ void gemm_body(
    const unsigned short* __restrict__ Abase,
    const unsigned short* __restrict__ Bbase,
    const float* __restrict__ bias, void* __restrict__ Cv,
    int Ntot, int m0, int n0, unsigned char* smem)
{
    constexpr int NC  = (SCHEME == 0) ? 24 : 8;
    constexpr int ARS = (SCHEME >= 2) ? KK : KST;
    constexpr int BRS = (SCHEME == 0) ? KST : KK;
    constexpr bool F16OUT = (SCHEME == 2);
    uint32_t sb = smem_u32(smem);
    const int tid = threadIdx.x;
    const int lane = tid & 31, wid = tid >> 5;
    const int warpM = wid & 3, warpN = wid >> 2;

    const unsigned short* Ag = Abase + (size_t)m0 * ARS;
    const unsigned short* Bg = Bbase + (size_t)n0 * BRS;

    float acc[2][8][4];
    #pragma unroll
    for (int i = 0; i < 2; i++)
        #pragma unroll
        for (int j = 0; j < 8; j++)
            #pragma unroll
            for (int r = 0; r < 4; r++) acc[i][j][r] = 0.f;

    auto load_chunk = [&](int c, int buf) {
        int p = c >> 3, cc = c & 7;
        int aoff, boff;
        if (SCHEME == 0) { aoff = ((p == 2) ? KK : 0) + cc * 64; boff = ((p == 1) ? KK : 0) + cc * 64; }
        else             { aoff = cc * 64;                        boff = cc * 64; }
        uint32_t d = sb + buf * STAGE;
        #pragma unroll
        for (int i = 0; i < 8; i++) {
            int id  = tid + i * 256;       // 0..2047
            int row = id >> 3;
            int kc  = (id & 7) * 8;        // element offset in chunk
            if (row < 128) {
                CP16(d + SWZ(row * 128 + kc * 2),
                     (const char*)(Ag + (size_t)row * ARS + aoff + kc));
            } else {
                int br = row - 128;
                CP16(d + 16384 + SWZ(br * 128 + kc * 2),
                     (const char*)(Bg + (size_t)br * BRS + boff + kc));
            }
        }
    };

    auto compute = [&](int buf) {
        uint32_t ab = sb + buf * STAGE;
        uint32_t bb = ab + 16384;
        #pragma unroll
        for (int ks = 0; ks < 4; ks++) {
            uint32_t afrag[2][4];
            int arow = warpM * 32 + (lane & 15);
            int akb  = ks * 32 + ((lane >> 4) & 1) * 16;   // bytes
            #pragma unroll
            for (int i = 0; i < 2; i++)
                ldmx4(afrag[i], ab + SWZ((arow + i * 16) * 128 + akb));
            uint32_t bfrag[8][2];
            int bkb = ks * 32 + ((lane >> 3) & 1) * 16;
            #pragma unroll
            for (int jp = 0; jp < 4; jp++) {
                int nrow = warpN * 64 + jp * 16 + ((lane >> 4) & 1) * 8 + (lane & 7);
                uint32_t r[4];
                ldmx4(r, bb + SWZ(nrow * 128 + bkb));
                bfrag[2 * jp][0]     = r[0];
                bfrag[2 * jp][1]     = r[1];
                bfrag[2 * jp + 1][0] = r[2];
                bfrag[2 * jp + 1][1] = r[3];
            }
            #pragma unroll
            for (int i = 0; i < 2; i++)
                #pragma unroll
                for (int j = 0; j < 8; j++)
                    mma16816t<(SCHEME >= 2)>(acc[i][j], afrag[i], bfrag[j]);
        }
    };

    load_chunk(0, 0);
    CPCOMMIT();
    load_chunk(1, 1);
    CPCOMMIT();
    int buf = 0;
    #pragma unroll 1
    for (int c = 0; c < NC; c++) {
        if (c + 2 < NC) CPWAIT1(); else CPWAIT0();
        __syncthreads();
        if (c + 2 < NC) {
            int nb = buf + 2; if (nb >= 3) nb -= 3;
            load_chunk(c + 2, nb);
            CPCOMMIT();
        }
        compute(buf);
        if (++buf == 3) buf = 0;
    }

    // epilogue
    int gr = lane >> 2, tg = (lane & 3) * 2;
    if (F16OUT) {
        __half* Ch = (__half*)Cv;
        #pragma unroll
        for (int i = 0; i < 2; i++) {
            int row = m0 + warpM * 32 + i * 16 + gr;
            #pragma unroll
            for (int j = 0; j < 8; j++) {
                int col = n0 + warpN * 64 + j * 8 + tg;
                *(__half2*)&Ch[(size_t)row * Ntot + col] =
                    __floats2half2_rn(acc[i][j][0], acc[i][j][1]);
                *(__half2*)&Ch[(size_t)(row + 8) * Ntot + col] =
                    __floats2half2_rn(acc[i][j][2], acc[i][j][3]);
            }
        }
    } else {
        float* C = (float*)Cv;
        #pragma unroll
        for (int i = 0; i < 2; i++) {
            int row = m0 + warpM * 32 + i * 16 + gr;
            #pragma unroll
            for (int j = 0; j < 8; j++) {
                int col = n0 + warpN * 64 + j * 8 + tg;
                float b0 = 0.f, b1 = 0.f;
                if (bias) { b0 = bias[col]; b1 = bias[col + 1]; }
                *(float2*)&C[(size_t)row * Ntot + col] =
                    make_float2(acc[i][j][0] + b0, acc[i][j][1] + b1);
                *(float2*)&C[(size_t)(row + 8) * Ntot + col] =
                    make_float2(acc[i][j][2] + b0, acc[i][j][3] + b1);
            }
        }
    }
}

// ---------------- fused front-end GEMMs (G2a + G2b + G1 in one launch) ------
//   [0,128)   offsets = q @ W_off + b_off   (bf16 3-pass)  nx=2, ny=64
//   [128,192) logits  = q @ W_w  + b_w      (fp16 1-pass)  ny=64
//   [192,704) V       = fmap^T @ Wv         (fp16 1-pass)  nx=4, ny=32, nz=4
__global__ __launch_bounds__(256, 2)
void gemm_front(const unsigned short* __restrict__ qb,
                const unsigned short* __restrict__ Wcb,
                const float* __restrict__ bc, float* __restrict__ OL,
                const unsigned short* __restrict__ qh,
                const unsigned short* __restrict__ Wwh,
                const unsigned short* __restrict__ Ab,
                const unsigned short* __restrict__ Wvb,
                unsigned short* __restrict__ V)
{
    extern __shared__ __align__(1024) unsigned char smem[];
    int bid = blockIdx.x;
    if (bid < 128) {                 // offsets, bf16 3-pass
        int nx = bid & 1, ny = bid >> 1;
        gemm_body<0>(qb, Wcb, bc, OL, NOL, ny * 128, nx * 128, smem);
    } else if (bid < 192) {          // logits, fp16 1-pass
        int ny = bid - 128;
        gemm_body<3>(qh, Wwh, bc + 256, OL + 256, NOL, ny * 128, 0, smem);
    } else {                         // V projection, fp16 1-pass
        int r = bid - 192;
        int nx = r & 3; r >>= 2;
        int ny = r & 31; int nz = r >> 5;
        gemm_body<2>(Ab + (size_t)nz * HW * KK, Wvb, nullptr,
                     V + (size_t)nz * HW * Dd, Dd, ny * 128, nx * 128, smem);
    }
}

// ---------------- standalone GEMM kernel (for the output projection) --------
template<int SCHEME>
__global__ __launch_bounds__(256, 2)
void mma_gemm(const unsigned short* __restrict__ Abf,
              const unsigned short* __restrict__ Bbf,
              const float* __restrict__ bias, void* __restrict__ Cv,
              int Ntot)
{
    extern __shared__ __align__(1024) unsigned char smem[];
    gemm_body<SCHEME>(Abf, Bbf, bias, Cv, Ntot,
                      blockIdx.y * 128, blockIdx.x * 128, smem);
}

// ---------------- softmax + bilinear gather ---------------------------------
// 64 threads per token; thread = (head h = tid>>3, 8-channel group tid&7).
// uint4 (LDG.128) gathers; packed f32x2 accumulation; ctx fp16 [BT][512].
__global__ __launch_bounds__(64)
void sample2(const unsigned short* __restrict__ V,
             const float* __restrict__ OL,
             const float* __restrict__ ref,
             unsigned short* __restrict__ CTXb)
{
    int bt = blockIdx.x;
    int b  = bt >> 11;
    int tid = threadIdx.x;

    __shared__ float s_w[Hh * Pp][4];
    __shared__ int   s_i[Hh * Pp][4];

    const float* olrow = OL + (long long)bt * NOL;
    float rx = ref[bt * 2 + 0];
    float ry = ref[bt * 2 + 1];

    #pragma unroll
    for (int rep = 0; rep < 2; rep++) {
        int hp = tid + rep * 64;
        float ox = olrow[2 * hp];
        float oy = olrow[2 * hp + 1];
        float lg = olrow[256 + hp];

        float ix = (rx + RAD * ox) * (float)(WF - 1);
        float iy = (ry + RAD * oy) * (float)(HF - 1);
        float x0f = floorf(ix), y0f = floorf(iy);
        int x0 = (int)x0f, y0 = (int)y0f;
        float fx = ix - x0f, fy = iy - y0f;

        // softmax over P=16 within each 16-lane group (hp groups == lane groups)
        float mx = lg;
        #pragma unroll
        for (int m = 8; m >= 1; m >>= 1)
            mx = fmaxf(mx, __shfl_xor_sync(0xffffffffu, mx, m, 16));
        float e = __expf(lg - mx);
        float s = e;
        #pragma unroll
        for (int m = 8; m >= 1; m >>= 1)
            s += __shfl_xor_sync(0xffffffffu, s, m, 16);
        float aw = e / s;

        bool vx0 = (x0 >= 0) && (x0 < WF);
        bool vx1 = (x0 + 1 >= 0) && (x0 + 1 < WF);
        bool vy0 = (y0 >= 0) && (y0 < HF);
        bool vy1 = (y0 + 1 >= 0) && (y0 + 1 < HF);
        int x0c = min(max(x0, 0), WF - 1);
        int x1c = min(max(x0 + 1, 0), WF - 1);
        int y0c = min(max(y0, 0), HF - 1);
        int y1c = min(max(y0 + 1, 0), HF - 1);

        s_w[hp][0] = (vx0 && vy0) ? (1.f - fx) * (1.f - fy) * aw : 0.f;
        s_w[hp][1] = (vx1 && vy0) ? fx * (1.f - fy) * aw : 0.f;
        s_w[hp][2] = (vx0 && vy1) ? (1.f - fx) * fy * aw : 0.f;
        s_w[hp][3] = (vx1 && vy1) ? fx * fy * aw : 0.f;
        s_i[hp][0] = y0c * WF + x0c;
        s_i[hp][1] = y0c * WF + x1c;
        s_i[hp][2] = y1c * WF + x0c;
        s_i[hp][3] = y1c * WF + x1c;
    }
    __syncthreads();

    int h  = tid >> 3;
    int l8 = tid & 7;
    const unsigned short* Vb = V + (size_t)b * HW * Dd + h * DH + l8 * 8;

    unsigned long long pacc[4] = {0ULL, 0ULL, 0ULL, 0ULL};

    #pragma unroll
    for (int p = 0; p < Pp; p++) {
        int hp = h * Pp + p;
        int4   ii = *(const int4*)s_i[hp];
        float4 ww = *(const float4*)s_w[hp];
        #pragma unroll
        for (int c = 0; c < 4; c++) {
            int   idx = (c == 0) ? ii.x : (c == 1) ? ii.y : (c == 2) ? ii.z : ii.w;
            float w   = (c == 0) ? ww.x : (c == 1) ? ww.y : (c == 2) ? ww.z : ww.w;
            uint4 u = *(const uint4*)(Vb + (size_t)idx * Dd);
            float2 f0 = __half22float2(*reinterpret_cast<const __half2*>(&u.x));
            float2 f1 = __half22float2(*reinterpret_cast<const __half2*>(&u.y));
            float2 f2 = __half22float2(*reinterpret_cast<const __half2*>(&u.z));
            float2 f3 = __half22float2(*reinterpret_cast<const __half2*>(&u.w));
            unsigned int wu = __float_as_uint(w);
            unsigned long long w2, v0, v1, v2, v3;
            PACK2(w2, wu, wu);
            PACK2(v0, __float_as_uint(f0.x), __float_as_uint(f0.y));
            PACK2(v1, __float_as_uint(f1.x), __float_as_uint(f1.y));
            PACK2(v2, __float_as_uint(f2.x), __float_as_uint(f2.y));
            PACK2(v3, __float_as_uint(f3.x), __float_as_uint(f3.y));
            FMA2(pacc[0], w2, v0, pacc[0]);
            FMA2(pacc[1], w2, v1, pacc[1]);
            FMA2(pacc[2], w2, v2, pacc[2]);
            FMA2(pacc[3], w2, v3, pacc[3]);
        }
    }

    uint4 o;
    #pragma unroll
    for (int j = 0; j < 4; j++) {
        unsigned int lo, hi;
        UNPACK2(lo, hi, pacc[j]);
        __half2 hh = __floats2half2_rn(__uint_as_float(lo), __uint_as_float(hi));
        ((uint32_t*)&o)[j] = *reinterpret_cast<uint32_t*>(&hh);
    }
    *(uint4*)(CTXb + (size_t)bt * KK + h * DH + l8 * 8) = o;
}

// ---------------- launch ----------------------------------------------------
extern "C" void kernel_launch(void* const* d_in, const int* in_sizes, int n_in,
                              void* d_out, int out_size)
{
    const float* q     = (const float*)d_in[0];
    const float* fmap  = (const float*)d_in[1];
    const float* ref   = (const float*)d_in[2];
    const float* Wv    = (const float*)d_in[3];
    const float* W_off = (const float*)d_in[4];
    const float* b_off = (const float*)d_in[5];
    const float* W_w   = (const float*)d_in[6];
    const float* b_w   = (const float*)d_in[7];
    const float* W_out = (const float*)d_in[8];
    const float* b_out = (const float*)d_in[9];
    float* out = (float*)d_out;

    float *OL, *bc;
    unsigned short *V, *Ab, *qb, *qh, *CTXb, *Wvb, *Wcb, *Wwh, *Wob;
    cudaGetSymbolAddress((void**)&V,    g_V);
    cudaGetSymbolAddress((void**)&OL,   g_OL);
    cudaGetSymbolAddress((void**)&bc,   g_bc);
    cudaGetSymbolAddress((void**)&Ab,   g_Ab);
    cudaGetSymbolAddress((void**)&qb,   g_qb);
    cudaGetSymbolAddress((void**)&qh,   g_qh);
    cudaGetSymbolAddress((void**)&CTXb, g_CTXb);
    cudaGetSymbolAddress((void**)&Wvb,  g_Wvb);
    cudaGetSymbolAddress((void**)&Wcb,  g_Wcb);
    cudaGetSymbolAddress((void**)&Wwh,  g_Wwh);
    cudaGetSymbolAddress((void**)&Wob,  g_Wob);

    cudaFuncSetAttribute(gemm_front,  cudaFuncAttributeMaxDynamicSharedMemorySize, GSMEM);
    cudaFuncSetAttribute(mma_gemm<3>, cudaFuncAttributeMaxDynamicSharedMemorySize, GSMEM);

    // 0) fused conversions
    prologue<<<PRO_BLOCKS, 256>>>(fmap, Wv, W_off, W_w, W_out, q, b_off, b_w,
                                  Ab, Wvb, Wcb, Wwh, Wob, qb, qh, bc);

    // 1) fused front-end: offsets (bf16 3-pass) + logits (fp16) + V (fp16)
    gemm_front<<<704, 256, GSMEM>>>(qb, Wcb, bc, OL, qh, Wwh, Ab, Wvb, V);

    // 2) softmax + bilinear gather (fp16 V) -> CTXb (fp16 single)
    sample2<<<BT, 64>>>(V, OL, ref, CTXb);

    // 3) out = CTX @ W_out + b_out   (8192 x 512), fp16 1-pass, f32 out
    mma_gemm<3><<<dim3(Dd / 128, BT / 128, 1), 256, GSMEM>>>(
        CTXb, Wob, b_out, out, Dd);
}